// round 3
// baseline (speedup 1.0000x reference)
#include <cuda_runtime.h>
#include <cuda_bf16.h>
#include <math.h>
#include <stdint.h>

// ---------------------------------------------------------------------------
// Token performer block: LN -> kqv -> performer attention -> proj+res -> LN
//                        -> mlp(gelu) -> +res
// Shapes: B=16, T=3136, DIM=EMB=512, M=256 random features.
// All GEMMs: tf32 mma.sync (m16n8k8), fp32 accumulate, fused epilogues.
// ---------------------------------------------------------------------------

#define BTC 50176LL          // B*T
#define TT  3136LL
#define NB  16LL

// ---------------- scratch (one big __device__ array, no allocs) ------------
constexpr long long OFF_H1    = 0;
constexpr long long OFF_KQV   = OFF_H1    + BTC*512;
constexpr long long OFF_KP    = OFF_KQV   + BTC*1536;
constexpr long long OFF_QP    = OFF_KP    + BTC*256;
constexpr long long OFF_XDK   = OFF_QP    + BTC*256;
constexpr long long OFF_XDQ   = OFF_XDK   + BTC;
constexpr long long OFF_DV    = OFF_XDQ   + BTC;
constexpr long long OFF_KS    = OFF_DV    + BTC;
constexpr long long OFF_KSP   = OFF_KS    + NB*256;
constexpr long long OFF_VT    = OFF_KSP   + 28LL*NB*256;
constexpr long long OFF_KPT   = OFF_VT    + NB*512*TT;
constexpr long long OFF_KPTV  = OFF_KPT   + NB*256*TT;
constexpr long long OFF_Y     = OFF_KPTV  + NB*512*256;
constexpr long long OFF_XRES  = OFF_Y     + BTC*512;
constexpr long long OFF_H2    = OFF_XRES  + BTC*512;
constexpr long long OFF_HM    = OFF_H2    + BTC*512;
constexpr long long OFF_WKQVT = OFF_HM    + BTC*512;
constexpr long long OFF_WPROJT= OFF_WKQVT + 1536LL*512;
constexpr long long OFF_WM1T  = OFF_WPROJT+ 512LL*512;
constexpr long long OFF_WM2T  = OFF_WM1T  + 512LL*512;
constexpr long long SCRATCH_TOTAL = OFF_WM2T + 512LL*512;

__device__ float g_scratch[SCRATCH_TOTAL];

// ---------------------------- helpers --------------------------------------
__device__ __forceinline__ unsigned tf32u(float x) {
    unsigned u;
    asm("cvt.rna.tf32.f32 %0, %1;" : "=r"(u) : "f"(x));
    return u;
}

__device__ __forceinline__ void mma_tf32(float c[4], const unsigned a[4], const unsigned b[2]) {
    asm volatile(
        "mma.sync.aligned.m16n8k8.row.col.f32.tf32.tf32.f32 "
        "{%0,%1,%2,%3}, {%4,%5,%6,%7}, {%8,%9}, {%0,%1,%2,%3};\n"
        : "+f"(c[0]), "+f"(c[1]), "+f"(c[2]), "+f"(c[3])
        : "r"(a[0]), "r"(a[1]), "r"(a[2]), "r"(a[3]), "r"(b[0]), "r"(b[1]));
}

// ------------------------------ LayerNorm -----------------------------------
__global__ void ln_kernel(const float* __restrict__ in, const float* __restrict__ g,
                          const float* __restrict__ be, float* __restrict__ out) {
    int r = blockIdx.x;          // token row
    int t = threadIdx.x;         // 128 threads, 4 floats each
    const float4* p = (const float4*)(in + (size_t)r * 512);
    float4 v = p[t];
    float s  = v.x + v.y + v.z + v.w;
    float sq = v.x*v.x + v.y*v.y + v.z*v.z + v.w*v.w;
    #pragma unroll
    for (int o = 16; o; o >>= 1) {
        s  += __shfl_xor_sync(0xffffffffu, s,  o);
        sq += __shfl_xor_sync(0xffffffffu, sq, o);
    }
    __shared__ float shs[4], shq[4];
    int wid = t >> 5, lane = t & 31;
    if (!lane) { shs[wid] = s; shq[wid] = sq; }
    __syncthreads();
    s  = shs[0] + shs[1] + shs[2] + shs[3];
    sq = shq[0] + shq[1] + shq[2] + shq[3];
    float mu  = s * (1.0f / 512.0f);
    float var = sq * (1.0f / 512.0f) - mu * mu;
    float inv = rsqrtf(var + 1e-5f);
    float4 gg = ((const float4*)g)[t];
    float4 bb = ((const float4*)be)[t];
    float4 o;
    o.x = (v.x - mu) * inv * gg.x + bb.x;
    o.y = (v.y - mu) * inv * gg.y + bb.y;
    o.z = (v.z - mu) * inv * gg.z + bb.z;
    o.w = (v.w - mu) * inv * gg.w + bb.w;
    ((float4*)(out + (size_t)r * 512))[t] = o;
}

// xd = 0.5*||row||^2 for k and q rows inside kqv buffer
__global__ void rownorm_kernel(const float* __restrict__ kqv,
                               float* __restrict__ xdk, float* __restrict__ xdq) {
    int r = blockIdx.x;
    int t = threadIdx.x;  // 128
    const float4* pk = (const float4*)(kqv + (size_t)r * 1536);
    const float4* pq = pk + 128;  // +512 floats
    float4 a = pk[t], b = pq[t];
    float sk = a.x*a.x + a.y*a.y + a.z*a.z + a.w*a.w;
    float sq = b.x*b.x + b.y*b.y + b.z*b.z + b.w*b.w;
    #pragma unroll
    for (int o = 16; o; o >>= 1) {
        sk += __shfl_xor_sync(0xffffffffu, sk, o);
        sq += __shfl_xor_sync(0xffffffffu, sq, o);
    }
    __shared__ float shk[4], shq2[4];
    int wid = t >> 5, lane = t & 31;
    if (!lane) { shk[wid] = sk; shq2[wid] = sq; }
    __syncthreads();
    if (t == 0) {
        xdk[r] = 0.5f * (shk[0] + shk[1] + shk[2] + shk[3]);
        xdq[r] = 0.5f * (shq2[0] + shq2[1] + shq2[2] + shq2[3]);
    }
}

// ks partial sums over t-chunks (deterministic two-stage)
__global__ void kpsum_part(const float* __restrict__ kp, float* __restrict__ part) {
    int b = blockIdx.y, c = blockIdx.x, m = threadIdx.x;  // 256 threads
    const float* p = kp + ((size_t)b * TT + (size_t)c * 112) * 256 + m;
    float s = 0.f;
    #pragma unroll 4
    for (int t = 0; t < 112; t++) s += p[(size_t)t * 256];
    part[((size_t)c * NB + b) * 256 + m] = s;
}

__global__ void kpsum_reduce(const float* __restrict__ part, float* __restrict__ ks) {
    int b = blockIdx.x, m = threadIdx.x;
    float s = 0.f;
    #pragma unroll
    for (int c = 0; c < 28; c++) s += part[((size_t)c * NB + b) * 256 + m];
    ks[b * 256 + m] = s;
}

// D[r] = qp[r,:] . ks[b,:]
__global__ void d_kernel(const float* __restrict__ qp, const float* __restrict__ ks,
                         float* __restrict__ D) {
    int r = blockIdx.x * 8 + (threadIdx.x >> 5);
    int lane = threadIdx.x & 31;
    int b = r / (int)TT;
    const float* q = qp + (size_t)r * 256;
    const float* s = ks + b * 256;
    float acc = 0.f;
    #pragma unroll
    for (int j = lane; j < 256; j += 32) acc += q[j] * s[j];
    #pragma unroll
    for (int o = 16; o; o >>= 1) acc += __shfl_xor_sync(0xffffffffu, acc, o);
    if (!lane) D[r] = acc;
}

// 32x32 tiled transpose (batched)
__global__ void transpose_kernel(const float* __restrict__ in, int ldin, long long strIn,
                                 float* __restrict__ out, int ldout, long long strOut,
                                 int rows, int cols) {
    __shared__ float tile[32][33];
    const float* inp = in + (size_t)blockIdx.z * strIn;
    float* outp = out + (size_t)blockIdx.z * strOut;
    int bx = blockIdx.x * 32, by = blockIdx.y * 32;
    int x = bx + threadIdx.x;
    #pragma unroll
    for (int j = threadIdx.y; j < 32; j += 8) {
        int y = by + j;
        tile[j][threadIdx.x] = (y < rows && x < cols) ? inp[(size_t)y * ldin + x] : 0.f;
    }
    __syncthreads();
    int ox = by + threadIdx.x;  // out col = in row
    #pragma unroll
    for (int j = threadIdx.y; j < 32; j += 8) {
        int oy = bx + j;        // out row = in col
        if (oy < cols && ox < rows) outp[(size_t)oy * ldout + ox] = tile[threadIdx.x][j];
    }
}

// ------------------------- generic tf32 GEMM (NT) ---------------------------
// C[m,n] = sum_k A[m,k] * B[n,k]   (A row-major [M,K], B row-major [N,K])
// Epilogues: 0 none, 1 +bias, 2 gelu(+bias), 3 +bias+resid, 4 prm_exp, 5 /rowv
#define GBM 128
#define GBN 128
#define GBK 16

template <int EPI>
__device__ __forceinline__ float epi_fn(float v, int r, int c, int ldc,
                                        const float* bias, const float* rowv,
                                        const float* resid) {
    if (EPI == 1) return v + bias[c];
    if (EPI == 2) { float x = v + bias[c]; return 0.5f * x * (1.0f + erff(x * 0.7071067811865476f)); }
    if (EPI == 3) return v + bias[c] + resid[(size_t)r * ldc + c];
    if (EPI == 4) return expf(v - rowv[r]) * 0.0625f;   // / sqrt(M=256)
    if (EPI == 5) return v / (rowv[r] + 1e-8f);
    return v;
}

template <int EPI>
__global__ __launch_bounds__(256, 2) void gemm_nt(
    const float* __restrict__ A, int lda, long long strA,
    const float* __restrict__ B, int ldb, long long strB,
    float* __restrict__ C, int ldc, long long strC,
    int M, int N, int K,
    const float* __restrict__ bias,
    const float* __restrict__ rowv, long long strRow,
    const float* __restrict__ resid, long long strRes) {
    __shared__ float sA[GBM][GBK + 4];
    __shared__ float sB[GBN][GBK + 4];

    A += (size_t)blockIdx.z * strA;
    B += (size_t)blockIdx.z * strB;
    C += (size_t)blockIdx.z * strC;
    if (rowv)  rowv  += (size_t)blockIdx.z * strRow;
    if (resid) resid += (size_t)blockIdx.z * strRes;

    const int m0 = blockIdx.y * GBM;
    const int n0 = blockIdx.x * GBN;
    const int tid = threadIdx.x;
    const int lane = tid & 31, w = tid >> 5;
    const int wm = w & 3, wn = w >> 2;      // 4 m-warps x 2 n-warps
    const int grp = lane >> 2, tig = lane & 3;

    float acc[2][8][4];
    #pragma unroll
    for (int mi = 0; mi < 2; mi++)
        #pragma unroll
        for (int ni = 0; ni < 8; ni++)
            #pragma unroll
            for (int j = 0; j < 4; j++) acc[mi][ni][j] = 0.f;

    for (int k0 = 0; k0 < K; k0 += GBK) {
        // load A tile (rows guarded vs M), convert to tf32 in smem
        #pragma unroll
        for (int i = 0; i < 2; i++) {
            int v = tid + i * 256;
            int r = v >> 2, c4 = (v & 3) << 2;
            float4 val = make_float4(0.f, 0.f, 0.f, 0.f);
            int gm = m0 + r;
            if (gm < M) val = *(const float4*)(A + (size_t)gm * lda + k0 + c4);
            float4 t4;
            t4.x = __uint_as_float(tf32u(val.x));
            t4.y = __uint_as_float(tf32u(val.y));
            t4.z = __uint_as_float(tf32u(val.z));
            t4.w = __uint_as_float(tf32u(val.w));
            *(float4*)&sA[r][c4] = t4;
        }
        // load B tile
        #pragma unroll
        for (int i = 0; i < 2; i++) {
            int v = tid + i * 256;
            int r = v >> 2, c4 = (v & 3) << 2;
            float4 val = make_float4(0.f, 0.f, 0.f, 0.f);
            int gn = n0 + r;
            if (gn < N) val = *(const float4*)(B + (size_t)gn * ldb + k0 + c4);
            float4 t4;
            t4.x = __uint_as_float(tf32u(val.x));
            t4.y = __uint_as_float(tf32u(val.y));
            t4.z = __uint_as_float(tf32u(val.z));
            t4.w = __uint_as_float(tf32u(val.w));
            *(float4*)&sB[r][c4] = t4;
        }
        __syncthreads();

        #pragma unroll
        for (int kk = 0; kk < GBK; kk += 8) {
            unsigned afr[2][4], bfr[8][2];
            #pragma unroll
            for (int mi = 0; mi < 2; mi++) {
                int r = wm * 32 + mi * 16 + grp;
                afr[mi][0] = __float_as_uint(sA[r][kk + tig]);
                afr[mi][1] = __float_as_uint(sA[r + 8][kk + tig]);
                afr[mi][2] = __float_as_uint(sA[r][kk + tig + 4]);
                afr[mi][3] = __float_as_uint(sA[r + 8][kk + tig + 4]);
            }
            #pragma unroll
            for (int ni = 0; ni < 8; ni++) {
                int c = wn * 64 + ni * 8 + grp;
                bfr[ni][0] = __float_as_uint(sB[c][kk + tig]);
                bfr[ni][1] = __float_as_uint(sB[c][kk + tig + 4]);
            }
            #pragma unroll
            for (int mi = 0; mi < 2; mi++)
                #pragma unroll
                for (int ni = 0; ni < 8; ni++)
                    mma_tf32(acc[mi][ni], afr[mi], bfr[ni]);
        }
        __syncthreads();
    }

    // epilogue + store (float2, cols always in range; rows guarded)
    #pragma unroll
    for (int mi = 0; mi < 2; mi++) {
        #pragma unroll
        for (int ni = 0; ni < 8; ni++) {
            int r = m0 + wm * 32 + mi * 16 + grp;
            int c = n0 + wn * 64 + ni * 8 + tig * 2;
            if (r < M) {
                float2 o;
                o.x = epi_fn<EPI>(acc[mi][ni][0], r, c,     ldc, bias, rowv, resid);
                o.y = epi_fn<EPI>(acc[mi][ni][1], r, c + 1, ldc, bias, rowv, resid);
                *(float2*)(C + (size_t)r * ldc + c) = o;
            }
            if (r + 8 < M) {
                float2 o;
                o.x = epi_fn<EPI>(acc[mi][ni][2], r + 8, c,     ldc, bias, rowv, resid);
                o.y = epi_fn<EPI>(acc[mi][ni][3], r + 8, c + 1, ldc, bias, rowv, resid);
                *(float2*)(C + (size_t)(r + 8) * ldc + c) = o;
            }
        }
    }
}

// ------------------------------- driver -------------------------------------
extern "C" void kernel_launch(void* const* d_in, const int* in_sizes, int n_in,
                              void* d_out, int out_size) {
    const float* x      = (const float*)d_in[0];
    const float* w_kqv  = (const float*)d_in[1];
    const float* b_kqv  = (const float*)d_in[2];
    const float* w_proj = (const float*)d_in[3];
    const float* b_proj = (const float*)d_in[4];
    const float* g1     = (const float*)d_in[5];
    const float* be1    = (const float*)d_in[6];
    const float* g2     = (const float*)d_in[7];
    const float* be2    = (const float*)d_in[8];
    const float* w_mlp1 = (const float*)d_in[9];
    const float* b_mlp1 = (const float*)d_in[10];
    const float* w_mlp2 = (const float*)d_in[11];
    const float* b_mlp2 = (const float*)d_in[12];
    const float* w_rand = (const float*)d_in[13];
    float* out = (float*)d_out;

    float* S = nullptr;
    cudaGetSymbolAddress((void**)&S, g_scratch);

    float* h1    = S + OFF_H1;
    float* kqv   = S + OFF_KQV;
    float* kp    = S + OFF_KP;
    float* qp    = S + OFF_QP;
    float* xdk   = S + OFF_XDK;
    float* xdq   = S + OFF_XDQ;
    float* Dv    = S + OFF_DV;
    float* ks    = S + OFF_KS;
    float* ksp   = S + OFF_KSP;
    float* vT    = S + OFF_VT;
    float* kpT   = S + OFF_KPT;
    float* kptv  = S + OFF_KPTV;
    float* y     = S + OFF_Y;
    float* xres  = S + OFF_XRES;
    float* h2    = S + OFF_H2;
    float* hm    = S + OFF_HM;
    float* wkqvT = S + OFF_WKQVT;
    float* wprojT= S + OFF_WPROJT;
    float* wm1T  = S + OFF_WM1T;
    float* wm2T  = S + OFF_WM2T;

    const int BT = (int)BTC;
    const float* nullf = nullptr;
    dim3 tb(32, 8);

    // 1. h1 = LN(x)
    ln_kernel<<<BT, 128>>>(x, g1, be1, h1);

    // 2. weight transposes into NT form
    transpose_kernel<<<dim3(48, 16, 1), tb>>>(w_kqv, 1536, 0, wkqvT, 512, 0, 512, 1536);
    transpose_kernel<<<dim3(16, 16, 1), tb>>>(w_proj, 512, 0, wprojT, 512, 0, 512, 512);
    transpose_kernel<<<dim3(16, 16, 1), tb>>>(w_mlp1, 512, 0, wm1T, 512, 0, 512, 512);
    transpose_kernel<<<dim3(16, 16, 1), tb>>>(w_mlp2, 512, 0, wm2T, 512, 0, 512, 512);

    // 3. kqv = h1 @ w_kqv + b_kqv
    gemm_nt<1><<<dim3(12, 392, 1), 256>>>(h1, 512, 0, wkqvT, 512, 0, kqv, 1536, 0,
                                          BT, 1536, 512, b_kqv, nullf, 0, nullf, 0);

    // 4. xd_k, xd_q
    rownorm_kernel<<<BT, 128>>>(kqv, xdk, xdq);

    // 5. kp = exp(k @ w_rand^T - xd_k)/16 ; qp likewise
    gemm_nt<4><<<dim3(2, 392, 1), 256>>>(kqv, 1536, 0, w_rand, 512, 0, kp, 256, 0,
                                         BT, 256, 512, nullf, xdk, 0, nullf, 0);
    gemm_nt<4><<<dim3(2, 392, 1), 256>>>(kqv + 512, 1536, 0, w_rand, 512, 0, qp, 256, 0,
                                         BT, 256, 512, nullf, xdq, 0, nullf, 0);

    // 6. ks = sum_t kp (deterministic two-stage)
    kpsum_part<<<dim3(28, 16, 1), 256>>>(kp, ksp);
    kpsum_reduce<<<16, 256>>>(ksp, ks);

    // 7. D = qp . ks
    d_kernel<<<BT / 8, 256>>>(qp, ks, Dv);

    // 8. transpose v and kp (per batch) into K-major for the kptv GEMM
    transpose_kernel<<<dim3(16, 98, 16), tb>>>(kqv + 1024, 1536, TT * 1536,
                                               vT, (int)TT, 512 * TT, (int)TT, 512);
    transpose_kernel<<<dim3(8, 98, 16), tb>>>(kp, 256, TT * 256,
                                              kpT, (int)TT, 256 * TT, (int)TT, 256);

    // 9. kptv[b] = vT @ kpT^T   (C[n_emb, m] = sum_t v[t,n] kp[t,m])
    gemm_nt<0><<<dim3(2, 4, 16), 256>>>(vT, (int)TT, 512 * TT, kpT, (int)TT, 256 * TT,
                                        kptv, 256, 512 * 256, 512, 256, (int)TT,
                                        nullf, nullf, 0, nullf, 0);

    // 10. y[b] = (qp[b] @ kptv[b]^T) / (D + eps)
    gemm_nt<5><<<dim3(4, 25, 16), 256>>>(qp, 256, TT * 256, kptv, 256, 512 * 256,
                                         y, 512, TT * 512, (int)TT, 512, 256,
                                         nullf, Dv, TT, nullf, 0);

    // 11. xres = x + y @ w_proj + b_proj
    gemm_nt<3><<<dim3(4, 392, 1), 256>>>(y, 512, 0, wprojT, 512, 0, xres, 512, 0,
                                         BT, 512, 512, b_proj, nullf, 0, x, 0);

    // 12. h2 = LN(xres)
    ln_kernel<<<BT, 128>>>(xres, g2, be2, h2);

    // 13. hm = gelu(h2 @ w_mlp1 + b_mlp1)
    gemm_nt<2><<<dim3(4, 392, 1), 256>>>(h2, 512, 0, wm1T, 512, 0, hm, 512, 0,
                                         BT, 512, 512, b_mlp1, nullf, 0, nullf, 0);

    // 14. out = xres + hm @ w_mlp2 + b_mlp2
    gemm_nt<3><<<dim3(4, 392, 1), 256>>>(hm, 512, 0, wm2T, 512, 0, out, 512, 0,
                                         BT, 512, 512, b_mlp2, nullf, 0, xres, 0);
}

// round 4
// speedup vs baseline: 1.1862x; 1.1862x over previous
#include <cuda_runtime.h>
#include <cuda_bf16.h>
#include <math.h>
#include <stdint.h>

// ---------------------------------------------------------------------------
// Token performer block: LN -> kqv -> performer attention -> proj+res -> LN
//                        -> mlp(gelu) -> +res
// Shapes: B=16, T=3136, DIM=EMB=512, M=256 random features.
// All GEMMs: tf32 mma.sync (m16n8k8), fp32 accumulate, fused epilogues.
// R3: cp.async 2-stage double-buffered mainloop, raw-fp32-as-tf32 (truncation).
// ---------------------------------------------------------------------------

#define BTC 50176LL          // B*T
#define TT  3136LL
#define NB  16LL

// ---------------- scratch (one big __device__ array, no allocs) ------------
constexpr long long OFF_H1    = 0;
constexpr long long OFF_KQV   = OFF_H1    + BTC*512;
constexpr long long OFF_KP    = OFF_KQV   + BTC*1536;
constexpr long long OFF_QP    = OFF_KP    + BTC*256;
constexpr long long OFF_XDK   = OFF_QP    + BTC*256;
constexpr long long OFF_XDQ   = OFF_XDK   + BTC;
constexpr long long OFF_DV    = OFF_XDQ   + BTC;
constexpr long long OFF_KS    = OFF_DV    + BTC;
constexpr long long OFF_KSP   = OFF_KS    + NB*256;
constexpr long long OFF_VT    = OFF_KSP   + 28LL*NB*256;
constexpr long long OFF_KPT   = OFF_VT    + NB*512*TT;
constexpr long long OFF_KPTV  = OFF_KPT   + NB*256*TT;
constexpr long long OFF_Y     = OFF_KPTV  + NB*512*256;
constexpr long long OFF_XRES  = OFF_Y     + BTC*512;
constexpr long long OFF_H2    = OFF_XRES  + BTC*512;
constexpr long long OFF_HM    = OFF_H2    + BTC*512;
constexpr long long OFF_WKQVT = OFF_HM    + BTC*512;
constexpr long long OFF_WPROJT= OFF_WKQVT + 1536LL*512;
constexpr long long OFF_WM1T  = OFF_WPROJT+ 512LL*512;
constexpr long long OFF_WM2T  = OFF_WM1T  + 512LL*512;
constexpr long long SCRATCH_TOTAL = OFF_WM2T + 512LL*512;

__device__ float g_scratch[SCRATCH_TOTAL];

// ---------------------------- helpers --------------------------------------
__device__ __forceinline__ void mma_tf32(float c[4], const unsigned a[4], const unsigned b[2]) {
    asm volatile(
        "mma.sync.aligned.m16n8k8.row.col.f32.tf32.tf32.f32 "
        "{%0,%1,%2,%3}, {%4,%5,%6,%7}, {%8,%9}, {%0,%1,%2,%3};\n"
        : "+f"(c[0]), "+f"(c[1]), "+f"(c[2]), "+f"(c[3])
        : "r"(a[0]), "r"(a[1]), "r"(a[2]), "r"(a[3]), "r"(b[0]), "r"(b[1]));
}

__device__ __forceinline__ void cp_async16(void* smem, const void* gmem, bool pred) {
    uint32_t s = (uint32_t)__cvta_generic_to_shared(smem);
    int sz = pred ? 16 : 0;   // src-size 0 => zero-fill 16B, no gmem access
    asm volatile("cp.async.cg.shared.global [%0], [%1], 16, %2;\n"
                 :: "r"(s), "l"(gmem), "r"(sz));
}
#define CP_COMMIT() asm volatile("cp.async.commit_group;\n" ::: "memory")
#define CP_WAIT0()  asm volatile("cp.async.wait_group 0;\n" ::: "memory")

// ------------------------------ LayerNorm -----------------------------------
__global__ void ln_kernel(const float* __restrict__ in, const float* __restrict__ g,
                          const float* __restrict__ be, float* __restrict__ out) {
    int r = blockIdx.x;          // token row
    int t = threadIdx.x;         // 128 threads, 4 floats each
    const float4* p = (const float4*)(in + (size_t)r * 512);
    float4 v = p[t];
    float s  = v.x + v.y + v.z + v.w;
    float sq = v.x*v.x + v.y*v.y + v.z*v.z + v.w*v.w;
    #pragma unroll
    for (int o = 16; o; o >>= 1) {
        s  += __shfl_xor_sync(0xffffffffu, s,  o);
        sq += __shfl_xor_sync(0xffffffffu, sq, o);
    }
    __shared__ float shs[4], shq[4];
    int wid = t >> 5, lane = t & 31;
    if (!lane) { shs[wid] = s; shq[wid] = sq; }
    __syncthreads();
    s  = shs[0] + shs[1] + shs[2] + shs[3];
    sq = shq[0] + shq[1] + shq[2] + shq[3];
    float mu  = s * (1.0f / 512.0f);
    float var = sq * (1.0f / 512.0f) - mu * mu;
    float inv = rsqrtf(var + 1e-5f);
    float4 gg = ((const float4*)g)[t];
    float4 bb = ((const float4*)be)[t];
    float4 o;
    o.x = (v.x - mu) * inv * gg.x + bb.x;
    o.y = (v.y - mu) * inv * gg.y + bb.y;
    o.z = (v.z - mu) * inv * gg.z + bb.z;
    o.w = (v.w - mu) * inv * gg.w + bb.w;
    ((float4*)(out + (size_t)r * 512))[t] = o;
}

// xd = 0.5*||row||^2 for k and q rows inside kqv buffer
__global__ void rownorm_kernel(const float* __restrict__ kqv,
                               float* __restrict__ xdk, float* __restrict__ xdq) {
    int r = blockIdx.x;
    int t = threadIdx.x;  // 128
    const float4* pk = (const float4*)(kqv + (size_t)r * 1536);
    const float4* pq = pk + 128;  // +512 floats
    float4 a = pk[t], b = pq[t];
    float sk = a.x*a.x + a.y*a.y + a.z*a.z + a.w*a.w;
    float sq = b.x*b.x + b.y*b.y + b.z*b.z + b.w*b.w;
    #pragma unroll
    for (int o = 16; o; o >>= 1) {
        sk += __shfl_xor_sync(0xffffffffu, sk, o);
        sq += __shfl_xor_sync(0xffffffffu, sq, o);
    }
    __shared__ float shk[4], shq2[4];
    int wid = t >> 5, lane = t & 31;
    if (!lane) { shk[wid] = sk; shq2[wid] = sq; }
    __syncthreads();
    if (t == 0) {
        xdk[r] = 0.5f * (shk[0] + shk[1] + shk[2] + shk[3]);
        xdq[r] = 0.5f * (shq2[0] + shq2[1] + shq2[2] + shq2[3]);
    }
}

// ks partial sums over t-chunks (deterministic two-stage)
__global__ void kpsum_part(const float* __restrict__ kp, float* __restrict__ part) {
    int b = blockIdx.y, c = blockIdx.x, m = threadIdx.x;  // 256 threads
    const float* p = kp + ((size_t)b * TT + (size_t)c * 112) * 256 + m;
    float s = 0.f;
    #pragma unroll 4
    for (int t = 0; t < 112; t++) s += p[(size_t)t * 256];
    part[((size_t)c * NB + b) * 256 + m] = s;
}

__global__ void kpsum_reduce(const float* __restrict__ part, float* __restrict__ ks) {
    int b = blockIdx.x, m = threadIdx.x;
    float s = 0.f;
    #pragma unroll
    for (int c = 0; c < 28; c++) s += part[((size_t)c * NB + b) * 256 + m];
    ks[b * 256 + m] = s;
}

// D[r] = qp[r,:] . ks[b,:]
__global__ void d_kernel(const float* __restrict__ qp, const float* __restrict__ ks,
                         float* __restrict__ D) {
    int r = blockIdx.x * 8 + (threadIdx.x >> 5);
    int lane = threadIdx.x & 31;
    int b = r / (int)TT;
    const float* q = qp + (size_t)r * 256;
    const float* s = ks + b * 256;
    float acc = 0.f;
    #pragma unroll
    for (int j = lane; j < 256; j += 32) acc += q[j] * s[j];
    #pragma unroll
    for (int o = 16; o; o >>= 1) acc += __shfl_xor_sync(0xffffffffu, acc, o);
    if (!lane) D[r] = acc;
}

// 32x32 tiled transpose (batched)
__global__ void transpose_kernel(const float* __restrict__ in, int ldin, long long strIn,
                                 float* __restrict__ out, int ldout, long long strOut,
                                 int rows, int cols) {
    __shared__ float tile[32][33];
    const float* inp = in + (size_t)blockIdx.z * strIn;
    float* outp = out + (size_t)blockIdx.z * strOut;
    int bx = blockIdx.x * 32, by = blockIdx.y * 32;
    int x = bx + threadIdx.x;
    #pragma unroll
    for (int j = threadIdx.y; j < 32; j += 8) {
        int y = by + j;
        tile[j][threadIdx.x] = (y < rows && x < cols) ? inp[(size_t)y * ldin + x] : 0.f;
    }
    __syncthreads();
    int ox = by + threadIdx.x;  // out col = in row
    #pragma unroll
    for (int j = threadIdx.y; j < 32; j += 8) {
        int oy = bx + j;        // out row = in col
        if (oy < cols && ox < rows) outp[(size_t)oy * ldout + ox] = tile[threadIdx.x][j];
    }
}

// ------------------------- generic tf32 GEMM (NT) ---------------------------
// C[m,n] = sum_k A[m,k] * B[n,k]   (A row-major [M,K], B row-major [N,K])
// Epilogues: 0 none, 1 +bias, 2 gelu(+bias), 3 +bias+resid, 4 prm_exp, 5 /rowv
// 2-stage cp.async pipeline; raw fp32 bits fed to tf32 mma (HW ignores low 13).
#define GBM 128
#define GBN 128
#define GBK 16

template <int EPI>
__device__ __forceinline__ float epi_fn(float v, int r, int c, int ldc,
                                        const float* bias, const float* rowv,
                                        const float* resid) {
    if (EPI == 1) return v + bias[c];
    if (EPI == 2) { float x = v + bias[c]; return 0.5f * x * (1.0f + erff(x * 0.7071067811865476f)); }
    if (EPI == 3) return v + bias[c] + resid[(size_t)r * ldc + c];
    if (EPI == 4) return expf(v - rowv[r]) * 0.0625f;   // / sqrt(M=256)
    if (EPI == 5) return v / (rowv[r] + 1e-8f);
    return v;
}

template <int EPI>
__global__ __launch_bounds__(256, 2) void gemm_nt(
    const float* __restrict__ A, int lda, long long strA,
    const float* __restrict__ B, int ldb, long long strB,
    float* __restrict__ C, int ldc, long long strC,
    int M, int N, int K,
    const float* __restrict__ bias,
    const float* __restrict__ rowv, long long strRow,
    const float* __restrict__ resid, long long strRes) {
    __shared__ float sA[2][GBM][GBK + 4];
    __shared__ float sB[2][GBN][GBK + 4];

    A += (size_t)blockIdx.z * strA;
    B += (size_t)blockIdx.z * strB;
    C += (size_t)blockIdx.z * strC;
    if (rowv)  rowv  += (size_t)blockIdx.z * strRow;
    if (resid) resid += (size_t)blockIdx.z * strRes;

    const int m0 = blockIdx.y * GBM;
    const int n0 = blockIdx.x * GBN;
    const int tid = threadIdx.x;
    const int lane = tid & 31, w = tid >> 5;
    const int wm = w & 3, wn = w >> 2;      // 4 m-warps x 2 n-warps
    const int grp = lane >> 2, tig = lane & 3;

    // per-thread copy coordinates (2 x 16B per operand per stage)
    const int r0c = tid >> 2;               // rows 0..63  (i=0)
    const int r1c = r0c + 64;               // rows 64..127 (i=1)
    const int c4  = (tid & 3) << 2;
    const bool pA0 = (m0 + r0c) < M;
    const bool pA1 = (m0 + r1c) < M;
    const bool pB0 = (n0 + r0c) < N;
    const bool pB1 = (n0 + r1c) < N;
    const float* gA0 = A + (size_t)(m0 + r0c) * lda + c4;
    const float* gA1 = A + (size_t)(m0 + r1c) * lda + c4;
    const float* gB0 = B + (size_t)(n0 + r0c) * ldb + c4;
    const float* gB1 = B + (size_t)(n0 + r1c) * ldb + c4;

    float acc[2][8][4];
    #pragma unroll
    for (int mi = 0; mi < 2; mi++)
        #pragma unroll
        for (int ni = 0; ni < 8; ni++)
            #pragma unroll
            for (int j = 0; j < 4; j++) acc[mi][ni][j] = 0.f;

    const int nk = K / GBK;

    // prologue: stage 0
    cp_async16(&sA[0][r0c][c4], gA0, pA0);
    cp_async16(&sA[0][r1c][c4], gA1, pA1);
    cp_async16(&sB[0][r0c][c4], gB0, pB0);
    cp_async16(&sB[0][r1c][c4], gB1, pB1);
    CP_COMMIT();

    for (int it = 0; it < nk; it++) {
        CP_WAIT0();
        __syncthreads();
        if (it + 1 < nk) {
            const int st = (it + 1) & 1;
            const int k0 = (it + 1) * GBK;
            cp_async16(&sA[st][r0c][c4], gA0 + k0, pA0);
            cp_async16(&sA[st][r1c][c4], gA1 + k0, pA1);
            cp_async16(&sB[st][r0c][c4], gB0 + k0, pB0);
            cp_async16(&sB[st][r1c][c4], gB1 + k0, pB1);
            CP_COMMIT();
        }
        const int st = it & 1;
        const float (*cA)[GBK + 4] = sA[st];
        const float (*cB)[GBK + 4] = sB[st];
        #pragma unroll
        for (int kk = 0; kk < GBK; kk += 8) {
            unsigned afr[2][4], bfr[8][2];
            #pragma unroll
            for (int mi = 0; mi < 2; mi++) {
                int r = wm * 32 + mi * 16 + grp;
                afr[mi][0] = __float_as_uint(cA[r][kk + tig]);
                afr[mi][1] = __float_as_uint(cA[r + 8][kk + tig]);
                afr[mi][2] = __float_as_uint(cA[r][kk + tig + 4]);
                afr[mi][3] = __float_as_uint(cA[r + 8][kk + tig + 4]);
            }
            #pragma unroll
            for (int ni = 0; ni < 8; ni++) {
                int c = wn * 64 + ni * 8 + grp;
                bfr[ni][0] = __float_as_uint(cB[c][kk + tig]);
                bfr[ni][1] = __float_as_uint(cB[c][kk + tig + 4]);
            }
            #pragma unroll
            for (int mi = 0; mi < 2; mi++)
                #pragma unroll
                for (int ni = 0; ni < 8; ni++)
                    mma_tf32(acc[mi][ni], afr[mi], bfr[ni]);
        }
    }

    // epilogue + store (float2, cols always in range; rows guarded)
    #pragma unroll
    for (int mi = 0; mi < 2; mi++) {
        #pragma unroll
        for (int ni = 0; ni < 8; ni++) {
            int r = m0 + wm * 32 + mi * 16 + grp;
            int c = n0 + wn * 64 + ni * 8 + tig * 2;
            if (r < M) {
                float2 o;
                o.x = epi_fn<EPI>(acc[mi][ni][0], r, c,     ldc, bias, rowv, resid);
                o.y = epi_fn<EPI>(acc[mi][ni][1], r, c + 1, ldc, bias, rowv, resid);
                *(float2*)(C + (size_t)r * ldc + c) = o;
            }
            if (r + 8 < M) {
                float2 o;
                o.x = epi_fn<EPI>(acc[mi][ni][2], r + 8, c,     ldc, bias, rowv, resid);
                o.y = epi_fn<EPI>(acc[mi][ni][3], r + 8, c + 1, ldc, bias, rowv, resid);
                *(float2*)(C + (size_t)(r + 8) * ldc + c) = o;
            }
        }
    }
}

// ------------------------------- driver -------------------------------------
extern "C" void kernel_launch(void* const* d_in, const int* in_sizes, int n_in,
                              void* d_out, int out_size) {
    const float* x      = (const float*)d_in[0];
    const float* w_kqv  = (const float*)d_in[1];
    const float* b_kqv  = (const float*)d_in[2];
    const float* w_proj = (const float*)d_in[3];
    const float* b_proj = (const float*)d_in[4];
    const float* g1     = (const float*)d_in[5];
    const float* be1    = (const float*)d_in[6];
    const float* g2     = (const float*)d_in[7];
    const float* be2    = (const float*)d_in[8];
    const float* w_mlp1 = (const float*)d_in[9];
    const float* b_mlp1 = (const float*)d_in[10];
    const float* w_mlp2 = (const float*)d_in[11];
    const float* b_mlp2 = (const float*)d_in[12];
    const float* w_rand = (const float*)d_in[13];
    float* out = (float*)d_out;

    float* S = nullptr;
    cudaGetSymbolAddress((void**)&S, g_scratch);

    float* h1    = S + OFF_H1;
    float* kqv   = S + OFF_KQV;
    float* kp    = S + OFF_KP;
    float* qp    = S + OFF_QP;
    float* xdk   = S + OFF_XDK;
    float* xdq   = S + OFF_XDQ;
    float* Dv    = S + OFF_DV;
    float* ks    = S + OFF_KS;
    float* ksp   = S + OFF_KSP;
    float* vT    = S + OFF_VT;
    float* kpT   = S + OFF_KPT;
    float* kptv  = S + OFF_KPTV;
    float* y     = S + OFF_Y;
    float* xres  = S + OFF_XRES;
    float* h2    = S + OFF_H2;
    float* hm    = S + OFF_HM;
    float* wkqvT = S + OFF_WKQVT;
    float* wprojT= S + OFF_WPROJT;
    float* wm1T  = S + OFF_WM1T;
    float* wm2T  = S + OFF_WM2T;

    const int BT = (int)BTC;
    const float* nullf = nullptr;
    dim3 tb(32, 8);

    // 1. h1 = LN(x)
    ln_kernel<<<BT, 128>>>(x, g1, be1, h1);

    // 2. weight transposes into NT form
    transpose_kernel<<<dim3(48, 16, 1), tb>>>(w_kqv, 1536, 0, wkqvT, 512, 0, 512, 1536);
    transpose_kernel<<<dim3(16, 16, 1), tb>>>(w_proj, 512, 0, wprojT, 512, 0, 512, 512);
    transpose_kernel<<<dim3(16, 16, 1), tb>>>(w_mlp1, 512, 0, wm1T, 512, 0, 512, 512);
    transpose_kernel<<<dim3(16, 16, 1), tb>>>(w_mlp2, 512, 0, wm2T, 512, 0, 512, 512);

    // 3. kqv = h1 @ w_kqv + b_kqv
    gemm_nt<1><<<dim3(12, 392, 1), 256>>>(h1, 512, 0, wkqvT, 512, 0, kqv, 1536, 0,
                                          BT, 1536, 512, b_kqv, nullf, 0, nullf, 0);

    // 4. xd_k, xd_q
    rownorm_kernel<<<BT, 128>>>(kqv, xdk, xdq);

    // 5. kp = exp(k @ w_rand^T - xd_k)/16 ; qp likewise
    gemm_nt<4><<<dim3(2, 392, 1), 256>>>(kqv, 1536, 0, w_rand, 512, 0, kp, 256, 0,
                                         BT, 256, 512, nullf, xdk, 0, nullf, 0);
    gemm_nt<4><<<dim3(2, 392, 1), 256>>>(kqv + 512, 1536, 0, w_rand, 512, 0, qp, 256, 0,
                                         BT, 256, 512, nullf, xdq, 0, nullf, 0);

    // 6. ks = sum_t kp (deterministic two-stage)
    kpsum_part<<<dim3(28, 16, 1), 256>>>(kp, ksp);
    kpsum_reduce<<<16, 256>>>(ksp, ks);

    // 7. D = qp . ks
    d_kernel<<<BT / 8, 256>>>(qp, ks, Dv);

    // 8. transpose v and kp (per batch) into K-major for the kptv GEMM
    transpose_kernel<<<dim3(16, 98, 16), tb>>>(kqv + 1024, 1536, TT * 1536,
                                               vT, (int)TT, 512 * TT, (int)TT, 512);
    transpose_kernel<<<dim3(8, 98, 16), tb>>>(kp, 256, TT * 256,
                                              kpT, (int)TT, 256 * TT, (int)TT, 256);

    // 9. kptv[b] = vT @ kpT^T   (C[n_emb, m] = sum_t v[t,n] kp[t,m])
    gemm_nt<0><<<dim3(2, 4, 16), 256>>>(vT, (int)TT, 512 * TT, kpT, (int)TT, 256 * TT,
                                        kptv, 256, 512 * 256, 512, 256, (int)TT,
                                        nullf, nullf, 0, nullf, 0);

    // 10. y[b] = (qp[b] @ kptv[b]^T) / (D + eps)
    gemm_nt<5><<<dim3(4, 25, 16), 256>>>(qp, 256, TT * 256, kptv, 256, 512 * 256,
                                         y, 512, TT * 512, (int)TT, 512, 256,
                                         nullf, Dv, TT, nullf, 0);

    // 11. xres = x + y @ w_proj + b_proj
    gemm_nt<3><<<dim3(4, 392, 1), 256>>>(y, 512, 0, wprojT, 512, 0, xres, 512, 0,
                                         BT, 512, 512, b_proj, nullf, 0, x, 0);

    // 12. h2 = LN(xres)
    ln_kernel<<<BT, 128>>>(xres, g2, be2, h2);

    // 13. hm = gelu(h2 @ w_mlp1 + b_mlp1)
    gemm_nt<2><<<dim3(4, 392, 1), 256>>>(h2, 512, 0, wm1T, 512, 0, hm, 512, 0,
                                         BT, 512, 512, b_mlp1, nullf, 0, nullf, 0);

    // 14. out = xres + hm @ w_mlp2 + b_mlp2
    gemm_nt<3><<<dim3(4, 392, 1), 256>>>(hm, 512, 0, wm2T, 512, 0, out, 512, 0,
                                         BT, 512, 512, b_mlp2, nullf, 0, xres, 0);
}

// round 5
// speedup vs baseline: 1.3830x; 1.1659x over previous
#include <cuda_runtime.h>
#include <cuda_bf16.h>
#include <math.h>
#include <stdint.h>

// ---------------------------------------------------------------------------
// Token performer block: LN -> kqv -> performer attention -> proj+res -> LN
//                        -> mlp(gelu) -> +res
// Shapes: B=16, T=3136, DIM=EMB=512, M=256 random features.
// All GEMMs: tf32 mma.sync (m16n8k8), fp32 accumulate, fused epilogues.
// R4: GBK=32 + k-permuted LDS.64 fragment loads (conflict-free, pad=8),
//     2-stage cp.async pipeline, merged weight-transpose launch.
// ---------------------------------------------------------------------------

#define BTC 50176LL          // B*T
#define TT  3136LL
#define NB  16LL

// ---------------- scratch (one big __device__ array, no allocs) ------------
constexpr long long OFF_H1    = 0;
constexpr long long OFF_KQV   = OFF_H1    + BTC*512;
constexpr long long OFF_KP    = OFF_KQV   + BTC*1536;
constexpr long long OFF_QP    = OFF_KP    + BTC*256;
constexpr long long OFF_XDK   = OFF_QP    + BTC*256;
constexpr long long OFF_XDQ   = OFF_XDK   + BTC;
constexpr long long OFF_DV    = OFF_XDQ   + BTC;
constexpr long long OFF_KS    = OFF_DV    + BTC;
constexpr long long OFF_KSP   = OFF_KS    + NB*256;
constexpr long long OFF_VT    = OFF_KSP   + 28LL*NB*256;
constexpr long long OFF_KPT   = OFF_VT    + NB*512*TT;
constexpr long long OFF_KPTV  = OFF_KPT   + NB*256*TT;
constexpr long long OFF_Y     = OFF_KPTV  + NB*512*256;
constexpr long long OFF_XRES  = OFF_Y     + BTC*512;
constexpr long long OFF_H2    = OFF_XRES  + BTC*512;
constexpr long long OFF_HM    = OFF_H2    + BTC*512;
constexpr long long OFF_WKQVT = OFF_HM    + BTC*512;
constexpr long long OFF_WPROJT= OFF_WKQVT + 1536LL*512;
constexpr long long OFF_WM1T  = OFF_WPROJT+ 512LL*512;
constexpr long long OFF_WM2T  = OFF_WM1T  + 512LL*512;
constexpr long long SCRATCH_TOTAL = OFF_WM2T + 512LL*512;

__device__ float g_scratch[SCRATCH_TOTAL];

// ---------------------------- helpers --------------------------------------
__device__ __forceinline__ void mma_tf32(float c[4], const unsigned a[4], const unsigned b[2]) {
    asm volatile(
        "mma.sync.aligned.m16n8k8.row.col.f32.tf32.tf32.f32 "
        "{%0,%1,%2,%3}, {%4,%5,%6,%7}, {%8,%9}, {%0,%1,%2,%3};\n"
        : "+f"(c[0]), "+f"(c[1]), "+f"(c[2]), "+f"(c[3])
        : "r"(a[0]), "r"(a[1]), "r"(a[2]), "r"(a[3]), "r"(b[0]), "r"(b[1]));
}

__device__ __forceinline__ void cp_async16(void* smem, const void* gmem, bool pred) {
    uint32_t s = (uint32_t)__cvta_generic_to_shared(smem);
    int sz = pred ? 16 : 0;   // src-size 0 => zero-fill 16B, no gmem access
    asm volatile("cp.async.cg.shared.global [%0], [%1], 16, %2;\n"
                 :: "r"(s), "l"(gmem), "r"(sz));
}
#define CP_COMMIT() asm volatile("cp.async.commit_group;\n" ::: "memory")
#define CP_WAIT0()  asm volatile("cp.async.wait_group 0;\n" ::: "memory")

// ------------------------------ LayerNorm -----------------------------------
__global__ void ln_kernel(const float* __restrict__ in, const float* __restrict__ g,
                          const float* __restrict__ be, float* __restrict__ out) {
    int r = blockIdx.x;          // token row
    int t = threadIdx.x;         // 128 threads, 4 floats each
    const float4* p = (const float4*)(in + (size_t)r * 512);
    float4 v = p[t];
    float s  = v.x + v.y + v.z + v.w;
    float sq = v.x*v.x + v.y*v.y + v.z*v.z + v.w*v.w;
    #pragma unroll
    for (int o = 16; o; o >>= 1) {
        s  += __shfl_xor_sync(0xffffffffu, s,  o);
        sq += __shfl_xor_sync(0xffffffffu, sq, o);
    }
    __shared__ float shs[4], shq[4];
    int wid = t >> 5, lane = t & 31;
    if (!lane) { shs[wid] = s; shq[wid] = sq; }
    __syncthreads();
    s  = shs[0] + shs[1] + shs[2] + shs[3];
    sq = shq[0] + shq[1] + shq[2] + shq[3];
    float mu  = s * (1.0f / 512.0f);
    float var = sq * (1.0f / 512.0f) - mu * mu;
    float inv = rsqrtf(var + 1e-5f);
    float4 gg = ((const float4*)g)[t];
    float4 bb = ((const float4*)be)[t];
    float4 o;
    o.x = (v.x - mu) * inv * gg.x + bb.x;
    o.y = (v.y - mu) * inv * gg.y + bb.y;
    o.z = (v.z - mu) * inv * gg.z + bb.z;
    o.w = (v.w - mu) * inv * gg.w + bb.w;
    ((float4*)(out + (size_t)r * 512))[t] = o;
}

// xd = 0.5*||row||^2 for k and q rows inside kqv buffer
__global__ void rownorm_kernel(const float* __restrict__ kqv,
                               float* __restrict__ xdk, float* __restrict__ xdq) {
    int r = blockIdx.x;
    int t = threadIdx.x;  // 128
    const float4* pk = (const float4*)(kqv + (size_t)r * 1536);
    const float4* pq = pk + 128;  // +512 floats
    float4 a = pk[t], b = pq[t];
    float sk = a.x*a.x + a.y*a.y + a.z*a.z + a.w*a.w;
    float sq = b.x*b.x + b.y*b.y + b.z*b.z + b.w*b.w;
    #pragma unroll
    for (int o = 16; o; o >>= 1) {
        sk += __shfl_xor_sync(0xffffffffu, sk, o);
        sq += __shfl_xor_sync(0xffffffffu, sq, o);
    }
    __shared__ float shk[4], shq2[4];
    int wid = t >> 5, lane = t & 31;
    if (!lane) { shk[wid] = sk; shq2[wid] = sq; }
    __syncthreads();
    if (t == 0) {
        xdk[r] = 0.5f * (shk[0] + shk[1] + shk[2] + shk[3]);
        xdq[r] = 0.5f * (shq2[0] + shq2[1] + shq2[2] + shq2[3]);
    }
}

// ks partial sums over t-chunks (deterministic two-stage)
__global__ void kpsum_part(const float* __restrict__ kp, float* __restrict__ part) {
    int b = blockIdx.y, c = blockIdx.x, m = threadIdx.x;  // 256 threads
    const float* p = kp + ((size_t)b * TT + (size_t)c * 112) * 256 + m;
    float s = 0.f;
    #pragma unroll 4
    for (int t = 0; t < 112; t++) s += p[(size_t)t * 256];
    part[((size_t)c * NB + b) * 256 + m] = s;
}

__global__ void kpsum_reduce(const float* __restrict__ part, float* __restrict__ ks) {
    int b = blockIdx.x, m = threadIdx.x;
    float s = 0.f;
    #pragma unroll
    for (int c = 0; c < 28; c++) s += part[((size_t)c * NB + b) * 256 + m];
    ks[b * 256 + m] = s;
}

// D[r] = qp[r,:] . ks[b,:]
__global__ void d_kernel(const float* __restrict__ qp, const float* __restrict__ ks,
                         float* __restrict__ D) {
    int r = blockIdx.x * 8 + (threadIdx.x >> 5);
    int lane = threadIdx.x & 31;
    int b = r / (int)TT;
    const float* q = qp + (size_t)r * 256;
    const float* s = ks + b * 256;
    float acc = 0.f;
    #pragma unroll
    for (int j = lane; j < 256; j += 32) acc += q[j] * s[j];
    #pragma unroll
    for (int o = 16; o; o >>= 1) acc += __shfl_xor_sync(0xffffffffu, acc, o);
    if (!lane) D[r] = acc;
}

// 32x32 tiled transpose (batched)
__global__ void transpose_kernel(const float* __restrict__ in, int ldin, long long strIn,
                                 float* __restrict__ out, int ldout, long long strOut,
                                 int rows, int cols) {
    __shared__ float tile[32][33];
    const float* inp = in + (size_t)blockIdx.z * strIn;
    float* outp = out + (size_t)blockIdx.z * strOut;
    int bx = blockIdx.x * 32, by = blockIdx.y * 32;
    int x = bx + threadIdx.x;
    #pragma unroll
    for (int j = threadIdx.y; j < 32; j += 8) {
        int y = by + j;
        tile[j][threadIdx.x] = (y < rows && x < cols) ? inp[(size_t)y * ldin + x] : 0.f;
    }
    __syncthreads();
    int ox = by + threadIdx.x;  // out col = in row
    #pragma unroll
    for (int j = threadIdx.y; j < 32; j += 8) {
        int oy = bx + j;        // out row = in col
        if (oy < cols && ox < rows) outp[(size_t)oy * ldout + ox] = tile[threadIdx.x][j];
    }
}

// merged weight transpose: wkqv (512x1536) + 3x (512x512), all dims /32
__global__ void transpose_weights(const float* __restrict__ wkqv,
                                  const float* __restrict__ wproj,
                                  const float* __restrict__ wm1,
                                  const float* __restrict__ wm2,
                                  float* __restrict__ okqv, float* __restrict__ oproj,
                                  float* __restrict__ om1,  float* __restrict__ om2) {
    __shared__ float tile[32][33];
    int bx = blockIdx.x;  // 0..95 virtual col tiles
    const float* in; float* out; int ldin; int ct;
    if (bx < 48)      { in = wkqv;  out = okqv;  ldin = 1536; ct = bx; }
    else if (bx < 64) { in = wproj; out = oproj; ldin = 512;  ct = bx - 48; }
    else if (bx < 80) { in = wm1;   out = om1;   ldin = 512;  ct = bx - 64; }
    else              { in = wm2;   out = om2;   ldin = 512;  ct = bx - 80; }
    int c0 = ct * 32, r0 = blockIdx.y * 32;
    int x = c0 + threadIdx.x;
    #pragma unroll
    for (int j = threadIdx.y; j < 32; j += 8)
        tile[j][threadIdx.x] = in[(size_t)(r0 + j) * ldin + x];
    __syncthreads();
    int ox = r0 + threadIdx.x;
    #pragma unroll
    for (int j = threadIdx.y; j < 32; j += 8)
        out[(size_t)(c0 + j) * 512 + ox] = tile[threadIdx.x][j];
}

// ------------------------- generic tf32 GEMM (NT) ---------------------------
// C[m,n] = sum_k A[m,k] * B[n,k]   (A row-major [M,K], B row-major [N,K])
// Epilogues: 0 none, 1 +bias, 2 gelu(+bias), 3 +bias+resid, 4 prm_exp, 5 /rowv
// 2-stage cp.async pipeline, GBK=32, pad=8 (row stride 40 floats => LDS.64
// fragment loads conflict-free), k-permuted within each 8-block (A and B use
// the same permutation so the dot product is exact).
#define GBM 128
#define GBN 128
#define GBK 32
#define GPAD 8
#define GLD  (GBK + GPAD)            // 40 floats per smem row
#define STAGE_F (128 * GLD)          // floats per stage per operand

template <int EPI>
__device__ __forceinline__ float epi_fn(float v, int r, int c, int ldc,
                                        const float* bias, const float* rowv,
                                        const float* resid) {
    if (EPI == 1) return v + bias[c];
    if (EPI == 2) { float x = v + bias[c]; return 0.5f * x * (1.0f + erff(x * 0.7071067811865476f)); }
    if (EPI == 3) return v + bias[c] + resid[(size_t)r * ldc + c];
    if (EPI == 4) return expf(v - rowv[r]) * 0.0625f;   // / sqrt(M=256)
    if (EPI == 5) return v / (rowv[r] + 1e-8f);
    return v;
}

template <int EPI>
__global__ __launch_bounds__(256, 2) void gemm_nt(
    const float* __restrict__ A, int lda, long long strA,
    const float* __restrict__ B, int ldb, long long strB,
    float* __restrict__ C, int ldc, long long strC,
    int M, int N, int K,
    const float* __restrict__ bias,
    const float* __restrict__ rowv, long long strRow,
    const float* __restrict__ resid, long long strRes) {
    extern __shared__ float dsm[];
    float* sA = dsm;                       // [2][128][GLD]
    float* sB = dsm + 2 * STAGE_F;         // [2][128][GLD]

    A += (size_t)blockIdx.z * strA;
    B += (size_t)blockIdx.z * strB;
    C += (size_t)blockIdx.z * strC;
    if (rowv)  rowv  += (size_t)blockIdx.z * strRow;
    if (resid) resid += (size_t)blockIdx.z * strRes;

    const int m0 = blockIdx.y * GBM;
    const int n0 = blockIdx.x * GBN;
    const int tid = threadIdx.x;
    const int lane = tid & 31, w = tid >> 5;
    const int wm = w & 3, wn = w >> 2;      // 4 m-warps x 2 n-warps
    const int grp = lane >> 2, tig = lane & 3;

    // per-thread copy coordinates: 4 x 16B per operand per stage
    const int rc = tid >> 3;                 // base row 0..31
    const int c4 = (tid & 7) << 2;           // k offset 0..28
    bool pA[4], pB[4];
    const float* gA[4];
    const float* gB[4];
    #pragma unroll
    for (int i = 0; i < 4; i++) {
        int r = rc + i * 32;
        pA[i] = (m0 + r) < M;
        pB[i] = (n0 + r) < N;
        gA[i] = A + (size_t)(m0 + r) * lda + c4;
        gB[i] = B + (size_t)(n0 + r) * ldb + c4;
    }

    float acc[2][8][4];
    #pragma unroll
    for (int mi = 0; mi < 2; mi++)
        #pragma unroll
        for (int ni = 0; ni < 8; ni++)
            #pragma unroll
            for (int j = 0; j < 4; j++) acc[mi][ni][j] = 0.f;

    const int nk = K / GBK;

    // prologue: stage 0
    #pragma unroll
    for (int i = 0; i < 4; i++) {
        cp_async16(&sA[(rc + i * 32) * GLD + c4], gA[i], pA[i]);
        cp_async16(&sB[(rc + i * 32) * GLD + c4], gB[i], pB[i]);
    }
    CP_COMMIT();

    for (int it = 0; it < nk; it++) {
        CP_WAIT0();
        __syncthreads();
        if (it + 1 < nk) {
            const int st = (it + 1) & 1;
            const int k0 = (it + 1) * GBK;
            #pragma unroll
            for (int i = 0; i < 4; i++) {
                cp_async16(&sA[st * STAGE_F + (rc + i * 32) * GLD + c4], gA[i] + k0, pA[i]);
                cp_async16(&sB[st * STAGE_F + (rc + i * 32) * GLD + c4], gB[i] + k0, pB[i]);
            }
            CP_COMMIT();
        }
        const int st = it & 1;
        const float* cA = sA + st * STAGE_F;
        const float* cB = sB + st * STAGE_F;
        #pragma unroll
        for (int kk = 0; kk < GBK; kk += 8) {
            // k-permuted fragment loads: logical slot tig -> physical kk+2*tig,
            // slot tig+4 -> kk+2*tig+1 (same permutation for A and B).
            unsigned afr[2][4], bfr[8][2];
            #pragma unroll
            for (int mi = 0; mi < 2; mi++) {
                int r = wm * 32 + mi * 16 + grp;
                float2 a0 = *(const float2*)&cA[r * GLD + kk + 2 * tig];
                float2 a1 = *(const float2*)&cA[(r + 8) * GLD + kk + 2 * tig];
                afr[mi][0] = __float_as_uint(a0.x);
                afr[mi][2] = __float_as_uint(a0.y);
                afr[mi][1] = __float_as_uint(a1.x);
                afr[mi][3] = __float_as_uint(a1.y);
            }
            #pragma unroll
            for (int ni = 0; ni < 8; ni++) {
                int c = wn * 64 + ni * 8 + grp;
                float2 b0 = *(const float2*)&cB[c * GLD + kk + 2 * tig];
                bfr[ni][0] = __float_as_uint(b0.x);
                bfr[ni][1] = __float_as_uint(b0.y);
            }
            #pragma unroll
            for (int mi = 0; mi < 2; mi++)
                #pragma unroll
                for (int ni = 0; ni < 8; ni++)
                    mma_tf32(acc[mi][ni], afr[mi], bfr[ni]);
        }
    }

    // epilogue + store (float2, cols always in range; rows guarded)
    #pragma unroll
    for (int mi = 0; mi < 2; mi++) {
        #pragma unroll
        for (int ni = 0; ni < 8; ni++) {
            int r = m0 + wm * 32 + mi * 16 + grp;
            int c = n0 + wn * 64 + ni * 8 + tig * 2;
            if (r < M) {
                float2 o;
                o.x = epi_fn<EPI>(acc[mi][ni][0], r, c,     ldc, bias, rowv, resid);
                o.y = epi_fn<EPI>(acc[mi][ni][1], r, c + 1, ldc, bias, rowv, resid);
                *(float2*)(C + (size_t)r * ldc + c) = o;
            }
            if (r + 8 < M) {
                float2 o;
                o.x = epi_fn<EPI>(acc[mi][ni][2], r + 8, c,     ldc, bias, rowv, resid);
                o.y = epi_fn<EPI>(acc[mi][ni][3], r + 8, c + 1, ldc, bias, rowv, resid);
                *(float2*)(C + (size_t)(r + 8) * ldc + c) = o;
            }
        }
    }
}

// ------------------------------- driver -------------------------------------
static const int GEMM_SMEM = 4 * STAGE_F * (int)sizeof(float);  // 81920 B

extern "C" void kernel_launch(void* const* d_in, const int* in_sizes, int n_in,
                              void* d_out, int out_size) {
    const float* x      = (const float*)d_in[0];
    const float* w_kqv  = (const float*)d_in[1];
    const float* b_kqv  = (const float*)d_in[2];
    const float* w_proj = (const float*)d_in[3];
    const float* b_proj = (const float*)d_in[4];
    const float* g1     = (const float*)d_in[5];
    const float* be1    = (const float*)d_in[6];
    const float* g2     = (const float*)d_in[7];
    const float* be2    = (const float*)d_in[8];
    const float* w_mlp1 = (const float*)d_in[9];
    const float* b_mlp1 = (const float*)d_in[10];
    const float* w_mlp2 = (const float*)d_in[11];
    const float* b_mlp2 = (const float*)d_in[12];
    const float* w_rand = (const float*)d_in[13];
    float* out = (float*)d_out;

    float* S = nullptr;
    cudaGetSymbolAddress((void**)&S, g_scratch);

    float* h1    = S + OFF_H1;
    float* kqv   = S + OFF_KQV;
    float* kp    = S + OFF_KP;
    float* qp    = S + OFF_QP;
    float* xdk   = S + OFF_XDK;
    float* xdq   = S + OFF_XDQ;
    float* Dv    = S + OFF_DV;
    float* ks    = S + OFF_KS;
    float* ksp   = S + OFF_KSP;
    float* vT    = S + OFF_VT;
    float* kpT   = S + OFF_KPT;
    float* kptv  = S + OFF_KPTV;
    float* y     = S + OFF_Y;
    float* xres  = S + OFF_XRES;
    float* h2    = S + OFF_H2;
    float* hm    = S + OFF_HM;
    float* wkqvT = S + OFF_WKQVT;
    float* wprojT= S + OFF_WPROJT;
    float* wm1T  = S + OFF_WM1T;
    float* wm2T  = S + OFF_WM2T;

    static bool attr_done = false;
    if (!attr_done) {
        cudaFuncSetAttribute(gemm_nt<0>, cudaFuncAttributeMaxDynamicSharedMemorySize, GEMM_SMEM);
        cudaFuncSetAttribute(gemm_nt<1>, cudaFuncAttributeMaxDynamicSharedMemorySize, GEMM_SMEM);
        cudaFuncSetAttribute(gemm_nt<2>, cudaFuncAttributeMaxDynamicSharedMemorySize, GEMM_SMEM);
        cudaFuncSetAttribute(gemm_nt<3>, cudaFuncAttributeMaxDynamicSharedMemorySize, GEMM_SMEM);
        cudaFuncSetAttribute(gemm_nt<4>, cudaFuncAttributeMaxDynamicSharedMemorySize, GEMM_SMEM);
        cudaFuncSetAttribute(gemm_nt<5>, cudaFuncAttributeMaxDynamicSharedMemorySize, GEMM_SMEM);
        attr_done = true;
    }

    const int BT = (int)BTC;
    const float* nullf = nullptr;
    dim3 tb(32, 8);

    // 1. h1 = LN(x)
    ln_kernel<<<BT, 128>>>(x, g1, be1, h1);

    // 2. all weight transposes in one launch
    transpose_weights<<<dim3(96, 16), tb>>>(w_kqv, w_proj, w_mlp1, w_mlp2,
                                            wkqvT, wprojT, wm1T, wm2T);

    // 3. kqv = h1 @ w_kqv + b_kqv
    gemm_nt<1><<<dim3(12, 392, 1), 256, GEMM_SMEM>>>(h1, 512, 0, wkqvT, 512, 0, kqv, 1536, 0,
                                          BT, 1536, 512, b_kqv, nullf, 0, nullf, 0);

    // 4. xd_k, xd_q
    rownorm_kernel<<<BT, 128>>>(kqv, xdk, xdq);

    // 5. kp = exp(k @ w_rand^T - xd_k)/16 ; qp likewise
    gemm_nt<4><<<dim3(2, 392, 1), 256, GEMM_SMEM>>>(kqv, 1536, 0, w_rand, 512, 0, kp, 256, 0,
                                         BT, 256, 512, nullf, xdk, 0, nullf, 0);
    gemm_nt<4><<<dim3(2, 392, 1), 256, GEMM_SMEM>>>(kqv + 512, 1536, 0, w_rand, 512, 0, qp, 256, 0,
                                         BT, 256, 512, nullf, xdq, 0, nullf, 0);

    // 6. ks = sum_t kp (deterministic two-stage)
    kpsum_part<<<dim3(28, 16, 1), 256>>>(kp, ksp);
    kpsum_reduce<<<16, 256>>>(ksp, ks);

    // 7. D = qp . ks
    d_kernel<<<BT / 8, 256>>>(qp, ks, Dv);

    // 8. transpose v and kp (per batch) into K-major for the kptv GEMM
    transpose_kernel<<<dim3(16, 98, 16), tb>>>(kqv + 1024, 1536, TT * 1536,
                                               vT, (int)TT, 512 * TT, (int)TT, 512);
    transpose_kernel<<<dim3(8, 98, 16), tb>>>(kp, 256, TT * 256,
                                              kpT, (int)TT, 256 * TT, (int)TT, 256);

    // 9. kptv[b] = vT @ kpT^T   (C[n_emb, m] = sum_t v[t,n] kp[t,m])
    gemm_nt<0><<<dim3(2, 4, 16), 256, GEMM_SMEM>>>(vT, (int)TT, 512 * TT, kpT, (int)TT, 256 * TT,
                                        kptv, 256, 512 * 256, 512, 256, (int)TT,
                                        nullf, nullf, 0, nullf, 0);

    // 10. y[b] = (qp[b] @ kptv[b]^T) / (D + eps)
    gemm_nt<5><<<dim3(4, 25, 16), 256, GEMM_SMEM>>>(qp, 256, TT * 256, kptv, 256, 512 * 256,
                                         y, 512, TT * 512, (int)TT, 512, 256,
                                         nullf, Dv, TT, nullf, 0);

    // 11. xres = x + y @ w_proj + b_proj
    gemm_nt<3><<<dim3(4, 392, 1), 256, GEMM_SMEM>>>(y, 512, 0, wprojT, 512, 0, xres, 512, 0,
                                         BT, 512, 512, b_proj, nullf, 0, x, 0);

    // 12. h2 = LN(xres)
    ln_kernel<<<BT, 128>>>(xres, g2, be2, h2);

    // 13. hm = gelu(h2 @ w_mlp1 + b_mlp1)
    gemm_nt<2><<<dim3(4, 392, 1), 256, GEMM_SMEM>>>(h2, 512, 0, wm1T, 512, 0, hm, 512, 0,
                                         BT, 512, 512, b_mlp1, nullf, 0, nullf, 0);

    // 14. out = xres + hm @ w_mlp2 + b_mlp2
    gemm_nt<3><<<dim3(4, 392, 1), 256, GEMM_SMEM>>>(hm, 512, 0, wm2T, 512, 0, out, 512, 0,
                                         BT, 512, 512, b_mlp2, nullf, 0, xres, 0);
}

// round 7
// speedup vs baseline: 1.6144x; 1.1673x over previous
#include <cuda_runtime.h>
#include <cuda_bf16.h>
#include <math.h>
#include <stdint.h>

// ---------------------------------------------------------------------------
// Token performer block. sm_103 (no 'a' features available in this toolchain):
// GEMMs via mma.sync. Sensitive path (kqv, kp, qp) in tf32 m16n8k8; streaming
// GEMMs (kptv, y, proj, mlp1, mlp2) in bf16 m16n8k16 with bf16 tensors.
// 128x256 CTA tiles, 8 warps, GBK=32, 2-stage cp.async, k-permuted LDS.64.
// ---------------------------------------------------------------------------

#define BTC 50176LL          // B*T
#define TT  3136LL
#define NB  16LL

// ---------------- scratch (fp32-sized regions; some reused as bf16) --------
constexpr long long OFF_H1    = 0;
constexpr long long OFF_KQV   = OFF_H1    + BTC*512;
constexpr long long OFF_KP    = OFF_KQV   + BTC*1536;
constexpr long long OFF_QP    = OFF_KP    + BTC*256;
constexpr long long OFF_XDK   = OFF_QP    + BTC*256;
constexpr long long OFF_XDQ   = OFF_XDK   + BTC;
constexpr long long OFF_DV    = OFF_XDQ   + BTC;
constexpr long long OFF_KS    = OFF_DV    + BTC;
constexpr long long OFF_KSP   = OFF_KS    + NB*256;
constexpr long long OFF_VT    = OFF_KSP   + 28LL*NB*256;
constexpr long long OFF_KPT   = OFF_VT    + NB*512*TT;
constexpr long long OFF_KPTV  = OFF_KPT   + NB*256*TT;
constexpr long long OFF_Y     = OFF_KPTV  + NB*512*256;
constexpr long long OFF_XRES  = OFF_Y     + BTC*512;
constexpr long long OFF_H2    = OFF_XRES  + BTC*512;
constexpr long long OFF_HM    = OFF_H2    + BTC*512;
constexpr long long OFF_WKQVT = OFF_HM    + BTC*512;
constexpr long long OFF_WPROJT= OFF_WKQVT + 1536LL*512;
constexpr long long OFF_WM1T  = OFF_WPROJT+ 512LL*512;
constexpr long long OFF_WM2T  = OFF_WM1T  + 512LL*512;
constexpr long long SCRATCH_TOTAL = OFF_WM2T + 512LL*512;

__device__ __align__(128) float g_scratch[SCRATCH_TOTAL];

// ---------------------------- helpers --------------------------------------
__device__ __forceinline__ void mma_tf32(float c[4], const unsigned a[4], const unsigned b[2]) {
    asm volatile(
        "mma.sync.aligned.m16n8k8.row.col.f32.tf32.tf32.f32 "
        "{%0,%1,%2,%3}, {%4,%5,%6,%7}, {%8,%9}, {%0,%1,%2,%3};\n"
        : "+f"(c[0]), "+f"(c[1]), "+f"(c[2]), "+f"(c[3])
        : "r"(a[0]), "r"(a[1]), "r"(a[2]), "r"(a[3]), "r"(b[0]), "r"(b[1]));
}

__device__ __forceinline__ void mma_bf16(float c[4], const unsigned a[4], const unsigned b[2]) {
    asm volatile(
        "mma.sync.aligned.m16n8k16.row.col.f32.bf16.bf16.f32 "
        "{%0,%1,%2,%3}, {%4,%5,%6,%7}, {%8,%9}, {%0,%1,%2,%3};\n"
        : "+f"(c[0]), "+f"(c[1]), "+f"(c[2]), "+f"(c[3])
        : "r"(a[0]), "r"(a[1]), "r"(a[2]), "r"(a[3]), "r"(b[0]), "r"(b[1]));
}

__device__ __forceinline__ void cp_async16(uint32_t saddr, const void* gmem, bool pred) {
    int sz = pred ? 16 : 0;   // src-size 0 => zero-fill, no gmem access
    asm volatile("cp.async.cg.shared.global [%0], [%1], 16, %2;\n"
                 :: "r"(saddr), "l"(gmem), "r"(sz));
}
#define CP_COMMIT() asm volatile("cp.async.commit_group;\n" ::: "memory")
#define CP_WAIT0()  asm volatile("cp.async.wait_group 0;\n" ::: "memory")

__device__ __forceinline__ float gelu_exact(float x) {
    return 0.5f * x * (1.0f + erff(x * 0.7071067811865476f));
}

// ------------------------------ LayerNorm -----------------------------------
template <int OB>
__global__ void ln_kernel(const float* __restrict__ in, const float* __restrict__ g,
                          const float* __restrict__ be, void* __restrict__ outv) {
    int r = blockIdx.x;
    int t = threadIdx.x;         // 128 threads, 4 floats each
    const float4* p = (const float4*)(in + (size_t)r * 512);
    float4 v = p[t];
    float s  = v.x + v.y + v.z + v.w;
    float sq = v.x*v.x + v.y*v.y + v.z*v.z + v.w*v.w;
    #pragma unroll
    for (int o = 16; o; o >>= 1) {
        s  += __shfl_xor_sync(0xffffffffu, s,  o);
        sq += __shfl_xor_sync(0xffffffffu, sq, o);
    }
    __shared__ float shs[4], shq[4];
    int wid = t >> 5, lane = t & 31;
    if (!lane) { shs[wid] = s; shq[wid] = sq; }
    __syncthreads();
    s  = shs[0] + shs[1] + shs[2] + shs[3];
    sq = shq[0] + shq[1] + shq[2] + shq[3];
    float mu  = s * (1.0f / 512.0f);
    float var = sq * (1.0f / 512.0f) - mu * mu;
    float inv = rsqrtf(var + 1e-5f);
    float4 gg = ((const float4*)g)[t];
    float4 bb = ((const float4*)be)[t];
    float4 o;
    o.x = (v.x - mu) * inv * gg.x + bb.x;
    o.y = (v.y - mu) * inv * gg.y + bb.y;
    o.z = (v.z - mu) * inv * gg.z + bb.z;
    o.w = (v.w - mu) * inv * gg.w + bb.w;
    if (OB) {
        __nv_bfloat16* ob = (__nv_bfloat16*)outv + (size_t)r * 512 + t * 4;
        *(__nv_bfloat162*)(ob)     = __floats2bfloat162_rn(o.x, o.y);
        *(__nv_bfloat162*)(ob + 2) = __floats2bfloat162_rn(o.z, o.w);
    } else {
        ((float4*)((float*)outv + (size_t)r * 512))[t] = o;
    }
}

// xd = 0.5*||row||^2 for k and q rows inside kqv buffer
__global__ void rownorm_kernel(const float* __restrict__ kqv,
                               float* __restrict__ xdk, float* __restrict__ xdq) {
    int r = blockIdx.x;
    int t = threadIdx.x;  // 128
    const float4* pk = (const float4*)(kqv + (size_t)r * 1536);
    const float4* pq = pk + 128;
    float4 a = pk[t], b = pq[t];
    float sk = a.x*a.x + a.y*a.y + a.z*a.z + a.w*a.w;
    float sq = b.x*b.x + b.y*b.y + b.z*b.z + b.w*b.w;
    #pragma unroll
    for (int o = 16; o; o >>= 1) {
        sk += __shfl_xor_sync(0xffffffffu, sk, o);
        sq += __shfl_xor_sync(0xffffffffu, sq, o);
    }
    __shared__ float shk[4], shq2[4];
    int wid = t >> 5, lane = t & 31;
    if (!lane) { shk[wid] = sk; shq2[wid] = sq; }
    __syncthreads();
    if (t == 0) {
        xdk[r] = 0.5f * (shk[0] + shk[1] + shk[2] + shk[3]);
        xdq[r] = 0.5f * (shq2[0] + shq2[1] + shq2[2] + shq2[3]);
    }
}

// ks partial sums over t-chunks (bf16 kp in, fp32 partials)
__global__ void kpsum_part(const __nv_bfloat16* __restrict__ kp, float* __restrict__ part) {
    int b = blockIdx.y, c = blockIdx.x, m = threadIdx.x;  // 256 threads
    const __nv_bfloat16* p = kp + ((size_t)b * TT + (size_t)c * 112) * 256 + m;
    float s = 0.f;
    #pragma unroll 4
    for (int t = 0; t < 112; t++) s += __bfloat162float(p[(size_t)t * 256]);
    part[((size_t)c * NB + b) * 256 + m] = s;
}

__global__ void kpsum_reduce(const float* __restrict__ part, float* __restrict__ ks) {
    int b = blockIdx.x, m = threadIdx.x;
    float s = 0.f;
    #pragma unroll
    for (int c = 0; c < 28; c++) s += part[((size_t)c * NB + b) * 256 + m];
    ks[b * 256 + m] = s;
}

// D[r] = qp[r,:] . ks[b,:]   (qp bf16)
__global__ void d_kernel(const __nv_bfloat16* __restrict__ qp, const float* __restrict__ ks,
                         float* __restrict__ D) {
    int r = blockIdx.x * 8 + (threadIdx.x >> 5);
    int lane = threadIdx.x & 31;
    int b = r / (int)TT;
    const __nv_bfloat16* q = qp + (size_t)r * 256;
    const float* s = ks + b * 256;
    float acc = 0.f;
    #pragma unroll
    for (int j = lane; j < 256; j += 32) acc += __bfloat162float(q[j]) * s[j];
    #pragma unroll
    for (int o = 16; o; o >>= 1) acc += __shfl_xor_sync(0xffffffffu, acc, o);
    if (!lane) D[r] = acc;
}

// 32x32 tiled transpose, fp32 in -> bf16 out
__global__ void transpose_f2b(const float* __restrict__ in, int ldin, long long strIn,
                              __nv_bfloat16* __restrict__ out, int ldout, long long strOut,
                              int rows, int cols) {
    __shared__ float tile[32][33];
    const float* inp = in + (size_t)blockIdx.z * strIn;
    __nv_bfloat16* outp = out + (size_t)blockIdx.z * strOut;
    int bx = blockIdx.x * 32, by = blockIdx.y * 32;
    int x = bx + threadIdx.x;
    #pragma unroll
    for (int j = threadIdx.y; j < 32; j += 8) {
        int y = by + j;
        tile[j][threadIdx.x] = (y < rows && x < cols) ? inp[(size_t)y * ldin + x] : 0.f;
    }
    __syncthreads();
    int ox = by + threadIdx.x;
    #pragma unroll
    for (int j = threadIdx.y; j < 32; j += 8) {
        int oy = bx + j;
        if (oy < cols && ox < rows)
            outp[(size_t)oy * ldout + ox] = __float2bfloat16(tile[threadIdx.x][j]);
    }
}

// 32x32 tiled transpose, bf16 in -> bf16 out
__global__ void transpose_b2b(const __nv_bfloat16* __restrict__ in, int ldin, long long strIn,
                              __nv_bfloat16* __restrict__ out, int ldout, long long strOut,
                              int rows, int cols) {
    __shared__ __nv_bfloat16 tile[32][34];
    const __nv_bfloat16* inp = in + (size_t)blockIdx.z * strIn;
    __nv_bfloat16* outp = out + (size_t)blockIdx.z * strOut;
    int bx = blockIdx.x * 32, by = blockIdx.y * 32;
    int x = bx + threadIdx.x;
    #pragma unroll
    for (int j = threadIdx.y; j < 32; j += 8) {
        int y = by + j;
        tile[j][threadIdx.x] = (y < rows && x < cols) ? inp[(size_t)y * ldin + x]
                                                      : __float2bfloat16(0.f);
    }
    __syncthreads();
    int ox = by + threadIdx.x;
    #pragma unroll
    for (int j = threadIdx.y; j < 32; j += 8) {
        int oy = bx + j;
        if (oy < cols && ox < rows) outp[(size_t)oy * ldout + ox] = tile[threadIdx.x][j];
    }
}

// merged weight transpose: wkqv -> fp32; wproj/wm1/wm2 -> bf16
__global__ void transpose_weights(const float* __restrict__ wkqv,
                                  const float* __restrict__ wproj,
                                  const float* __restrict__ wm1,
                                  const float* __restrict__ wm2,
                                  float* __restrict__ okqv,
                                  __nv_bfloat16* __restrict__ oproj,
                                  __nv_bfloat16* __restrict__ om1,
                                  __nv_bfloat16* __restrict__ om2) {
    __shared__ float tile[32][33];
    int bx = blockIdx.x;
    const float* in; int ldin, ct, region;
    __nv_bfloat16* outb = nullptr;
    if (bx < 48)      { in = wkqv;  ldin = 1536; ct = bx;      region = 0; }
    else if (bx < 64) { in = wproj; ldin = 512;  ct = bx - 48; region = 1; outb = oproj; }
    else if (bx < 80) { in = wm1;   ldin = 512;  ct = bx - 64; region = 2; outb = om1; }
    else              { in = wm2;   ldin = 512;  ct = bx - 80; region = 3; outb = om2; }
    int c0 = ct * 32, r0 = blockIdx.y * 32;
    int x = c0 + threadIdx.x;
    #pragma unroll
    for (int j = threadIdx.y; j < 32; j += 8)
        tile[j][threadIdx.x] = in[(size_t)(r0 + j) * ldin + x];
    __syncthreads();
    int ox = r0 + threadIdx.x;
    #pragma unroll
    for (int j = threadIdx.y; j < 32; j += 8) {
        float v = tile[threadIdx.x][j];
        if (region == 0) okqv[(size_t)(c0 + j) * 512 + ox] = v;
        else             outb[(size_t)(c0 + j) * 512 + ox] = __float2bfloat16(v);
    }
}

// ------------------------- tf32 GEMM (NT), 128x256 tile ---------------------
// C[m,n] = sum_k A[m,k]*B[n,k]. 8 warps (2m x 4n), warp tile 64x64, GBK=32.
// smem row stride 40 floats (160B): conflict-free k-permuted LDS.64 frags.
// EPI: 1 = +bias (fp32 out), 4 = exp(v - rowv)/16 (bf16 out when OB=1).
#define T32_STAGE 61440
#define T32_SMEM  122880

template <int EPI, int OB>
__global__ __launch_bounds__(256, 1) void tgemm32(
    const float* __restrict__ A, int lda,
    const float* __restrict__ B, int ldb,
    void* __restrict__ Cv, int ldc,
    int Mdim, int K,
    const float* __restrict__ bias,
    const float* __restrict__ rowv) {
    extern __shared__ __align__(16) char smem[];
    const uint32_t sbase = (uint32_t)__cvta_generic_to_shared(smem);
    const int tid = threadIdx.x;
    const int wid = tid >> 5, lane = tid & 31;
    const int wm = wid & 1, wn = wid >> 1;       // 2 m-warps x 4 n-warps
    const int grp = lane >> 2, tig = lane & 3;

    const int m0 = blockIdx.y * 128;
    const int n0 = blockIdx.x * 256;

    // copy map: 12 chunks (A 4, B 8), 16B each, per stage
    uint32_t soff[12];
    const char* gp[12];
    #pragma unroll
    for (int i = 0; i < 12; i++) {
        if (i < 4) {
            int q = tid + i * 256;                 // 0..1023
            int r = q >> 3, kc = q & 7;
            soff[i] = (uint32_t)(r * 160 + kc * 16);
            gp[i] = (const char*)(A + (size_t)(m0 + r) * lda + kc * 4);
        } else {
            int q = tid + (i - 4) * 256;           // 0..2047
            int r = q >> 3, kc = q & 7;
            soff[i] = (uint32_t)(20480 + r * 160 + kc * 16);
            gp[i] = (const char*)(B + (size_t)(n0 + r) * ldb + kc * 4);
        }
    }

    float acc[4][8][4];
    #pragma unroll
    for (int mi = 0; mi < 4; mi++)
        #pragma unroll
        for (int ni = 0; ni < 8; ni++)
            #pragma unroll
            for (int j = 0; j < 4; j++) acc[mi][ni][j] = 0.f;

    const int nk = K / 32;
    #pragma unroll
    for (int i = 0; i < 12; i++) cp_async16(sbase + soff[i], gp[i], true);
    CP_COMMIT();

    for (int it = 0; it < nk; it++) {
        CP_WAIT0();
        __syncthreads();
        if (it + 1 < nk) {
            const uint32_t sb1 = sbase + ((it + 1) & 1) * T32_STAGE;
            const int adv = (it + 1) * 128;   // 32 floats
            #pragma unroll
            for (int i = 0; i < 12; i++) cp_async16(sb1 + soff[i], gp[i] + adv, true);
            CP_COMMIT();
        }
        const char* sb = smem + (it & 1) * T32_STAGE;
        #pragma unroll
        for (int kk = 0; kk < 32; kk += 8) {
            unsigned af[4][4], bf[8][2];
            #pragma unroll
            for (int mi = 0; mi < 4; mi++) {
                int r = wm * 64 + mi * 16 + grp;
                float2 a0 = *(const float2*)(sb + (r * 40 + kk + 2 * tig) * 4);
                float2 a1 = *(const float2*)(sb + ((r + 8) * 40 + kk + 2 * tig) * 4);
                af[mi][0] = __float_as_uint(a0.x);
                af[mi][2] = __float_as_uint(a0.y);
                af[mi][1] = __float_as_uint(a1.x);
                af[mi][3] = __float_as_uint(a1.y);
            }
            #pragma unroll
            for (int ni = 0; ni < 8; ni++) {
                int c = wn * 64 + ni * 8 + grp;
                float2 b0 = *(const float2*)(sb + 20480 + (c * 40 + kk + 2 * tig) * 4);
                bf[ni][0] = __float_as_uint(b0.x);
                bf[ni][1] = __float_as_uint(b0.y);
            }
            #pragma unroll
            for (int mi = 0; mi < 4; mi++)
                #pragma unroll
                for (int ni = 0; ni < 8; ni++)
                    mma_tf32(acc[mi][ni], af[mi], bf[ni]);
        }
    }

    // epilogue
    #pragma unroll
    for (int mi = 0; mi < 4; mi++) {
        #pragma unroll
        for (int half = 0; half < 2; half++) {
            int r = m0 + wm * 64 + mi * 16 + grp + half * 8;
            if (r >= Mdim) continue;
            float rv = (EPI == 4) ? rowv[r] : 0.f;
            #pragma unroll
            for (int ni = 0; ni < 8; ni++) {
                int c = n0 + wn * 64 + ni * 8 + tig * 2;
                float v0 = acc[mi][ni][half * 2 + 0];
                float v1 = acc[mi][ni][half * 2 + 1];
                if (EPI == 1) { v0 += bias[c]; v1 += bias[c + 1]; }
                if (EPI == 4) {
                    v0 = expf(v0 - rv) * 0.0625f;
                    v1 = expf(v1 - rv) * 0.0625f;
                }
                if (OB) {
                    __nv_bfloat16* cp = (__nv_bfloat16*)Cv + (size_t)r * ldc + c;
                    *(__nv_bfloat162*)cp = __floats2bfloat162_rn(v0, v1);
                } else {
                    float* cp = (float*)Cv + (size_t)r * ldc + c;
                    *(float2*)cp = make_float2(v0, v1);
                }
            }
        }
    }
}

// ------------------------- bf16 GEMM (NT), 128x256 tile ---------------------
// m16n8k16 bf16, fp32 accum. smem row stride 48 halfwords (96B), GBK=32.
// EPI: 0 none, 2 gelu(+bias), 3 +bias+resid(fp32), 5 /(rowv+eps).
#define B16_STAGE 36864
#define B16_SMEM  73728

template <int EPI, int OB>
__global__ __launch_bounds__(256, 1) void bgemm(
    const __nv_bfloat16* __restrict__ A, int lda, long long strA,
    const __nv_bfloat16* __restrict__ B, int ldb, long long strB,
    void* __restrict__ Cv, int ldc, long long strC,
    int Mdim, int K,
    const float* __restrict__ bias,
    const float* __restrict__ rowv, long long strRow,
    const float* __restrict__ resid, long long strRes) {
    extern __shared__ __align__(16) char smem[];
    const uint32_t sbase = (uint32_t)__cvta_generic_to_shared(smem);
    const int tid = threadIdx.x;
    const int wid = tid >> 5, lane = tid & 31;
    const int wm = wid & 1, wn = wid >> 1;
    const int grp = lane >> 2, tig = lane & 3;

    A += (size_t)blockIdx.z * strA;
    B += (size_t)blockIdx.z * strB;
    if (rowv)  rowv  += (size_t)blockIdx.z * strRow;
    if (resid) resid += (size_t)blockIdx.z * strRes;
    const size_t cOff = (size_t)blockIdx.z * strC;

    const int m0 = blockIdx.y * 128;
    const int n0 = blockIdx.x * 256;

    // copy map: 6 chunks (A 2, B 4), 16B each, per stage
    uint32_t soff[6];
    const char* gp[6];
    bool pred[6];
    #pragma unroll
    for (int i = 0; i < 6; i++) {
        if (i < 2) {
            int q = tid + i * 256;                 // 0..511
            int r = q >> 2, kc = q & 3;
            soff[i] = (uint32_t)(r * 96 + kc * 16);
            gp[i] = (const char*)(A + (size_t)(m0 + r) * lda + kc * 8);
            pred[i] = (m0 + r) < Mdim;
        } else {
            int q = tid + (i - 2) * 256;           // 0..1023
            int r = q >> 2, kc = q & 3;
            soff[i] = (uint32_t)(12288 + r * 96 + kc * 16);
            gp[i] = (const char*)(B + (size_t)(n0 + r) * ldb + kc * 8);
            pred[i] = true;
        }
    }

    float acc[4][8][4];
    #pragma unroll
    for (int mi = 0; mi < 4; mi++)
        #pragma unroll
        for (int ni = 0; ni < 8; ni++)
            #pragma unroll
            for (int j = 0; j < 4; j++) acc[mi][ni][j] = 0.f;

    const int nk = K / 32;
    #pragma unroll
    for (int i = 0; i < 6; i++) cp_async16(sbase + soff[i], gp[i], pred[i]);
    CP_COMMIT();

    for (int it = 0; it < nk; it++) {
        CP_WAIT0();
        __syncthreads();
        if (it + 1 < nk) {
            const uint32_t sb1 = sbase + ((it + 1) & 1) * B16_STAGE;
            const int adv = (it + 1) * 64;   // 32 bf16
            #pragma unroll
            for (int i = 0; i < 6; i++) cp_async16(sb1 + soff[i], gp[i] + adv, pred[i]);
            CP_COMMIT();
        }
        const char* sb = smem + (it & 1) * B16_STAGE;
        #pragma unroll
        for (int kk = 0; kk < 32; kk += 16) {
            unsigned af[4][4], bf[8][2];
            #pragma unroll
            for (int mi = 0; mi < 4; mi++) {
                int r = wm * 64 + mi * 16 + grp;
                uint2 a0 = *(const uint2*)(sb + r * 96 + (kk + 4 * tig) * 2);
                uint2 a1 = *(const uint2*)(sb + (r + 8) * 96 + (kk + 4 * tig) * 2);
                af[mi][0] = a0.x; af[mi][2] = a0.y;
                af[mi][1] = a1.x; af[mi][3] = a1.y;
            }
            #pragma unroll
            for (int ni = 0; ni < 8; ni++) {
                int c = wn * 64 + ni * 8 + grp;
                uint2 b0 = *(const uint2*)(sb + 12288 + c * 96 + (kk + 4 * tig) * 2);
                bf[ni][0] = b0.x; bf[ni][1] = b0.y;
            }
            #pragma unroll
            for (int mi = 0; mi < 4; mi++)
                #pragma unroll
                for (int ni = 0; ni < 8; ni++)
                    mma_bf16(acc[mi][ni], af[mi], bf[ni]);
        }
    }

    // epilogue
    #pragma unroll
    for (int mi = 0; mi < 4; mi++) {
        #pragma unroll
        for (int half = 0; half < 2; half++) {
            int r = m0 + wm * 64 + mi * 16 + grp + half * 8;
            if (r >= Mdim) continue;
            float invd = 0.f;
            if (EPI == 5) invd = 1.0f / (rowv[r] + 1e-8f);
            #pragma unroll
            for (int ni = 0; ni < 8; ni++) {
                int c = n0 + wn * 64 + ni * 8 + tig * 2;
                float v0 = acc[mi][ni][half * 2 + 0];
                float v1 = acc[mi][ni][half * 2 + 1];
                if (EPI == 2 || EPI == 3) { v0 += bias[c]; v1 += bias[c + 1]; }
                if (EPI == 2) { v0 = gelu_exact(v0); v1 = gelu_exact(v1); }
                if (EPI == 3) {
                    float2 rr = *(const float2*)(resid + (size_t)r * ldc + c);
                    v0 += rr.x; v1 += rr.y;
                }
                if (EPI == 5) { v0 *= invd; v1 *= invd; }
                if (OB) {
                    __nv_bfloat16* cp = (__nv_bfloat16*)Cv + cOff + (size_t)r * ldc + c;
                    *(__nv_bfloat162*)cp = __floats2bfloat162_rn(v0, v1);
                } else {
                    float* cp = (float*)Cv + cOff + (size_t)r * ldc + c;
                    *(float2*)cp = make_float2(v0, v1);
                }
            }
        }
    }
}

// ------------------------------- driver -------------------------------------
extern "C" void kernel_launch(void* const* d_in, const int* in_sizes, int n_in,
                              void* d_out, int out_size) {
    const float* x      = (const float*)d_in[0];
    const float* w_kqv  = (const float*)d_in[1];
    const float* b_kqv  = (const float*)d_in[2];
    const float* w_proj = (const float*)d_in[3];
    const float* b_proj = (const float*)d_in[4];
    const float* g1     = (const float*)d_in[5];
    const float* be1    = (const float*)d_in[6];
    const float* g2     = (const float*)d_in[7];
    const float* be2    = (const float*)d_in[8];
    const float* w_mlp1 = (const float*)d_in[9];
    const float* b_mlp1 = (const float*)d_in[10];
    const float* w_mlp2 = (const float*)d_in[11];
    const float* b_mlp2 = (const float*)d_in[12];
    const float* w_rand = (const float*)d_in[13];
    float* out = (float*)d_out;

    float* S = nullptr;
    cudaGetSymbolAddress((void**)&S, g_scratch);

    float* h1     = S + OFF_H1;
    float* kqv    = S + OFF_KQV;
    __nv_bfloat16* kpb   = (__nv_bfloat16*)(S + OFF_KP);
    __nv_bfloat16* qpb   = (__nv_bfloat16*)(S + OFF_QP);
    float* xdk    = S + OFF_XDK;
    float* xdq    = S + OFF_XDQ;
    float* Dv     = S + OFF_DV;
    float* ks     = S + OFF_KS;
    float* ksp    = S + OFF_KSP;
    __nv_bfloat16* vTb   = (__nv_bfloat16*)(S + OFF_VT);
    __nv_bfloat16* kpTb  = (__nv_bfloat16*)(S + OFF_KPT);
    __nv_bfloat16* kptvb = (__nv_bfloat16*)(S + OFF_KPTV);
    __nv_bfloat16* yb    = (__nv_bfloat16*)(S + OFF_Y);
    float* xres   = S + OFF_XRES;
    __nv_bfloat16* h2b   = (__nv_bfloat16*)(S + OFF_H2);
    __nv_bfloat16* hmb   = (__nv_bfloat16*)(S + OFF_HM);
    float* wkqvT  = S + OFF_WKQVT;
    __nv_bfloat16* wprojTb = (__nv_bfloat16*)(S + OFF_WPROJT);
    __nv_bfloat16* wm1Tb   = (__nv_bfloat16*)(S + OFF_WM1T);
    __nv_bfloat16* wm2Tb   = (__nv_bfloat16*)(S + OFF_WM2T);

    cudaFuncSetAttribute(tgemm32<1,0>, cudaFuncAttributeMaxDynamicSharedMemorySize, T32_SMEM);
    cudaFuncSetAttribute(tgemm32<4,1>, cudaFuncAttributeMaxDynamicSharedMemorySize, T32_SMEM);
    cudaFuncSetAttribute(bgemm<0,1>,   cudaFuncAttributeMaxDynamicSharedMemorySize, B16_SMEM);
    cudaFuncSetAttribute(bgemm<5,1>,   cudaFuncAttributeMaxDynamicSharedMemorySize, B16_SMEM);
    cudaFuncSetAttribute(bgemm<3,0>,   cudaFuncAttributeMaxDynamicSharedMemorySize, B16_SMEM);
    cudaFuncSetAttribute(bgemm<2,1>,   cudaFuncAttributeMaxDynamicSharedMemorySize, B16_SMEM);

    const int BT = (int)BTC;
    const float* nullf = nullptr;
    dim3 tb(32, 8);

    // 1. h1 = LN(x)   (fp32 out)
    ln_kernel<0><<<BT, 128>>>(x, g1, be1, (void*)h1);

    // 2. weight transposes (wkqv fp32; proj/mlp bf16)
    transpose_weights<<<dim3(96, 16), tb>>>(w_kqv, w_proj, w_mlp1, w_mlp2,
                                            wkqvT, wprojTb, wm1Tb, wm2Tb);

    // 3. kqv = h1 @ w_kqv + b_kqv   (tf32, fp32 out)
    tgemm32<1,0><<<dim3(6, 392), 256, T32_SMEM>>>(h1, 512, wkqvT, 512,
                                                  kqv, 1536, BT, 512, b_kqv, nullf);

    // 4. xd_k, xd_q
    rownorm_kernel<<<BT, 128>>>(kqv, xdk, xdq);

    // 5. kp/qp = exp(k|q @ w_rand^T - xd)/16   (tf32, bf16 out)
    tgemm32<4,1><<<dim3(1, 392), 256, T32_SMEM>>>(kqv, 1536, w_rand, 512,
                                                  kpb, 256, BT, 512, nullf, xdk);
    tgemm32<4,1><<<dim3(1, 392), 256, T32_SMEM>>>(kqv + 512, 1536, w_rand, 512,
                                                  qpb, 256, BT, 512, nullf, xdq);

    // 6. ks = sum_t kp
    kpsum_part<<<dim3(28, 16), 256>>>(kpb, ksp);
    kpsum_reduce<<<16, 256>>>(ksp, ks);

    // 7. D = qp . ks
    d_kernel<<<BT / 8, 256>>>(qpb, ks, Dv);

    // 8. transposes into K-major bf16
    transpose_f2b<<<dim3(16, 98, 16), tb>>>(kqv + 1024, 1536, TT * 1536,
                                            vTb, (int)TT, 512 * TT, (int)TT, 512);
    transpose_b2b<<<dim3(8, 98, 16), tb>>>(kpb, 256, TT * 256,
                                           kpTb, (int)TT, 256 * TT, (int)TT, 256);

    // 9. kptv[b] = vT @ kpT^T   (bf16, M=512, N=256, K=3136)
    bgemm<0,1><<<dim3(1, 4, 16), 256, B16_SMEM>>>(vTb, (int)TT, 512 * TT,
                                                  kpTb, (int)TT, 256 * TT,
                                                  kptvb, 256, 512 * 256, 512, (int)TT,
                                                  nullf, nullf, 0, nullf, 0);

    // 10. y[b] = (qp @ kptv^T) / (D + eps)   (bf16, M=3136, N=512, K=256)
    bgemm<5,1><<<dim3(2, 25, 16), 256, B16_SMEM>>>(qpb, 256, TT * 256,
                                                   kptvb, 256, 512 * 256,
                                                   yb, 512, TT * 512, (int)TT, 256,
                                                   nullf, Dv, TT, nullf, 0);

    // 11. xres = x + y @ w_proj + b_proj   (bf16 gemm, fp32 out)
    bgemm<3,0><<<dim3(2, 392, 1), 256, B16_SMEM>>>(yb, 512, 0, wprojTb, 512, 0,
                                                   xres, 512, 0, BT, 512,
                                                   b_proj, nullf, 0, x, 0);

    // 12. h2 = LN(xres)   (bf16 out)
    ln_kernel<1><<<BT, 128>>>(xres, g2, be2, (void*)h2b);

    // 13. hm = gelu(h2 @ w_mlp1 + b_mlp1)   (bf16 out)
    bgemm<2,1><<<dim3(2, 392, 1), 256, B16_SMEM>>>(h2b, 512, 0, wm1Tb, 512, 0,
                                                   hmb, 512, 0, BT, 512,
                                                   b_mlp1, nullf, 0, nullf, 0);

    // 14. out = xres + hm @ w_mlp2 + b_mlp2   (fp32 out)
    bgemm<3,0><<<dim3(2, 392, 1), 256, B16_SMEM>>>(hmb, 512, 0, wm2Tb, 512, 0,
                                                   out, 512, 0, BT, 512,
                                                   b_mlp2, nullf, 0, xres, 0);
}

// round 8
// speedup vs baseline: 1.9093x; 1.1826x over previous
#include <cuda_runtime.h>
#include <cuda_bf16.h>
#include <math.h>
#include <stdint.h>

// ---------------------------------------------------------------------------
// Token performer block. mma.sync path (tcgen05 unavailable on this target).
// kqv + all streaming GEMMs in bf16 m16n8k16; exp-feature GEMMs (kp,qp) in
// tf32 m16n8k8 for precision. 128x256 CTA tiles, GBK=32, 2-stage cp.async.
// R8: kqv->bf16 with fused rownorm epilogue, kptv split-K x7.
// ---------------------------------------------------------------------------

#define BTC 50176LL          // B*T
#define TT  3136LL
#define NB  16LL

constexpr long long OFF_H1    = 0;                       // h1 bf16 / kptv partials fp32
constexpr long long OFF_KQV   = OFF_H1    + BTC*512;
constexpr long long OFF_KP    = OFF_KQV   + BTC*1536;
constexpr long long OFF_QP    = OFF_KP    + BTC*256;
constexpr long long OFF_XDK   = OFF_QP    + BTC*256;
constexpr long long OFF_XDQ   = OFF_XDK   + BTC;
constexpr long long OFF_DV    = OFF_XDQ   + BTC;
constexpr long long OFF_KS    = OFF_DV    + BTC;
constexpr long long OFF_KSP   = OFF_KS    + NB*256;
constexpr long long OFF_VT    = OFF_KSP   + 28LL*NB*256;
constexpr long long OFF_KPT   = OFF_VT    + NB*512*TT;
constexpr long long OFF_KPTV  = OFF_KPT   + NB*256*TT;
constexpr long long OFF_Y     = OFF_KPTV  + NB*512*256;
constexpr long long OFF_XRES  = OFF_Y     + BTC*512;
constexpr long long OFF_H2    = OFF_XRES  + BTC*512;
constexpr long long OFF_HM    = OFF_H2    + BTC*512;
constexpr long long OFF_WKQVT = OFF_HM    + BTC*512;
constexpr long long OFF_WPROJT= OFF_WKQVT + 1536LL*512;
constexpr long long OFF_WM1T  = OFF_WPROJT+ 512LL*512;
constexpr long long OFF_WM2T  = OFF_WM1T  + 512LL*512;
constexpr long long SCRATCH_TOTAL = OFF_WM2T + 512LL*512;

__device__ __align__(128) float g_scratch[SCRATCH_TOTAL];

// ---------------------------- helpers --------------------------------------
__device__ __forceinline__ void mma_tf32(float c[4], const unsigned a[4], const unsigned b[2]) {
    asm volatile(
        "mma.sync.aligned.m16n8k8.row.col.f32.tf32.tf32.f32 "
        "{%0,%1,%2,%3}, {%4,%5,%6,%7}, {%8,%9}, {%0,%1,%2,%3};\n"
        : "+f"(c[0]), "+f"(c[1]), "+f"(c[2]), "+f"(c[3])
        : "r"(a[0]), "r"(a[1]), "r"(a[2]), "r"(a[3]), "r"(b[0]), "r"(b[1]));
}

__device__ __forceinline__ void mma_bf16(float c[4], const unsigned a[4], const unsigned b[2]) {
    asm volatile(
        "mma.sync.aligned.m16n8k16.row.col.f32.bf16.bf16.f32 "
        "{%0,%1,%2,%3}, {%4,%5,%6,%7}, {%8,%9}, {%0,%1,%2,%3};\n"
        : "+f"(c[0]), "+f"(c[1]), "+f"(c[2]), "+f"(c[3])
        : "r"(a[0]), "r"(a[1]), "r"(a[2]), "r"(a[3]), "r"(b[0]), "r"(b[1]));
}

__device__ __forceinline__ void cp_async16(uint32_t saddr, const void* gmem, bool pred) {
    int sz = pred ? 16 : 0;   // src-size 0 => zero-fill, no gmem access
    asm volatile("cp.async.cg.shared.global [%0], [%1], 16, %2;\n"
                 :: "r"(saddr), "l"(gmem), "r"(sz));
}
#define CP_COMMIT() asm volatile("cp.async.commit_group;\n" ::: "memory")
#define CP_WAIT0()  asm volatile("cp.async.wait_group 0;\n" ::: "memory")

__device__ __forceinline__ float gelu_exact(float x) {
    return 0.5f * x * (1.0f + erff(x * 0.7071067811865476f));
}

// ------------------------------ LayerNorm -----------------------------------
template <int OB>
__global__ void ln_kernel(const float* __restrict__ in, const float* __restrict__ g,
                          const float* __restrict__ be, void* __restrict__ outv) {
    int r = blockIdx.x;
    int t = threadIdx.x;         // 128 threads, 4 floats each
    const float4* p = (const float4*)(in + (size_t)r * 512);
    float4 v = p[t];
    float s  = v.x + v.y + v.z + v.w;
    float sq = v.x*v.x + v.y*v.y + v.z*v.z + v.w*v.w;
    #pragma unroll
    for (int o = 16; o; o >>= 1) {
        s  += __shfl_xor_sync(0xffffffffu, s,  o);
        sq += __shfl_xor_sync(0xffffffffu, sq, o);
    }
    __shared__ float shs[4], shq[4];
    int wid = t >> 5, lane = t & 31;
    if (!lane) { shs[wid] = s; shq[wid] = sq; }
    __syncthreads();
    s  = shs[0] + shs[1] + shs[2] + shs[3];
    sq = shq[0] + shq[1] + shq[2] + shq[3];
    float mu  = s * (1.0f / 512.0f);
    float var = sq * (1.0f / 512.0f) - mu * mu;
    float inv = rsqrtf(var + 1e-5f);
    float4 gg = ((const float4*)g)[t];
    float4 bb = ((const float4*)be)[t];
    float4 o;
    o.x = (v.x - mu) * inv * gg.x + bb.x;
    o.y = (v.y - mu) * inv * gg.y + bb.y;
    o.z = (v.z - mu) * inv * gg.z + bb.z;
    o.w = (v.w - mu) * inv * gg.w + bb.w;
    if (OB) {
        __nv_bfloat16* ob = (__nv_bfloat16*)outv + (size_t)r * 512 + t * 4;
        *(__nv_bfloat162*)(ob)     = __floats2bfloat162_rn(o.x, o.y);
        *(__nv_bfloat162*)(ob + 2) = __floats2bfloat162_rn(o.z, o.w);
    } else {
        ((float4*)((float*)outv + (size_t)r * 512))[t] = o;
    }
}

// ks partial sums over t-chunks (bf16 kp in, fp32 partials)
__global__ void kpsum_part(const __nv_bfloat16* __restrict__ kp, float* __restrict__ part) {
    int b = blockIdx.y, c = blockIdx.x, m = threadIdx.x;  // 256 threads
    const __nv_bfloat16* p = kp + ((size_t)b * TT + (size_t)c * 112) * 256 + m;
    float s = 0.f;
    #pragma unroll 4
    for (int t = 0; t < 112; t++) s += __bfloat162float(p[(size_t)t * 256]);
    part[((size_t)c * NB + b) * 256 + m] = s;
}

__global__ void kpsum_reduce(const float* __restrict__ part, float* __restrict__ ks) {
    int b = blockIdx.x, m = threadIdx.x;
    float s = 0.f;
    #pragma unroll
    for (int c = 0; c < 28; c++) s += part[((size_t)c * NB + b) * 256 + m];
    ks[b * 256 + m] = s;
}

// D[r] = qp[r,:] . ks[b,:]   (qp bf16)
__global__ void d_kernel(const __nv_bfloat16* __restrict__ qp, const float* __restrict__ ks,
                         float* __restrict__ D) {
    int r = blockIdx.x * 8 + (threadIdx.x >> 5);
    int lane = threadIdx.x & 31;
    int b = r / (int)TT;
    const __nv_bfloat16* q = qp + (size_t)r * 256;
    const float* s = ks + b * 256;
    float acc = 0.f;
    #pragma unroll
    for (int j = lane; j < 256; j += 32) acc += __bfloat162float(q[j]) * s[j];
    #pragma unroll
    for (int o = 16; o; o >>= 1) acc += __shfl_xor_sync(0xffffffffu, acc, o);
    if (!lane) D[r] = acc;
}

// 32x32 tiled transpose, fp32 in -> bf16 out
__global__ void transpose_f2b(const float* __restrict__ in, int ldin, long long strIn,
                              __nv_bfloat16* __restrict__ out, int ldout, long long strOut,
                              int rows, int cols) {
    __shared__ float tile[32][33];
    const float* inp = in + (size_t)blockIdx.z * strIn;
    __nv_bfloat16* outp = out + (size_t)blockIdx.z * strOut;
    int bx = blockIdx.x * 32, by = blockIdx.y * 32;
    int x = bx + threadIdx.x;
    #pragma unroll
    for (int j = threadIdx.y; j < 32; j += 8) {
        int y = by + j;
        tile[j][threadIdx.x] = (y < rows && x < cols) ? inp[(size_t)y * ldin + x] : 0.f;
    }
    __syncthreads();
    int ox = by + threadIdx.x;
    #pragma unroll
    for (int j = threadIdx.y; j < 32; j += 8) {
        int oy = bx + j;
        if (oy < cols && ox < rows)
            outp[(size_t)oy * ldout + ox] = __float2bfloat16(tile[threadIdx.x][j]);
    }
}

// 32x32 tiled transpose, bf16 in -> bf16 out
__global__ void transpose_b2b(const __nv_bfloat16* __restrict__ in, int ldin, long long strIn,
                              __nv_bfloat16* __restrict__ out, int ldout, long long strOut,
                              int rows, int cols) {
    __shared__ __nv_bfloat16 tile[32][34];
    const __nv_bfloat16* inp = in + (size_t)blockIdx.z * strIn;
    __nv_bfloat16* outp = out + (size_t)blockIdx.z * strOut;
    int bx = blockIdx.x * 32, by = blockIdx.y * 32;
    int x = bx + threadIdx.x;
    #pragma unroll
    for (int j = threadIdx.y; j < 32; j += 8) {
        int y = by + j;
        tile[j][threadIdx.x] = (y < rows && x < cols) ? inp[(size_t)y * ldin + x]
                                                      : __float2bfloat16(0.f);
    }
    __syncthreads();
    int ox = by + threadIdx.x;
    #pragma unroll
    for (int j = threadIdx.y; j < 32; j += 8) {
        int oy = bx + j;
        if (oy < cols && ox < rows) outp[(size_t)oy * ldout + ox] = tile[threadIdx.x][j];
    }
}

// merged weight transpose: wkqv/wproj/wm1/wm2 -> bf16 NT form
__global__ void transpose_weights(const float* __restrict__ wkqv,
                                  const float* __restrict__ wproj,
                                  const float* __restrict__ wm1,
                                  const float* __restrict__ wm2,
                                  __nv_bfloat16* __restrict__ okqv,
                                  __nv_bfloat16* __restrict__ oproj,
                                  __nv_bfloat16* __restrict__ om1,
                                  __nv_bfloat16* __restrict__ om2) {
    __shared__ float tile[32][33];
    int bx = blockIdx.x;
    const float* in; int ldin, ct;
    __nv_bfloat16* outb;
    if (bx < 48)      { in = wkqv;  ldin = 1536; ct = bx;      outb = okqv; }
    else if (bx < 64) { in = wproj; ldin = 512;  ct = bx - 48; outb = oproj; }
    else if (bx < 80) { in = wm1;   ldin = 512;  ct = bx - 64; outb = om1; }
    else              { in = wm2;   ldin = 512;  ct = bx - 80; outb = om2; }
    int c0 = ct * 32, r0 = blockIdx.y * 32;
    int x = c0 + threadIdx.x;
    #pragma unroll
    for (int j = threadIdx.y; j < 32; j += 8)
        tile[j][threadIdx.x] = in[(size_t)(r0 + j) * ldin + x];
    __syncthreads();
    int ox = r0 + threadIdx.x;
    #pragma unroll
    for (int j = threadIdx.y; j < 32; j += 8)
        outb[(size_t)(c0 + j) * 512 + ox] = __float2bfloat16(tile[threadIdx.x][j]);
}

// reduce split-K kptv partials (7 chunks) -> bf16
__global__ void reduce_kptv(const float* __restrict__ part, __nv_bfloat16* __restrict__ out) {
    int idx = blockIdx.x * 256 + threadIdx.x;   // over 16*131072
    float s = 0.f;
    #pragma unroll
    for (int c = 0; c < 7; c++) s += part[(size_t)c * 2097152 + idx];
    out[idx] = __float2bfloat16(s);
}

// ------------------------- tf32 GEMM (NT), 128x256 tile ---------------------
// EPI: 4 = exp(v - rowv)/16 (bf16 out).
#define T32_STAGE 61440
#define T32_SMEM  122880

template <int EPI, int OB>
__global__ __launch_bounds__(256, 1) void tgemm32(
    const float* __restrict__ A, int lda,
    const float* __restrict__ B, int ldb,
    void* __restrict__ Cv, int ldc,
    int Mdim, int K,
    const float* __restrict__ bias,
    const float* __restrict__ rowv) {
    extern __shared__ __align__(16) char smem[];
    const uint32_t sbase = (uint32_t)__cvta_generic_to_shared(smem);
    const int tid = threadIdx.x;
    const int wid = tid >> 5, lane = tid & 31;
    const int wm = wid & 1, wn = wid >> 1;
    const int grp = lane >> 2, tig = lane & 3;

    const int m0 = blockIdx.y * 128;
    const int n0 = blockIdx.x * 256;

    uint32_t soff[12];
    const char* gp[12];
    #pragma unroll
    for (int i = 0; i < 12; i++) {
        if (i < 4) {
            int q = tid + i * 256;
            int r = q >> 3, kc = q & 7;
            soff[i] = (uint32_t)(r * 160 + kc * 16);
            gp[i] = (const char*)(A + (size_t)(m0 + r) * lda + kc * 4);
        } else {
            int q = tid + (i - 4) * 256;
            int r = q >> 3, kc = q & 7;
            soff[i] = (uint32_t)(20480 + r * 160 + kc * 16);
            gp[i] = (const char*)(B + (size_t)(n0 + r) * ldb + kc * 4);
        }
    }

    float acc[4][8][4];
    #pragma unroll
    for (int mi = 0; mi < 4; mi++)
        #pragma unroll
        for (int ni = 0; ni < 8; ni++)
            #pragma unroll
            for (int j = 0; j < 4; j++) acc[mi][ni][j] = 0.f;

    const int nk = K / 32;
    #pragma unroll
    for (int i = 0; i < 12; i++) cp_async16(sbase + soff[i], gp[i], true);
    CP_COMMIT();

    for (int it = 0; it < nk; it++) {
        CP_WAIT0();
        __syncthreads();
        if (it + 1 < nk) {
            const uint32_t sb1 = sbase + ((it + 1) & 1) * T32_STAGE;
            const int adv = (it + 1) * 128;
            #pragma unroll
            for (int i = 0; i < 12; i++) cp_async16(sb1 + soff[i], gp[i] + adv, true);
            CP_COMMIT();
        }
        const char* sb = smem + (it & 1) * T32_STAGE;
        #pragma unroll
        for (int kk = 0; kk < 32; kk += 8) {
            unsigned af[4][4], bf[8][2];
            #pragma unroll
            for (int mi = 0; mi < 4; mi++) {
                int r = wm * 64 + mi * 16 + grp;
                float2 a0 = *(const float2*)(sb + (r * 40 + kk + 2 * tig) * 4);
                float2 a1 = *(const float2*)(sb + ((r + 8) * 40 + kk + 2 * tig) * 4);
                af[mi][0] = __float_as_uint(a0.x);
                af[mi][2] = __float_as_uint(a0.y);
                af[mi][1] = __float_as_uint(a1.x);
                af[mi][3] = __float_as_uint(a1.y);
            }
            #pragma unroll
            for (int ni = 0; ni < 8; ni++) {
                int c = wn * 64 + ni * 8 + grp;
                float2 b0 = *(const float2*)(sb + 20480 + (c * 40 + kk + 2 * tig) * 4);
                bf[ni][0] = __float_as_uint(b0.x);
                bf[ni][1] = __float_as_uint(b0.y);
            }
            #pragma unroll
            for (int mi = 0; mi < 4; mi++)
                #pragma unroll
                for (int ni = 0; ni < 8; ni++)
                    mma_tf32(acc[mi][ni], af[mi], bf[ni]);
        }
    }

    #pragma unroll
    for (int mi = 0; mi < 4; mi++) {
        #pragma unroll
        for (int half = 0; half < 2; half++) {
            int r = m0 + wm * 64 + mi * 16 + grp + half * 8;
            if (r >= Mdim) continue;
            float rv = (EPI == 4) ? rowv[r] : 0.f;
            #pragma unroll
            for (int ni = 0; ni < 8; ni++) {
                int c = n0 + wn * 64 + ni * 8 + tig * 2;
                float v0 = acc[mi][ni][half * 2 + 0];
                float v1 = acc[mi][ni][half * 2 + 1];
                if (EPI == 1) { v0 += bias[c]; v1 += bias[c + 1]; }
                if (EPI == 4) {
                    v0 = expf(v0 - rv) * 0.0625f;
                    v1 = expf(v1 - rv) * 0.0625f;
                }
                if (OB) {
                    __nv_bfloat16* cp = (__nv_bfloat16*)Cv + (size_t)r * ldc + c;
                    *(__nv_bfloat162*)cp = __floats2bfloat162_rn(v0, v1);
                } else {
                    float* cp = (float*)Cv + (size_t)r * ldc + c;
                    *(float2*)cp = make_float2(v0, v1);
                }
            }
        }
    }
}

// ------------------------- bf16 GEMM (NT), 128x256 tile ---------------------
// EPI: 0 none, 1 +bias (+optional fused xd row-sumsq), 2 gelu(+bias),
//      3 +bias+resid(fp32), 5 /(rowv+eps).
// zdiv: blockIdx.z = kc*zdiv + bz; bz indexes batch strides, kc*K is k-offset.
#define B16_STAGE 36864
#define B16_SMEM  73728

template <int EPI, int OB>
__global__ __launch_bounds__(256, 1) void bgemm(
    const __nv_bfloat16* __restrict__ A, int lda, long long strA,
    const __nv_bfloat16* __restrict__ B, int ldb, long long strB,
    void* __restrict__ Cv, int ldc, long long strC,
    int Mdim, int K, int zdiv,
    const float* __restrict__ bias,
    const float* __restrict__ rowv, long long strRow,
    const float* __restrict__ resid, long long strRes,
    float* __restrict__ xdk, float* __restrict__ xdq) {
    extern __shared__ __align__(16) char smem[];
    __shared__ float sxd[4][128];
    const uint32_t sbase = (uint32_t)__cvta_generic_to_shared(smem);
    const int tid = threadIdx.x;
    const int wid = tid >> 5, lane = tid & 31;
    const int wm = wid & 1, wn = wid >> 1;
    const int grp = lane >> 2, tig = lane & 3;

    const int bz = blockIdx.z % zdiv;
    const int kc = blockIdx.z / zdiv;
    A += (size_t)bz * strA + (size_t)kc * K;
    B += (size_t)bz * strB + (size_t)kc * K;
    if (rowv)  rowv  += (size_t)bz * strRow;
    if (resid) resid += (size_t)bz * strRes;
    const size_t cOff = (size_t)blockIdx.z * strC;

    const int m0 = blockIdx.y * 128;
    const int n0 = blockIdx.x * 256;

    float* xdp = nullptr;
    if (EPI == 1) {
        int seg = n0 >> 9;
        xdp = (seg == 0) ? xdk : ((seg == 1) ? xdq : nullptr);
    }

    uint32_t soff[6];
    const char* gp[6];
    bool pred[6];
    #pragma unroll
    for (int i = 0; i < 6; i++) {
        if (i < 2) {
            int q = tid + i * 256;
            int r = q >> 2, kcq = q & 3;
            soff[i] = (uint32_t)(r * 96 + kcq * 16);
            gp[i] = (const char*)(A + (size_t)(m0 + r) * lda + kcq * 8);
            pred[i] = (m0 + r) < Mdim;
        } else {
            int q = tid + (i - 2) * 256;
            int r = q >> 2, kcq = q & 3;
            soff[i] = (uint32_t)(12288 + r * 96 + kcq * 16);
            gp[i] = (const char*)(B + (size_t)(n0 + r) * ldb + kcq * 8);
            pred[i] = true;
        }
    }

    float acc[4][8][4];
    #pragma unroll
    for (int mi = 0; mi < 4; mi++)
        #pragma unroll
        for (int ni = 0; ni < 8; ni++)
            #pragma unroll
            for (int j = 0; j < 4; j++) acc[mi][ni][j] = 0.f;

    const int nk = K / 32;
    #pragma unroll
    for (int i = 0; i < 6; i++) cp_async16(sbase + soff[i], gp[i], pred[i]);
    CP_COMMIT();

    for (int it = 0; it < nk; it++) {
        CP_WAIT0();
        __syncthreads();
        if (it + 1 < nk) {
            const uint32_t sb1 = sbase + ((it + 1) & 1) * B16_STAGE;
            const int adv = (it + 1) * 64;
            #pragma unroll
            for (int i = 0; i < 6; i++) cp_async16(sb1 + soff[i], gp[i] + adv, pred[i]);
            CP_COMMIT();
        }
        const char* sb = smem + (it & 1) * B16_STAGE;
        #pragma unroll
        for (int kk = 0; kk < 32; kk += 16) {
            unsigned af[4][4], bf[8][2];
            #pragma unroll
            for (int mi = 0; mi < 4; mi++) {
                int r = wm * 64 + mi * 16 + grp;
                uint2 a0 = *(const uint2*)(sb + r * 96 + (kk + 4 * tig) * 2);
                uint2 a1 = *(const uint2*)(sb + (r + 8) * 96 + (kk + 4 * tig) * 2);
                af[mi][0] = a0.x; af[mi][2] = a0.y;
                af[mi][1] = a1.x; af[mi][3] = a1.y;
            }
            #pragma unroll
            for (int ni = 0; ni < 8; ni++) {
                int c = wn * 64 + ni * 8 + grp;
                uint2 b0 = *(const uint2*)(sb + 12288 + c * 96 + (kk + 4 * tig) * 2);
                bf[ni][0] = b0.x; bf[ni][1] = b0.y;
            }
            #pragma unroll
            for (int mi = 0; mi < 4; mi++)
                #pragma unroll
                for (int ni = 0; ni < 8; ni++)
                    mma_bf16(acc[mi][ni], af[mi], bf[ni]);
        }
    }

    // epilogue (+ optional fused row sum-of-squares for xd)
    #pragma unroll
    for (int mi = 0; mi < 4; mi++) {
        #pragma unroll
        for (int half = 0; half < 2; half++) {
            int r = m0 + wm * 64 + mi * 16 + grp + half * 8;
            float ss = 0.f;
            if (r < Mdim) {
                float invd = 0.f;
                if (EPI == 5) invd = 1.0f / (rowv[r] + 1e-8f);
                #pragma unroll
                for (int ni = 0; ni < 8; ni++) {
                    int c = n0 + wn * 64 + ni * 8 + tig * 2;
                    float v0 = acc[mi][ni][half * 2 + 0];
                    float v1 = acc[mi][ni][half * 2 + 1];
                    if (EPI == 1 || EPI == 2 || EPI == 3) { v0 += bias[c]; v1 += bias[c + 1]; }
                    if (EPI == 2) { v0 = gelu_exact(v0); v1 = gelu_exact(v1); }
                    if (EPI == 3) {
                        float2 rr = *(const float2*)(resid + (size_t)r * ldc + c);
                        v0 += rr.x; v1 += rr.y;
                    }
                    if (EPI == 5) { v0 *= invd; v1 *= invd; }
                    if (EPI == 1) ss += v0 * v0 + v1 * v1;
                    if (OB) {
                        __nv_bfloat16* cp = (__nv_bfloat16*)Cv + cOff + (size_t)r * ldc + c;
                        *(__nv_bfloat162*)cp = __floats2bfloat162_rn(v0, v1);
                    } else {
                        float* cp = (float*)Cv + cOff + (size_t)r * ldc + c;
                        *(float2*)cp = make_float2(v0, v1);
                    }
                }
            }
            if (EPI == 1) {
                ss += __shfl_xor_sync(0xffffffffu, ss, 1);
                ss += __shfl_xor_sync(0xffffffffu, ss, 2);
                if (tig == 0) sxd[wn][wm * 64 + mi * 16 + grp + half * 8] = ss;
            }
        }
    }
    if (EPI == 1) {
        __syncthreads();
        if (xdp && tid < 128 && (m0 + tid) < Mdim) {
            float s = sxd[0][tid] + sxd[1][tid] + sxd[2][tid] + sxd[3][tid];
            atomicAdd(&xdp[m0 + tid], 0.5f * s);   // exactly 2 contributions/row
        }
    }
}

// ------------------------------- driver -------------------------------------
extern "C" void kernel_launch(void* const* d_in, const int* in_sizes, int n_in,
                              void* d_out, int out_size) {
    const float* x      = (const float*)d_in[0];
    const float* w_kqv  = (const float*)d_in[1];
    const float* b_kqv  = (const float*)d_in[2];
    const float* w_proj = (const float*)d_in[3];
    const float* b_proj = (const float*)d_in[4];
    const float* g1     = (const float*)d_in[5];
    const float* be1    = (const float*)d_in[6];
    const float* g2     = (const float*)d_in[7];
    const float* be2    = (const float*)d_in[8];
    const float* w_mlp1 = (const float*)d_in[9];
    const float* b_mlp1 = (const float*)d_in[10];
    const float* w_mlp2 = (const float*)d_in[11];
    const float* b_mlp2 = (const float*)d_in[12];
    const float* w_rand = (const float*)d_in[13];
    float* out = (float*)d_out;

    float* S = nullptr;
    cudaGetSymbolAddress((void**)&S, g_scratch);

    __nv_bfloat16* h1b   = (__nv_bfloat16*)(S + OFF_H1);
    float* kpart  = S + OFF_H1;               // reused after kqv consumes h1
    float* kqv    = S + OFF_KQV;
    __nv_bfloat16* kpb   = (__nv_bfloat16*)(S + OFF_KP);
    __nv_bfloat16* qpb   = (__nv_bfloat16*)(S + OFF_QP);
    float* xdk    = S + OFF_XDK;
    float* xdq    = S + OFF_XDQ;
    float* Dv     = S + OFF_DV;
    float* ks     = S + OFF_KS;
    float* ksp    = S + OFF_KSP;
    __nv_bfloat16* vTb   = (__nv_bfloat16*)(S + OFF_VT);
    __nv_bfloat16* kpTb  = (__nv_bfloat16*)(S + OFF_KPT);
    __nv_bfloat16* kptvb = (__nv_bfloat16*)(S + OFF_KPTV);
    __nv_bfloat16* yb    = (__nv_bfloat16*)(S + OFF_Y);
    float* xres   = S + OFF_XRES;
    __nv_bfloat16* h2b   = (__nv_bfloat16*)(S + OFF_H2);
    __nv_bfloat16* hmb   = (__nv_bfloat16*)(S + OFF_HM);
    __nv_bfloat16* wkqvTb  = (__nv_bfloat16*)(S + OFF_WKQVT);
    __nv_bfloat16* wprojTb = (__nv_bfloat16*)(S + OFF_WPROJT);
    __nv_bfloat16* wm1Tb   = (__nv_bfloat16*)(S + OFF_WM1T);
    __nv_bfloat16* wm2Tb   = (__nv_bfloat16*)(S + OFF_WM2T);

    cudaFuncSetAttribute(tgemm32<4,1>, cudaFuncAttributeMaxDynamicSharedMemorySize, T32_SMEM);
    cudaFuncSetAttribute(bgemm<0,0>,   cudaFuncAttributeMaxDynamicSharedMemorySize, B16_SMEM);
    cudaFuncSetAttribute(bgemm<1,0>,   cudaFuncAttributeMaxDynamicSharedMemorySize, B16_SMEM);
    cudaFuncSetAttribute(bgemm<5,1>,   cudaFuncAttributeMaxDynamicSharedMemorySize, B16_SMEM);
    cudaFuncSetAttribute(bgemm<3,0>,   cudaFuncAttributeMaxDynamicSharedMemorySize, B16_SMEM);
    cudaFuncSetAttribute(bgemm<2,1>,   cudaFuncAttributeMaxDynamicSharedMemorySize, B16_SMEM);

    const int BT = (int)BTC;
    const float* nullf = nullptr;
    float* nullx = nullptr;
    dim3 tb(32, 8);

    // 1. h1 = LN(x)  (bf16)
    ln_kernel<1><<<BT, 128>>>(x, g1, be1, (void*)h1b);

    // 2. weight transposes (all bf16)
    transpose_weights<<<dim3(96, 16), tb>>>(w_kqv, w_proj, w_mlp1, w_mlp2,
                                            wkqvTb, wprojTb, wm1Tb, wm2Tb);

    // 3. zero xd accumulators (xdk,xdq adjacent)
    cudaMemsetAsync(xdk, 0, 2 * BTC * sizeof(float));

    // 4. kqv = h1 @ w_kqv + b_kqv  (bf16 gemm, fp32 out) + fused xd row-sumsq
    bgemm<1,0><<<dim3(6, 392, 1), 256, B16_SMEM>>>(h1b, 512, 0, wkqvTb, 512, 0,
                                                   kqv, 1536, 0, BT, 512, 1,
                                                   b_kqv, nullf, 0, nullf, 0,
                                                   xdk, xdq);

    // 5. kp/qp = exp(k|q @ w_rand^T - xd)/16  (tf32, bf16 out)
    tgemm32<4,1><<<dim3(1, 392), 256, T32_SMEM>>>(kqv, 1536, w_rand, 512,
                                                  kpb, 256, BT, 512, nullf, xdk);
    tgemm32<4,1><<<dim3(1, 392), 256, T32_SMEM>>>(kqv + 512, 1536, w_rand, 512,
                                                  qpb, 256, BT, 512, nullf, xdq);

    // 6. ks = sum_t kp
    kpsum_part<<<dim3(28, 16), 256>>>(kpb, ksp);
    kpsum_reduce<<<16, 256>>>(ksp, ks);

    // 7. D = qp . ks
    d_kernel<<<BT / 8, 256>>>(qpb, ks, Dv);

    // 8. transposes into K-major bf16
    transpose_f2b<<<dim3(16, 98, 16), tb>>>(kqv + 1024, 1536, TT * 1536,
                                            vTb, (int)TT, 512 * TT, (int)TT, 512);
    transpose_b2b<<<dim3(8, 98, 16), tb>>>(kpb, 256, TT * 256,
                                           kpTb, (int)TT, 256 * TT, (int)TT, 256);

    // 9. kptv split-K x7: partials (fp32) then reduce -> bf16
    bgemm<0,0><<<dim3(1, 4, 112), 256, B16_SMEM>>>(vTb, (int)TT, 512 * TT,
                                                   kpTb, (int)TT, 256 * TT,
                                                   kpart, 256, 131072, 512, 448, 16,
                                                   nullf, nullf, 0, nullf, 0,
                                                   nullx, nullx);
    reduce_kptv<<<8192, 256>>>(kpart, kptvb);

    // 10. y[b] = (qp @ kptv^T) / (D + eps)  (bf16)
    bgemm<5,1><<<dim3(2, 25, 16), 256, B16_SMEM>>>(qpb, 256, TT * 256,
                                                   kptvb, 256, 512 * 256,
                                                   yb, 512, TT * 512, (int)TT, 256, 16,
                                                   nullf, Dv, TT, nullf, 0,
                                                   nullx, nullx);

    // 11. xres = x + y @ w_proj + b_proj  (fp32 out)
    bgemm<3,0><<<dim3(2, 392, 1), 256, B16_SMEM>>>(yb, 512, 0, wprojTb, 512, 0,
                                                   xres, 512, 0, BT, 512, 1,
                                                   b_proj, nullf, 0, x, 0,
                                                   nullx, nullx);

    // 12. h2 = LN(xres)  (bf16)
    ln_kernel<1><<<BT, 128>>>(xres, g2, be2, (void*)h2b);

    // 13. hm = gelu(h2 @ w_mlp1 + b_mlp1)  (bf16)
    bgemm<2,1><<<dim3(2, 392, 1), 256, B16_SMEM>>>(h2b, 512, 0, wm1Tb, 512, 0,
                                                   hmb, 512, 0, BT, 512, 1,
                                                   b_mlp1, nullf, 0, nullf, 0,
                                                   nullx, nullx);

    // 14. out = xres + hm @ w_mlp2 + b_mlp2  (fp32 out)
    bgemm<3,0><<<dim3(2, 392, 1), 256, B16_SMEM>>>(hmb, 512, 0, wm2Tb, 512, 0,
                                                   out, 512, 0, BT, 512, 1,
                                                   b_mlp2, nullf, 0, xres, 0,
                                                   nullx, nullx);
}

// round 10
// speedup vs baseline: 2.1787x; 1.1411x over previous
#include <cuda_runtime.h>
#include <cuda_bf16.h>
#include <math.h>
#include <stdint.h>

// ---------------------------------------------------------------------------
// Token performer block. mma.sync bf16 m16n8k16 everywhere (fp32 accumulate);
// error analysis + R8 measurement show the exp-feature path tolerates bf16
// (k/q perturbations cancel in the qp.kptv / qp.ks ratio).
// 128x256 CTA tiles, GBK=64, 2-stage cp.async, k-permuted LDS.64 fragments.
// R9: bf16 kqv out (fused xd), merged kp+qp launch, GBK 32->64, tf32 removed.
// ---------------------------------------------------------------------------

#define BTC 50176LL          // B*T
#define TT  3136LL
#define NB  16LL

constexpr long long OFF_H1    = 0;                       // h1 bf16 / kptv partials fp32
constexpr long long OFF_KQV   = OFF_H1    + BTC*512;     // kqv bf16 (half used)
constexpr long long OFF_KP    = OFF_KQV   + BTC*1536;
constexpr long long OFF_QP    = OFF_KP    + BTC*256;
constexpr long long OFF_XDK   = OFF_QP    + BTC*256;
constexpr long long OFF_XDQ   = OFF_XDK   + BTC;
constexpr long long OFF_DV    = OFF_XDQ   + BTC;
constexpr long long OFF_KS    = OFF_DV    + BTC;
constexpr long long OFF_KSP   = OFF_KS    + NB*256;
constexpr long long OFF_VT    = OFF_KSP   + 28LL*NB*256;
constexpr long long OFF_KPT   = OFF_VT    + NB*512*TT;
constexpr long long OFF_KPTV  = OFF_KPT   + NB*256*TT;
constexpr long long OFF_Y     = OFF_KPTV  + NB*512*256;
constexpr long long OFF_XRES  = OFF_Y     + BTC*512;
constexpr long long OFF_H2    = OFF_XRES  + BTC*512;
constexpr long long OFF_HM    = OFF_H2    + BTC*512;
constexpr long long OFF_WKQVT = OFF_HM    + BTC*512;
constexpr long long OFF_WPROJT= OFF_WKQVT + 1536LL*512;
constexpr long long OFF_WM1T  = OFF_WPROJT+ 512LL*512;
constexpr long long OFF_WM2T  = OFF_WM1T  + 512LL*512;
constexpr long long OFF_WRB   = OFF_WM2T  + 512LL*512;   // bf16 w_rand (half used)
constexpr long long SCRATCH_TOTAL = OFF_WRB + 256LL*512;

__device__ __align__(128) float g_scratch[SCRATCH_TOTAL];

// ---------------------------- helpers --------------------------------------
__device__ __forceinline__ void mma_bf16(float c[4], const unsigned a[4], const unsigned b[2]) {
    asm volatile(
        "mma.sync.aligned.m16n8k16.row.col.f32.bf16.bf16.f32 "
        "{%0,%1,%2,%3}, {%4,%5,%6,%7}, {%8,%9}, {%0,%1,%2,%3};\n"
        : "+f"(c[0]), "+f"(c[1]), "+f"(c[2]), "+f"(c[3])
        : "r"(a[0]), "r"(a[1]), "r"(a[2]), "r"(a[3]), "r"(b[0]), "r"(b[1]));
}

__device__ __forceinline__ void cp_async16(uint32_t saddr, const void* gmem, bool pred) {
    int sz = pred ? 16 : 0;   // src-size 0 => zero-fill, no gmem access
    asm volatile("cp.async.cg.shared.global [%0], [%1], 16, %2;\n"
                 :: "r"(saddr), "l"(gmem), "r"(sz));
}
#define CP_COMMIT() asm volatile("cp.async.commit_group;\n" ::: "memory")
#define CP_WAIT0()  asm volatile("cp.async.wait_group 0;\n" ::: "memory")

__device__ __forceinline__ float gelu_exact(float x) {
    return 0.5f * x * (1.0f + erff(x * 0.7071067811865476f));
}

// ------------------------------ LayerNorm -----------------------------------
__global__ void ln_kernel(const float* __restrict__ in, const float* __restrict__ g,
                          const float* __restrict__ be, __nv_bfloat16* __restrict__ outv) {
    int r = blockIdx.x;
    int t = threadIdx.x;         // 128 threads, 4 floats each
    const float4* p = (const float4*)(in + (size_t)r * 512);
    float4 v = p[t];
    float s  = v.x + v.y + v.z + v.w;
    float sq = v.x*v.x + v.y*v.y + v.z*v.z + v.w*v.w;
    #pragma unroll
    for (int o = 16; o; o >>= 1) {
        s  += __shfl_xor_sync(0xffffffffu, s,  o);
        sq += __shfl_xor_sync(0xffffffffu, sq, o);
    }
    __shared__ float shs[4], shq[4];
    int wid = t >> 5, lane = t & 31;
    if (!lane) { shs[wid] = s; shq[wid] = sq; }
    __syncthreads();
    s  = shs[0] + shs[1] + shs[2] + shs[3];
    sq = shq[0] + shq[1] + shq[2] + shq[3];
    float mu  = s * (1.0f / 512.0f);
    float var = sq * (1.0f / 512.0f) - mu * mu;
    float inv = rsqrtf(var + 1e-5f);
    float4 gg = ((const float4*)g)[t];
    float4 bb = ((const float4*)be)[t];
    float4 o;
    o.x = (v.x - mu) * inv * gg.x + bb.x;
    o.y = (v.y - mu) * inv * gg.y + bb.y;
    o.z = (v.z - mu) * inv * gg.z + bb.z;
    o.w = (v.w - mu) * inv * gg.w + bb.w;
    __nv_bfloat16* ob = outv + (size_t)r * 512 + t * 4;
    *(__nv_bfloat162*)(ob)     = __floats2bfloat162_rn(o.x, o.y);
    *(__nv_bfloat162*)(ob + 2) = __floats2bfloat162_rn(o.z, o.w);
}

// ks partial sums over t-chunks (bf16 kp in, fp32 partials)
__global__ void kpsum_part(const __nv_bfloat16* __restrict__ kp, float* __restrict__ part) {
    int b = blockIdx.y, c = blockIdx.x, m = threadIdx.x;  // 256 threads
    const __nv_bfloat16* p = kp + ((size_t)b * TT + (size_t)c * 112) * 256 + m;
    float s = 0.f;
    #pragma unroll 4
    for (int t = 0; t < 112; t++) s += __bfloat162float(p[(size_t)t * 256]);
    part[((size_t)c * NB + b) * 256 + m] = s;
}

__global__ void kpsum_reduce(const float* __restrict__ part, float* __restrict__ ks) {
    int b = blockIdx.x, m = threadIdx.x;
    float s = 0.f;
    #pragma unroll
    for (int c = 0; c < 28; c++) s += part[((size_t)c * NB + b) * 256 + m];
    ks[b * 256 + m] = s;
}

// D[r] = qp[r,:] . ks[b,:]   (qp bf16)
__global__ void d_kernel(const __nv_bfloat16* __restrict__ qp, const float* __restrict__ ks,
                         float* __restrict__ D) {
    int r = blockIdx.x * 8 + (threadIdx.x >> 5);
    int lane = threadIdx.x & 31;
    int b = r / (int)TT;
    const __nv_bfloat16* q = qp + (size_t)r * 256;
    const float* s = ks + b * 256;
    float acc = 0.f;
    #pragma unroll
    for (int j = lane; j < 256; j += 32) acc += __bfloat162float(q[j]) * s[j];
    #pragma unroll
    for (int o = 16; o; o >>= 1) acc += __shfl_xor_sync(0xffffffffu, acc, o);
    if (!lane) D[r] = acc;
}

// 32x32 tiled transpose, bf16 in -> bf16 out
__global__ void transpose_b2b(const __nv_bfloat16* __restrict__ in, int ldin, long long strIn,
                              __nv_bfloat16* __restrict__ out, int ldout, long long strOut,
                              int rows, int cols) {
    __shared__ __nv_bfloat16 tile[32][34];
    const __nv_bfloat16* inp = in + (size_t)blockIdx.z * strIn;
    __nv_bfloat16* outp = out + (size_t)blockIdx.z * strOut;
    int bx = blockIdx.x * 32, by = blockIdx.y * 32;
    int x = bx + threadIdx.x;
    #pragma unroll
    for (int j = threadIdx.y; j < 32; j += 8) {
        int y = by + j;
        tile[j][threadIdx.x] = (y < rows && x < cols) ? inp[(size_t)y * ldin + x]
                                                      : __float2bfloat16(0.f);
    }
    __syncthreads();
    int ox = by + threadIdx.x;
    #pragma unroll
    for (int j = threadIdx.y; j < 32; j += 8) {
        int oy = bx + j;
        if (oy < cols && ox < rows) outp[(size_t)oy * ldout + ox] = tile[threadIdx.x][j];
    }
}

// merged weight transpose: wkqv/wproj/wm1/wm2 -> bf16 NT form
__global__ void transpose_weights(const float* __restrict__ wkqv,
                                  const float* __restrict__ wproj,
                                  const float* __restrict__ wm1,
                                  const float* __restrict__ wm2,
                                  __nv_bfloat16* __restrict__ okqv,
                                  __nv_bfloat16* __restrict__ oproj,
                                  __nv_bfloat16* __restrict__ om1,
                                  __nv_bfloat16* __restrict__ om2) {
    __shared__ float tile[32][33];
    int bx = blockIdx.x;
    const float* in; int ldin, ct;
    __nv_bfloat16* outb;
    if (bx < 48)      { in = wkqv;  ldin = 1536; ct = bx;      outb = okqv; }
    else if (bx < 64) { in = wproj; ldin = 512;  ct = bx - 48; outb = oproj; }
    else if (bx < 80) { in = wm1;   ldin = 512;  ct = bx - 64; outb = om1; }
    else              { in = wm2;   ldin = 512;  ct = bx - 80; outb = om2; }
    int c0 = ct * 32, r0 = blockIdx.y * 32;
    int x = c0 + threadIdx.x;
    #pragma unroll
    for (int j = threadIdx.y; j < 32; j += 8)
        tile[j][threadIdx.x] = in[(size_t)(r0 + j) * ldin + x];
    __syncthreads();
    int ox = r0 + threadIdx.x;
    #pragma unroll
    for (int j = threadIdx.y; j < 32; j += 8)
        outb[(size_t)(c0 + j) * 512 + ox] = __float2bfloat16(tile[threadIdx.x][j]);
}

// fp32 -> bf16 copy of w_rand (already NT form: [256, 512])
__global__ void convert_wrand(const float* __restrict__ in, __nv_bfloat16* __restrict__ out) {
    int i = blockIdx.x * 256 + threadIdx.x;   // 131072 elems
    out[i] = __float2bfloat16(in[i]);
}

// reduce split-K kptv partials (7 chunks) -> bf16
__global__ void reduce_kptv(const float* __restrict__ part, __nv_bfloat16* __restrict__ out) {
    int idx = blockIdx.x * 256 + threadIdx.x;   // over 16*131072
    float s = 0.f;
    #pragma unroll
    for (int c = 0; c < 7; c++) s += part[(size_t)c * 2097152 + idx];
    out[idx] = __float2bfloat16(s);
}

// ------------------------- bf16 GEMM (NT), 128x256 tile, GBK=64 -------------
// EPI: 0 none, 1 +bias (+fused xd row-sumsq), 2 gelu(+bias),
//      3 +bias+resid(fp32), 4 exp(v-rowv)/16, 5 /(rowv+eps).
// zdiv: blockIdx.z = kc*zdiv + bz; bz indexes batch strides, kc*K is k-offset.
// smem row stride 80 halfwords (160B) -> conflict-free k-permuted LDS.64.
#define B16_STAGE 61440          // A 128*160 + B 256*160
#define B16_SMEM  122880

template <int EPI, int OB>
__global__ __launch_bounds__(256, 1) void bgemm(
    const __nv_bfloat16* __restrict__ A, int lda, long long strA,
    const __nv_bfloat16* __restrict__ B, int ldb, long long strB,
    void* __restrict__ Cv, int ldc, long long strC,
    int Mdim, int K, int zdiv,
    const float* __restrict__ bias,
    const float* __restrict__ rowv, long long strRow,
    const float* __restrict__ resid, long long strRes,
    float* __restrict__ xdk, float* __restrict__ xdq) {
    extern __shared__ __align__(16) char smem[];
    __shared__ float sxd[4][128];
    const uint32_t sbase = (uint32_t)__cvta_generic_to_shared(smem);
    const int tid = threadIdx.x;
    const int wid = tid >> 5, lane = tid & 31;
    const int wm = wid & 1, wn = wid >> 1;
    const int grp = lane >> 2, tig = lane & 3;

    const int bz = blockIdx.z % zdiv;
    const int kc = blockIdx.z / zdiv;
    A += (size_t)bz * strA + (size_t)kc * K;
    B += (size_t)bz * strB + (size_t)kc * K;
    if (rowv)  rowv  += (size_t)bz * strRow;
    if (resid) resid += (size_t)bz * strRes;
    const size_t cOff = (size_t)blockIdx.z * strC;

    const int m0 = blockIdx.y * 128;
    const int n0 = blockIdx.x * 256;

    float* xdp = nullptr;
    if (EPI == 1) {
        int seg = n0 >> 9;
        xdp = (seg == 0) ? xdk : ((seg == 1) ? xdq : nullptr);
    }

    // copy map: 12 x 16B per thread per stage (A 1024 chunks, B 2048 chunks)
    uint32_t soff[12];
    const char* gp[12];
    bool pred[12];
    #pragma unroll
    for (int i = 0; i < 12; i++) {
        if (i < 4) {
            int q = tid + i * 256;                 // 0..1023
            int r = q >> 3, kcq = q & 7;
            soff[i] = (uint32_t)(r * 160 + kcq * 16);
            gp[i] = (const char*)(A + (size_t)(m0 + r) * lda + kcq * 8);
            pred[i] = (m0 + r) < Mdim;
        } else {
            int q = tid + (i - 4) * 256;           // 0..2047
            int r = q >> 3, kcq = q & 7;
            soff[i] = (uint32_t)(20480 + r * 160 + kcq * 16);
            gp[i] = (const char*)(B + (size_t)(n0 + r) * ldb + kcq * 8);
            pred[i] = true;
        }
    }

    float acc[4][8][4];
    #pragma unroll
    for (int mi = 0; mi < 4; mi++)
        #pragma unroll
        for (int ni = 0; ni < 8; ni++)
            #pragma unroll
            for (int j = 0; j < 4; j++) acc[mi][ni][j] = 0.f;

    const int nk = K / 64;
    #pragma unroll
    for (int i = 0; i < 12; i++) cp_async16(sbase + soff[i], gp[i], pred[i]);
    CP_COMMIT();

    for (int it = 0; it < nk; it++) {
        CP_WAIT0();
        __syncthreads();
        if (it + 1 < nk) {
            const uint32_t sb1 = sbase + ((it + 1) & 1) * B16_STAGE;
            const int adv = (it + 1) * 128;   // 64 bf16 = 128 bytes
            #pragma unroll
            for (int i = 0; i < 12; i++) cp_async16(sb1 + soff[i], gp[i] + adv, pred[i]);
            CP_COMMIT();
        }
        const char* sb = smem + (it & 1) * B16_STAGE;
        #pragma unroll
        for (int kk = 0; kk < 64; kk += 16) {
            unsigned af[4][4], bf[8][2];
            #pragma unroll
            for (int mi = 0; mi < 4; mi++) {
                int r = wm * 64 + mi * 16 + grp;
                uint2 a0 = *(const uint2*)(sb + r * 160 + (kk + 4 * tig) * 2);
                uint2 a1 = *(const uint2*)(sb + (r + 8) * 160 + (kk + 4 * tig) * 2);
                af[mi][0] = a0.x; af[mi][2] = a0.y;
                af[mi][1] = a1.x; af[mi][3] = a1.y;
            }
            #pragma unroll
            for (int ni = 0; ni < 8; ni++) {
                int c = wn * 64 + ni * 8 + grp;
                uint2 b0 = *(const uint2*)(sb + 20480 + c * 160 + (kk + 4 * tig) * 2);
                bf[ni][0] = b0.x; bf[ni][1] = b0.y;
            }
            #pragma unroll
            for (int mi = 0; mi < 4; mi++)
                #pragma unroll
                for (int ni = 0; ni < 8; ni++)
                    mma_bf16(acc[mi][ni], af[mi], bf[ni]);
        }
    }

    // epilogue (+ optional fused row sum-of-squares for xd)
    #pragma unroll
    for (int mi = 0; mi < 4; mi++) {
        #pragma unroll
        for (int half = 0; half < 2; half++) {
            int r = m0 + wm * 64 + mi * 16 + grp + half * 8;
            float ss = 0.f;
            if (r < Mdim) {
                float invd = 0.f, rv = 0.f;
                if (EPI == 5) invd = 1.0f / (rowv[r] + 1e-8f);
                if (EPI == 4) rv = rowv[r];
                #pragma unroll
                for (int ni = 0; ni < 8; ni++) {
                    int c = n0 + wn * 64 + ni * 8 + tig * 2;
                    float v0 = acc[mi][ni][half * 2 + 0];
                    float v1 = acc[mi][ni][half * 2 + 1];
                    if (EPI == 1 || EPI == 2 || EPI == 3) { v0 += bias[c]; v1 += bias[c + 1]; }
                    if (EPI == 2) { v0 = gelu_exact(v0); v1 = gelu_exact(v1); }
                    if (EPI == 3) {
                        float2 rr = *(const float2*)(resid + (size_t)r * ldc + c);
                        v0 += rr.x; v1 += rr.y;
                    }
                    if (EPI == 4) {
                        v0 = expf(v0 - rv) * 0.0625f;
                        v1 = expf(v1 - rv) * 0.0625f;
                    }
                    if (EPI == 5) { v0 *= invd; v1 *= invd; }
                    if (EPI == 1) ss += v0 * v0 + v1 * v1;
                    if (OB) {
                        __nv_bfloat16* cp = (__nv_bfloat16*)Cv + cOff + (size_t)r * ldc + c;
                        *(__nv_bfloat162*)cp = __floats2bfloat162_rn(v0, v1);
                    } else {
                        float* cp = (float*)Cv + cOff + (size_t)r * ldc + c;
                        *(float2*)cp = make_float2(v0, v1);
                    }
                }
            }
            if (EPI == 1) {
                ss += __shfl_xor_sync(0xffffffffu, ss, 1);
                ss += __shfl_xor_sync(0xffffffffu, ss, 2);
                if (tig == 0) sxd[wn][wm * 64 + mi * 16 + grp + half * 8] = ss;
            }
        }
    }
    if (EPI == 1) {
        __syncthreads();
        if (xdp && tid < 128 && (m0 + tid) < Mdim) {
            float s = sxd[0][tid] + sxd[1][tid] + sxd[2][tid] + sxd[3][tid];
            atomicAdd(&xdp[m0 + tid], 0.5f * s);   // exactly 2 contributions/row
        }
    }
}

// ------------------------------- driver -------------------------------------
extern "C" void kernel_launch(void* const* d_in, const int* in_sizes, int n_in,
                              void* d_out, int out_size) {
    const float* x      = (const float*)d_in[0];
    const float* w_kqv  = (const float*)d_in[1];
    const float* b_kqv  = (const float*)d_in[2];
    const float* w_proj = (const float*)d_in[3];
    const float* b_proj = (const float*)d_in[4];
    const float* g1     = (const float*)d_in[5];
    const float* be1    = (const float*)d_in[6];
    const float* g2     = (const float*)d_in[7];
    const float* be2    = (const float*)d_in[8];
    const float* w_mlp1 = (const float*)d_in[9];
    const float* b_mlp1 = (const float*)d_in[10];
    const float* w_mlp2 = (const float*)d_in[11];
    const float* b_mlp2 = (const float*)d_in[12];
    const float* w_rand = (const float*)d_in[13];
    float* out = (float*)d_out;

    float* S = nullptr;
    cudaGetSymbolAddress((void**)&S, g_scratch);

    __nv_bfloat16* h1b   = (__nv_bfloat16*)(S + OFF_H1);
    float* kpart  = S + OFF_H1;               // reused after kqv consumes h1
    __nv_bfloat16* kqvb  = (__nv_bfloat16*)(S + OFF_KQV);
    __nv_bfloat16* kpb   = (__nv_bfloat16*)(S + OFF_KP);
    float* xdk    = S + OFF_XDK;
    float* xdq    = S + OFF_XDQ;
    float* Dv     = S + OFF_DV;
    float* ks     = S + OFF_KS;
    float* ksp    = S + OFF_KSP;
    __nv_bfloat16* vTb   = (__nv_bfloat16*)(S + OFF_VT);
    __nv_bfloat16* kpTb  = (__nv_bfloat16*)(S + OFF_KPT);
    __nv_bfloat16* kptvb = (__nv_bfloat16*)(S + OFF_KPTV);
    __nv_bfloat16* yb    = (__nv_bfloat16*)(S + OFF_Y);
    float* xres   = S + OFF_XRES;
    __nv_bfloat16* h2b   = (__nv_bfloat16*)(S + OFF_H2);
    __nv_bfloat16* hmb   = (__nv_bfloat16*)(S + OFF_HM);
    __nv_bfloat16* wkqvTb  = (__nv_bfloat16*)(S + OFF_WKQVT);
    __nv_bfloat16* wprojTb = (__nv_bfloat16*)(S + OFF_WPROJT);
    __nv_bfloat16* wm1Tb   = (__nv_bfloat16*)(S + OFF_WM1T);
    __nv_bfloat16* wm2Tb   = (__nv_bfloat16*)(S + OFF_WM2T);
    __nv_bfloat16* wrandb  = (__nv_bfloat16*)(S + OFF_WRB);

    // qp lives right after kp: stride BTC*512 bf16 elems (uses merged z launch)
    __nv_bfloat16* qpb = kpb + (size_t)BTC * 512;

    cudaFuncSetAttribute(bgemm<1,1>, cudaFuncAttributeMaxDynamicSharedMemorySize, B16_SMEM);
    cudaFuncSetAttribute(bgemm<4,1>, cudaFuncAttributeMaxDynamicSharedMemorySize, B16_SMEM);
    cudaFuncSetAttribute(bgemm<0,0>, cudaFuncAttributeMaxDynamicSharedMemorySize, B16_SMEM);
    cudaFuncSetAttribute(bgemm<5,1>, cudaFuncAttributeMaxDynamicSharedMemorySize, B16_SMEM);
    cudaFuncSetAttribute(bgemm<3,0>, cudaFuncAttributeMaxDynamicSharedMemorySize, B16_SMEM);
    cudaFuncSetAttribute(bgemm<2,1>, cudaFuncAttributeMaxDynamicSharedMemorySize, B16_SMEM);

    const int BT = (int)BTC;
    const float* nullf = nullptr;
    float* nullx = nullptr;
    dim3 tb(32, 8);

    // 1. h1 = LN(x)  (bf16)
    ln_kernel<<<BT, 128>>>(x, g1, be1, h1b);

    // 2. weight transposes (bf16) + w_rand bf16 copy
    transpose_weights<<<dim3(96, 16), tb>>>(w_kqv, w_proj, w_mlp1, w_mlp2,
                                            wkqvTb, wprojTb, wm1Tb, wm2Tb);
    convert_wrand<<<512, 256>>>(w_rand, wrandb);

    // 3. zero xd accumulators (xdk,xdq adjacent)
    cudaMemsetAsync(xdk, 0, 2 * BTC * sizeof(float));

    // 4. kqv = h1 @ w_kqv + b_kqv  (bf16 out) + fused xd row-sumsq
    bgemm<1,1><<<dim3(6, 392, 1), 256, B16_SMEM>>>(h1b, 512, 0, wkqvTb, 512, 0,
                                                   kqvb, 1536, 0, BT, 512, 1,
                                                   b_kqv, nullf, 0, nullf, 0,
                                                   xdk, xdq);

    // 5. kp/qp = exp((k|q) @ w_rand^T - xd)/16  (merged, z=0 -> k, z=1 -> q)
    bgemm<4,1><<<dim3(1, 392, 2), 256, B16_SMEM>>>(kqvb, 1536, 512, wrandb, 512, 0,
                                                   kpb, 256, (long long)BTC * 512,
                                                   BT, 512, 2,
                                                   nullf, xdk, BTC, nullf, 0,
                                                   nullx, nullx);

    // 6. ks = sum_t kp
    kpsum_part<<<dim3(28, 16), 256>>>(kpb, ksp);
    kpsum_reduce<<<16, 256>>>(ksp, ks);

    // 7. D = qp . ks
    d_kernel<<<BT / 8, 256>>>(qpb, ks, Dv);

    // 8. transposes into K-major bf16
    transpose_b2b<<<dim3(16, 98, 16), tb>>>(kqvb + 1024, 1536, TT * 1536,
                                            vTb, (int)TT, 512 * TT, (int)TT, 512);
    transpose_b2b<<<dim3(8, 98, 16), tb>>>(kpb, 256, TT * 256,
                                           kpTb, (int)TT, 256 * TT, (int)TT, 256);

    // 9. kptv split-K x7: partials (fp32) then reduce -> bf16
    bgemm<0,0><<<dim3(1, 4, 112), 256, B16_SMEM>>>(vTb, (int)TT, 512 * TT,
                                                   kpTb, (int)TT, 256 * TT,
                                                   kpart, 256, 131072, 512, 448, 16,
                                                   nullf, nullf, 0, nullf, 0,
                                                   nullx, nullx);
    reduce_kptv<<<8192, 256>>>(kpart, kptvb);

    // 10. y[b] = (qp @ kptv^T) / (D + eps)  (bf16)
    bgemm<5,1><<<dim3(2, 25, 16), 256, B16_SMEM>>>(qpb, 256, TT * 256,
                                                   kptvb, 256, 512 * 256,
                                                   yb, 512, TT * 512, (int)TT, 256, 16,
                                                   nullf, Dv, TT, nullf, 0,
                                                   nullx, nullx);

    // 11. xres = x + y @ w_proj + b_proj  (fp32 out)
    bgemm<3,0><<<dim3(2, 392, 1), 256, B16_SMEM>>>(yb, 512, 0, wprojTb, 512, 0,
                                                   xres, 512, 0, BT, 512, 1,
                                                   b_proj, nullf, 0, x, 0,
                                                   nullx, nullx);

    // 12. h2 = LN(xres)  (bf16)
    ln_kernel<<<BT, 128>>>(xres, g2, be2, h2b);

    // 13. hm = gelu(h2 @ w_mlp1 + b_mlp1)  (bf16)
    bgemm<2,1><<<dim3(2, 392, 1), 256, B16_SMEM>>>(h2b, 512, 0, wm1Tb, 512, 0,
                                                   hmb, 512, 0, BT, 512, 1,
                                                   b_mlp1, nullf, 0, nullf, 0,
                                                   nullx, nullx);

    // 14. out = xres + hm @ w_mlp2 + b_mlp2  (fp32 out)
    bgemm<3,0><<<dim3(2, 392, 1), 256, B16_SMEM>>>(hmb, 512, 0, wm2Tb, 512, 0,
                                                   out, 512, 0, BT, 512, 1,
                                                   b_mlp2, nullf, 0, xres, 0,
                                                   nullx, nullx);
}

// round 11
// speedup vs baseline: 2.1974x; 1.0086x over previous
#include <cuda_runtime.h>
#include <cuda_bf16.h>
#include <math.h>
#include <stdint.h>

// ---------------------------------------------------------------------------
// Token performer block. mma.sync bf16 m16n8k16 everywhere (fp32 accumulate).
// 128x256 CTA tiles, GBK=64, 3-stage cp.async pipeline (wait_group 1),
// k-permuted LDS.64 fragments, fused epilogues.
// R10: pipeline depth 2 -> 3 to close the latency bubble seen at occ=12.5%.
// ---------------------------------------------------------------------------

#define BTC 50176LL          // B*T
#define TT  3136LL
#define NB  16LL

constexpr long long OFF_H1    = 0;                       // h1 bf16 / kptv partials fp32
constexpr long long OFF_KQV   = OFF_H1    + BTC*512;     // kqv bf16 (half used)
constexpr long long OFF_KP    = OFF_KQV   + BTC*1536;
constexpr long long OFF_QP    = OFF_KP    + BTC*256;
constexpr long long OFF_XDK   = OFF_QP    + BTC*256;
constexpr long long OFF_XDQ   = OFF_XDK   + BTC;
constexpr long long OFF_DV    = OFF_XDQ   + BTC;
constexpr long long OFF_KS    = OFF_DV    + BTC;
constexpr long long OFF_KSP   = OFF_KS    + NB*256;
constexpr long long OFF_VT    = OFF_KSP   + 28LL*NB*256;
constexpr long long OFF_KPT   = OFF_VT    + NB*512*TT;
constexpr long long OFF_KPTV  = OFF_KPT   + NB*256*TT;
constexpr long long OFF_Y     = OFF_KPTV  + NB*512*256;
constexpr long long OFF_XRES  = OFF_Y     + BTC*512;
constexpr long long OFF_H2    = OFF_XRES  + BTC*512;
constexpr long long OFF_HM    = OFF_H2    + BTC*512;
constexpr long long OFF_WKQVT = OFF_HM    + BTC*512;
constexpr long long OFF_WPROJT= OFF_WKQVT + 1536LL*512;
constexpr long long OFF_WM1T  = OFF_WPROJT+ 512LL*512;
constexpr long long OFF_WM2T  = OFF_WM1T  + 512LL*512;
constexpr long long OFF_WRB   = OFF_WM2T  + 512LL*512;   // bf16 w_rand (half used)
constexpr long long SCRATCH_TOTAL = OFF_WRB + 256LL*512;

__device__ __align__(128) float g_scratch[SCRATCH_TOTAL];

// ---------------------------- helpers --------------------------------------
__device__ __forceinline__ void mma_bf16(float c[4], const unsigned a[4], const unsigned b[2]) {
    asm volatile(
        "mma.sync.aligned.m16n8k16.row.col.f32.bf16.bf16.f32 "
        "{%0,%1,%2,%3}, {%4,%5,%6,%7}, {%8,%9}, {%0,%1,%2,%3};\n"
        : "+f"(c[0]), "+f"(c[1]), "+f"(c[2]), "+f"(c[3])
        : "r"(a[0]), "r"(a[1]), "r"(a[2]), "r"(a[3]), "r"(b[0]), "r"(b[1]));
}

__device__ __forceinline__ void cp_async16(uint32_t saddr, const void* gmem, bool pred) {
    int sz = pred ? 16 : 0;   // src-size 0 => zero-fill, no gmem access
    asm volatile("cp.async.cg.shared.global [%0], [%1], 16, %2;\n"
                 :: "r"(saddr), "l"(gmem), "r"(sz));
}
#define CP_COMMIT() asm volatile("cp.async.commit_group;\n" ::: "memory")
#define CP_WAIT0()  asm volatile("cp.async.wait_group 0;\n" ::: "memory")
#define CP_WAIT1()  asm volatile("cp.async.wait_group 1;\n" ::: "memory")

__device__ __forceinline__ float gelu_exact(float x) {
    return 0.5f * x * (1.0f + erff(x * 0.7071067811865476f));
}

// ------------------------------ LayerNorm -----------------------------------
__global__ void ln_kernel(const float* __restrict__ in, const float* __restrict__ g,
                          const float* __restrict__ be, __nv_bfloat16* __restrict__ outv) {
    int r = blockIdx.x;
    int t = threadIdx.x;         // 128 threads, 4 floats each
    const float4* p = (const float4*)(in + (size_t)r * 512);
    float4 v = p[t];
    float s  = v.x + v.y + v.z + v.w;
    float sq = v.x*v.x + v.y*v.y + v.z*v.z + v.w*v.w;
    #pragma unroll
    for (int o = 16; o; o >>= 1) {
        s  += __shfl_xor_sync(0xffffffffu, s,  o);
        sq += __shfl_xor_sync(0xffffffffu, sq, o);
    }
    __shared__ float shs[4], shq[4];
    int wid = t >> 5, lane = t & 31;
    if (!lane) { shs[wid] = s; shq[wid] = sq; }
    __syncthreads();
    s  = shs[0] + shs[1] + shs[2] + shs[3];
    sq = shq[0] + shq[1] + shq[2] + shq[3];
    float mu  = s * (1.0f / 512.0f);
    float var = sq * (1.0f / 512.0f) - mu * mu;
    float inv = rsqrtf(var + 1e-5f);
    float4 gg = ((const float4*)g)[t];
    float4 bb = ((const float4*)be)[t];
    float4 o;
    o.x = (v.x - mu) * inv * gg.x + bb.x;
    o.y = (v.y - mu) * inv * gg.y + bb.y;
    o.z = (v.z - mu) * inv * gg.z + bb.z;
    o.w = (v.w - mu) * inv * gg.w + bb.w;
    __nv_bfloat16* ob = outv + (size_t)r * 512 + t * 4;
    *(__nv_bfloat162*)(ob)     = __floats2bfloat162_rn(o.x, o.y);
    *(__nv_bfloat162*)(ob + 2) = __floats2bfloat162_rn(o.z, o.w);
}

// ks partial sums over t-chunks (bf16 kp in, fp32 partials)
__global__ void kpsum_part(const __nv_bfloat16* __restrict__ kp, float* __restrict__ part) {
    int b = blockIdx.y, c = blockIdx.x, m = threadIdx.x;  // 256 threads
    const __nv_bfloat16* p = kp + ((size_t)b * TT + (size_t)c * 112) * 256 + m;
    float s = 0.f;
    #pragma unroll 4
    for (int t = 0; t < 112; t++) s += __bfloat162float(p[(size_t)t * 256]);
    part[((size_t)c * NB + b) * 256 + m] = s;
}

__global__ void kpsum_reduce(const float* __restrict__ part, float* __restrict__ ks) {
    int b = blockIdx.x, m = threadIdx.x;
    float s = 0.f;
    #pragma unroll
    for (int c = 0; c < 28; c++) s += part[((size_t)c * NB + b) * 256 + m];
    ks[b * 256 + m] = s;
}

// D[r] = qp[r,:] . ks[b,:]   (qp bf16)
__global__ void d_kernel(const __nv_bfloat16* __restrict__ qp, const float* __restrict__ ks,
                         float* __restrict__ D) {
    int r = blockIdx.x * 8 + (threadIdx.x >> 5);
    int lane = threadIdx.x & 31;
    int b = r / (int)TT;
    const __nv_bfloat16* q = qp + (size_t)r * 256;
    const float* s = ks + b * 256;
    float acc = 0.f;
    #pragma unroll
    for (int j = lane; j < 256; j += 32) acc += __bfloat162float(q[j]) * s[j];
    #pragma unroll
    for (int o = 16; o; o >>= 1) acc += __shfl_xor_sync(0xffffffffu, acc, o);
    if (!lane) D[r] = acc;
}

// 32x32 tiled transpose, bf16 in -> bf16 out
__global__ void transpose_b2b(const __nv_bfloat16* __restrict__ in, int ldin, long long strIn,
                              __nv_bfloat16* __restrict__ out, int ldout, long long strOut,
                              int rows, int cols) {
    __shared__ __nv_bfloat16 tile[32][34];
    const __nv_bfloat16* inp = in + (size_t)blockIdx.z * strIn;
    __nv_bfloat16* outp = out + (size_t)blockIdx.z * strOut;
    int bx = blockIdx.x * 32, by = blockIdx.y * 32;
    int x = bx + threadIdx.x;
    #pragma unroll
    for (int j = threadIdx.y; j < 32; j += 8) {
        int y = by + j;
        tile[j][threadIdx.x] = (y < rows && x < cols) ? inp[(size_t)y * ldin + x]
                                                      : __float2bfloat16(0.f);
    }
    __syncthreads();
    int ox = by + threadIdx.x;
    #pragma unroll
    for (int j = threadIdx.y; j < 32; j += 8) {
        int oy = bx + j;
        if (oy < cols && ox < rows) outp[(size_t)oy * ldout + ox] = tile[threadIdx.x][j];
    }
}

// merged weight transpose: wkqv/wproj/wm1/wm2 -> bf16 NT form
__global__ void transpose_weights(const float* __restrict__ wkqv,
                                  const float* __restrict__ wproj,
                                  const float* __restrict__ wm1,
                                  const float* __restrict__ wm2,
                                  __nv_bfloat16* __restrict__ okqv,
                                  __nv_bfloat16* __restrict__ oproj,
                                  __nv_bfloat16* __restrict__ om1,
                                  __nv_bfloat16* __restrict__ om2) {
    __shared__ float tile[32][33];
    int bx = blockIdx.x;
    const float* in; int ldin, ct;
    __nv_bfloat16* outb;
    if (bx < 48)      { in = wkqv;  ldin = 1536; ct = bx;      outb = okqv; }
    else if (bx < 64) { in = wproj; ldin = 512;  ct = bx - 48; outb = oproj; }
    else if (bx < 80) { in = wm1;   ldin = 512;  ct = bx - 64; outb = om1; }
    else              { in = wm2;   ldin = 512;  ct = bx - 80; outb = om2; }
    int c0 = ct * 32, r0 = blockIdx.y * 32;
    int x = c0 + threadIdx.x;
    #pragma unroll
    for (int j = threadIdx.y; j < 32; j += 8)
        tile[j][threadIdx.x] = in[(size_t)(r0 + j) * ldin + x];
    __syncthreads();
    int ox = r0 + threadIdx.x;
    #pragma unroll
    for (int j = threadIdx.y; j < 32; j += 8)
        outb[(size_t)(c0 + j) * 512 + ox] = __float2bfloat16(tile[threadIdx.x][j]);
}

// fp32 -> bf16 copy of w_rand (already NT form: [256, 512])
__global__ void convert_wrand(const float* __restrict__ in, __nv_bfloat16* __restrict__ out) {
    int i = blockIdx.x * 256 + threadIdx.x;   // 131072 elems
    out[i] = __float2bfloat16(in[i]);
}

// reduce split-K kptv partials (7 chunks) -> bf16
__global__ void reduce_kptv(const float* __restrict__ part, __nv_bfloat16* __restrict__ out) {
    int idx = blockIdx.x * 256 + threadIdx.x;   // over 16*131072
    float s = 0.f;
    #pragma unroll
    for (int c = 0; c < 7; c++) s += part[(size_t)c * 2097152 + idx];
    out[idx] = __float2bfloat16(s);
}

// ------------------- bf16 GEMM (NT), 128x256 tile, GBK=64, 3 stages ---------
// EPI: 0 none, 1 +bias (+fused xd row-sumsq), 2 gelu(+bias),
//      3 +bias+resid(fp32), 4 exp(v-rowv)/16, 5 /(rowv+eps).
// zdiv: blockIdx.z = kc*zdiv + bz; bz indexes batch strides, kc*K is k-offset.
// smem row stride 80 halfwords (160B) -> conflict-free k-permuted LDS.64.
#define B16_STAGE 61440          // A 128*160 + B 256*160
#define B16_SMEM  184320         // 3 stages

template <int EPI, int OB>
__global__ __launch_bounds__(256, 1) void bgemm(
    const __nv_bfloat16* __restrict__ A, int lda, long long strA,
    const __nv_bfloat16* __restrict__ B, int ldb, long long strB,
    void* __restrict__ Cv, int ldc, long long strC,
    int Mdim, int K, int zdiv,
    const float* __restrict__ bias,
    const float* __restrict__ rowv, long long strRow,
    const float* __restrict__ resid, long long strRes,
    float* __restrict__ xdk, float* __restrict__ xdq) {
    extern __shared__ __align__(16) char smem[];
    __shared__ float sxd[4][128];
    const uint32_t sbase = (uint32_t)__cvta_generic_to_shared(smem);
    const int tid = threadIdx.x;
    const int wid = tid >> 5, lane = tid & 31;
    const int wm = wid & 1, wn = wid >> 1;
    const int grp = lane >> 2, tig = lane & 3;

    const int bz = blockIdx.z % zdiv;
    const int kc = blockIdx.z / zdiv;
    A += (size_t)bz * strA + (size_t)kc * K;
    B += (size_t)bz * strB + (size_t)kc * K;
    if (rowv)  rowv  += (size_t)bz * strRow;
    if (resid) resid += (size_t)bz * strRes;
    const size_t cOff = (size_t)blockIdx.z * strC;

    const int m0 = blockIdx.y * 128;
    const int n0 = blockIdx.x * 256;

    float* xdp = nullptr;
    if (EPI == 1) {
        int seg = n0 >> 9;
        xdp = (seg == 0) ? xdk : ((seg == 1) ? xdq : nullptr);
    }

    // copy map: 12 x 16B per thread per stage (A 1024 chunks, B 2048 chunks)
    uint32_t soff[12];
    const char* gp[12];
    bool pred[12];
    #pragma unroll
    for (int i = 0; i < 12; i++) {
        if (i < 4) {
            int q = tid + i * 256;                 // 0..1023
            int r = q >> 3, kcq = q & 7;
            soff[i] = (uint32_t)(r * 160 + kcq * 16);
            gp[i] = (const char*)(A + (size_t)(m0 + r) * lda + kcq * 8);
            pred[i] = (m0 + r) < Mdim;
        } else {
            int q = tid + (i - 4) * 256;           // 0..2047
            int r = q >> 3, kcq = q & 7;
            soff[i] = (uint32_t)(20480 + r * 160 + kcq * 16);
            gp[i] = (const char*)(B + (size_t)(n0 + r) * ldb + kcq * 8);
            pred[i] = true;
        }
    }

    float acc[4][8][4];
    #pragma unroll
    for (int mi = 0; mi < 4; mi++)
        #pragma unroll
        for (int ni = 0; ni < 8; ni++)
            #pragma unroll
            for (int j = 0; j < 4; j++) acc[mi][ni][j] = 0.f;

    const int nk = K / 64;

    // prologue: stages 0 and 1
    #pragma unroll
    for (int i = 0; i < 12; i++) cp_async16(sbase + soff[i], gp[i], pred[i]);
    CP_COMMIT();
    if (nk > 1) {
        #pragma unroll
        for (int i = 0; i < 12; i++)
            cp_async16(sbase + B16_STAGE + soff[i], gp[i] + 128, pred[i]);
        CP_COMMIT();
    }

    for (int it = 0; it < nk; it++) {
        // stage `it` must be complete: allowed-incomplete = 1 while another
        // group (stage it+1) is in flight, 0 on the final iteration.
        if (it + 1 < nk) CP_WAIT1(); else CP_WAIT0();
        __syncthreads();
        if (it + 2 < nk) {
            const uint32_t sb1 = sbase + ((it + 2) % 3) * B16_STAGE;
            const int adv = (it + 2) * 128;   // 64 bf16 = 128 bytes
            #pragma unroll
            for (int i = 0; i < 12; i++) cp_async16(sb1 + soff[i], gp[i] + adv, pred[i]);
            CP_COMMIT();
        }
        const char* sb = smem + (it % 3) * B16_STAGE;
        #pragma unroll
        for (int kk = 0; kk < 64; kk += 16) {
            unsigned af[4][4], bf[8][2];
            #pragma unroll
            for (int mi = 0; mi < 4; mi++) {
                int r = wm * 64 + mi * 16 + grp;
                uint2 a0 = *(const uint2*)(sb + r * 160 + (kk + 4 * tig) * 2);
                uint2 a1 = *(const uint2*)(sb + (r + 8) * 160 + (kk + 4 * tig) * 2);
                af[mi][0] = a0.x; af[mi][2] = a0.y;
                af[mi][1] = a1.x; af[mi][3] = a1.y;
            }
            #pragma unroll
            for (int ni = 0; ni < 8; ni++) {
                int c = wn * 64 + ni * 8 + grp;
                uint2 b0 = *(const uint2*)(sb + 20480 + c * 160 + (kk + 4 * tig) * 2);
                bf[ni][0] = b0.x; bf[ni][1] = b0.y;
            }
            #pragma unroll
            for (int mi = 0; mi < 4; mi++)
                #pragma unroll
                for (int ni = 0; ni < 8; ni++)
                    mma_bf16(acc[mi][ni], af[mi], bf[ni]);
        }
    }

    // epilogue (+ optional fused row sum-of-squares for xd)
    #pragma unroll
    for (int mi = 0; mi < 4; mi++) {
        #pragma unroll
        for (int half = 0; half < 2; half++) {
            int r = m0 + wm * 64 + mi * 16 + grp + half * 8;
            float ss = 0.f;
            if (r < Mdim) {
                float invd = 0.f, rv = 0.f;
                if (EPI == 5) invd = 1.0f / (rowv[r] + 1e-8f);
                if (EPI == 4) rv = rowv[r];
                #pragma unroll
                for (int ni = 0; ni < 8; ni++) {
                    int c = n0 + wn * 64 + ni * 8 + tig * 2;
                    float v0 = acc[mi][ni][half * 2 + 0];
                    float v1 = acc[mi][ni][half * 2 + 1];
                    if (EPI == 1 || EPI == 2 || EPI == 3) { v0 += bias[c]; v1 += bias[c + 1]; }
                    if (EPI == 2) { v0 = gelu_exact(v0); v1 = gelu_exact(v1); }
                    if (EPI == 3) {
                        float2 rr = *(const float2*)(resid + (size_t)r * ldc + c);
                        v0 += rr.x; v1 += rr.y;
                    }
                    if (EPI == 4) {
                        v0 = expf(v0 - rv) * 0.0625f;
                        v1 = expf(v1 - rv) * 0.0625f;
                    }
                    if (EPI == 5) { v0 *= invd; v1 *= invd; }
                    if (EPI == 1) ss += v0 * v0 + v1 * v1;
                    if (OB) {
                        __nv_bfloat16* cp = (__nv_bfloat16*)Cv + cOff + (size_t)r * ldc + c;
                        *(__nv_bfloat162*)cp = __floats2bfloat162_rn(v0, v1);
                    } else {
                        float* cp = (float*)Cv + cOff + (size_t)r * ldc + c;
                        *(float2*)cp = make_float2(v0, v1);
                    }
                }
            }
            if (EPI == 1) {
                ss += __shfl_xor_sync(0xffffffffu, ss, 1);
                ss += __shfl_xor_sync(0xffffffffu, ss, 2);
                if (tig == 0) sxd[wn][wm * 64 + mi * 16 + grp + half * 8] = ss;
            }
        }
    }
    if (EPI == 1) {
        __syncthreads();
        if (xdp && tid < 128 && (m0 + tid) < Mdim) {
            float s = sxd[0][tid] + sxd[1][tid] + sxd[2][tid] + sxd[3][tid];
            atomicAdd(&xdp[m0 + tid], 0.5f * s);   // exactly 2 contributions/row
        }
    }
}

// ------------------------------- driver -------------------------------------
extern "C" void kernel_launch(void* const* d_in, const int* in_sizes, int n_in,
                              void* d_out, int out_size) {
    const float* x      = (const float*)d_in[0];
    const float* w_kqv  = (const float*)d_in[1];
    const float* b_kqv  = (const float*)d_in[2];
    const float* w_proj = (const float*)d_in[3];
    const float* b_proj = (const float*)d_in[4];
    const float* g1     = (const float*)d_in[5];
    const float* be1    = (const float*)d_in[6];
    const float* g2     = (const float*)d_in[7];
    const float* be2    = (const float*)d_in[8];
    const float* w_mlp1 = (const float*)d_in[9];
    const float* b_mlp1 = (const float*)d_in[10];
    const float* w_mlp2 = (const float*)d_in[11];
    const float* b_mlp2 = (const float*)d_in[12];
    const float* w_rand = (const float*)d_in[13];
    float* out = (float*)d_out;

    float* S = nullptr;
    cudaGetSymbolAddress((void**)&S, g_scratch);

    __nv_bfloat16* h1b   = (__nv_bfloat16*)(S + OFF_H1);
    float* kpart  = S + OFF_H1;               // reused after kqv consumes h1
    __nv_bfloat16* kqvb  = (__nv_bfloat16*)(S + OFF_KQV);
    __nv_bfloat16* kpb   = (__nv_bfloat16*)(S + OFF_KP);
    float* xdk    = S + OFF_XDK;
    float* xdq    = S + OFF_XDQ;
    float* Dv     = S + OFF_DV;
    float* ks     = S + OFF_KS;
    float* ksp    = S + OFF_KSP;
    __nv_bfloat16* vTb   = (__nv_bfloat16*)(S + OFF_VT);
    __nv_bfloat16* kpTb  = (__nv_bfloat16*)(S + OFF_KPT);
    __nv_bfloat16* kptvb = (__nv_bfloat16*)(S + OFF_KPTV);
    __nv_bfloat16* yb    = (__nv_bfloat16*)(S + OFF_Y);
    float* xres   = S + OFF_XRES;
    __nv_bfloat16* h2b   = (__nv_bfloat16*)(S + OFF_H2);
    __nv_bfloat16* hmb   = (__nv_bfloat16*)(S + OFF_HM);
    __nv_bfloat16* wkqvTb  = (__nv_bfloat16*)(S + OFF_WKQVT);
    __nv_bfloat16* wprojTb = (__nv_bfloat16*)(S + OFF_WPROJT);
    __nv_bfloat16* wm1Tb   = (__nv_bfloat16*)(S + OFF_WM1T);
    __nv_bfloat16* wm2Tb   = (__nv_bfloat16*)(S + OFF_WM2T);
    __nv_bfloat16* wrandb  = (__nv_bfloat16*)(S + OFF_WRB);

    // qp lives right after kp: stride BTC*512 bf16 elems (merged z launch)
    __nv_bfloat16* qpb = kpb + (size_t)BTC * 512;

    cudaFuncSetAttribute(bgemm<1,1>, cudaFuncAttributeMaxDynamicSharedMemorySize, B16_SMEM);
    cudaFuncSetAttribute(bgemm<4,1>, cudaFuncAttributeMaxDynamicSharedMemorySize, B16_SMEM);
    cudaFuncSetAttribute(bgemm<0,0>, cudaFuncAttributeMaxDynamicSharedMemorySize, B16_SMEM);
    cudaFuncSetAttribute(bgemm<5,1>, cudaFuncAttributeMaxDynamicSharedMemorySize, B16_SMEM);
    cudaFuncSetAttribute(bgemm<3,0>, cudaFuncAttributeMaxDynamicSharedMemorySize, B16_SMEM);
    cudaFuncSetAttribute(bgemm<2,1>, cudaFuncAttributeMaxDynamicSharedMemorySize, B16_SMEM);

    const int BT = (int)BTC;
    const float* nullf = nullptr;
    float* nullx = nullptr;
    dim3 tb(32, 8);

    // 1. h1 = LN(x)  (bf16)
    ln_kernel<<<BT, 128>>>(x, g1, be1, h1b);

    // 2. weight transposes (bf16) + w_rand bf16 copy
    transpose_weights<<<dim3(96, 16), tb>>>(w_kqv, w_proj, w_mlp1, w_mlp2,
                                            wkqvTb, wprojTb, wm1Tb, wm2Tb);
    convert_wrand<<<512, 256>>>(w_rand, wrandb);

    // 3. zero xd accumulators (xdk,xdq adjacent)
    cudaMemsetAsync(xdk, 0, 2 * BTC * sizeof(float));

    // 4. kqv = h1 @ w_kqv + b_kqv  (bf16 out) + fused xd row-sumsq
    bgemm<1,1><<<dim3(6, 392, 1), 256, B16_SMEM>>>(h1b, 512, 0, wkqvTb, 512, 0,
                                                   kqvb, 1536, 0, BT, 512, 1,
                                                   b_kqv, nullf, 0, nullf, 0,
                                                   xdk, xdq);

    // 5. kp/qp = exp((k|q) @ w_rand^T - xd)/16  (merged, z=0 -> k, z=1 -> q)
    bgemm<4,1><<<dim3(1, 392, 2), 256, B16_SMEM>>>(kqvb, 1536, 512, wrandb, 512, 0,
                                                   kpb, 256, (long long)BTC * 512,
                                                   BT, 512, 2,
                                                   nullf, xdk, BTC, nullf, 0,
                                                   nullx, nullx);

    // 6. ks = sum_t kp
    kpsum_part<<<dim3(28, 16), 256>>>(kpb, ksp);
    kpsum_reduce<<<16, 256>>>(ksp, ks);

    // 7. D = qp . ks
    d_kernel<<<BT / 8, 256>>>(qpb, ks, Dv);

    // 8. transposes into K-major bf16
    transpose_b2b<<<dim3(16, 98, 16), tb>>>(kqvb + 1024, 1536, TT * 1536,
                                            vTb, (int)TT, 512 * TT, (int)TT, 512);
    transpose_b2b<<<dim3(8, 98, 16), tb>>>(kpb, 256, TT * 256,
                                           kpTb, (int)TT, 256 * TT, (int)TT, 256);

    // 9. kptv split-K x7: partials (fp32) then reduce -> bf16
    bgemm<0,0><<<dim3(1, 4, 112), 256, B16_SMEM>>>(vTb, (int)TT, 512 * TT,
                                                   kpTb, (int)TT, 256 * TT,
                                                   kpart, 256, 131072, 512, 448, 16,
                                                   nullf, nullf, 0, nullf, 0,
                                                   nullx, nullx);
    reduce_kptv<<<8192, 256>>>(kpart, kptvb);

    // 10. y[b] = (qp @ kptv^T) / (D + eps)  (bf16)
    bgemm<5,1><<<dim3(2, 25, 16), 256, B16_SMEM>>>(qpb, 256, TT * 256,
                                                   kptvb, 256, 512 * 256,
                                                   yb, 512, TT * 512, (int)TT, 256, 16,
                                                   nullf, Dv, TT, nullf, 0,
                                                   nullx, nullx);

    // 11. xres = x + y @ w_proj + b_proj  (fp32 out)
    bgemm<3,0><<<dim3(2, 392, 1), 256, B16_SMEM>>>(yb, 512, 0, wprojTb, 512, 0,
                                                   xres, 512, 0, BT, 512, 1,
                                                   b_proj, nullf, 0, x, 0,
                                                   nullx, nullx);

    // 12. h2 = LN(xres)  (bf16)
    ln_kernel<<<BT, 128>>>(xres, g2, be2, h2b);

    // 13. hm = gelu(h2 @ w_mlp1 + b_mlp1)  (bf16)
    bgemm<2,1><<<dim3(2, 392, 1), 256, B16_SMEM>>>(h2b, 512, 0, wm1Tb, 512, 0,
                                                   hmb, 512, 0, BT, 512, 1,
                                                   b_mlp1, nullf, 0, nullf, 0,
                                                   nullx, nullx);

    // 14. out = xres + hm @ w_mlp2 + b_mlp2  (fp32 out)
    bgemm<3,0><<<dim3(2, 392, 1), 256, B16_SMEM>>>(hmb, 512, 0, wm2Tb, 512, 0,
                                                   out, 512, 0, BT, 512, 1,
                                                   b_mlp2, nullf, 0, xres, 0,
                                                   nullx, nullx);
}

// round 12
// speedup vs baseline: 2.5142x; 1.1442x over previous
#include <cuda_runtime.h>
#include <cuda_bf16.h>
#include <math.h>
#include <stdint.h>

// ---------------------------------------------------------------------------
// Token performer block. mma.sync bf16 m16n8k16 everywhere (fp32 accumulate).
// R11: 128x128 CTA tiles @ 2 CTAs/SM (occupancy 2x to hide LDS->MMA latency),
// GBK=64, 2-stage cp.async, k-permuted LDS.64 fragments, fused epilogues.
// xd via deterministic per-tile partials + reduce (no atomics).
// ---------------------------------------------------------------------------

#define BTC 50176LL          // B*T
#define TT  3136LL
#define NB  16LL

constexpr long long OFF_H1    = 0;                       // h1 bf16 / kptv partials fp32
constexpr long long OFF_KQV   = OFF_H1    + BTC*512;     // kqv bf16 (half used)
constexpr long long OFF_KP    = OFF_KQV   + BTC*1536;
constexpr long long OFF_QP    = OFF_KP    + BTC*256;
constexpr long long OFF_XDK   = OFF_QP    + BTC*256;
constexpr long long OFF_XDQ   = OFF_XDK   + BTC;
constexpr long long OFF_DV    = OFF_XDQ   + BTC;
constexpr long long OFF_KS    = OFF_DV    + BTC;
constexpr long long OFF_KSP   = OFF_KS    + NB*256;
constexpr long long OFF_VT    = OFF_KSP   + 28LL*NB*256;
constexpr long long OFF_KPT   = OFF_VT    + NB*512*TT;
constexpr long long OFF_KPTV  = OFF_KPT   + NB*256*TT;
constexpr long long OFF_Y     = OFF_KPTV  + NB*512*256;
constexpr long long OFF_XRES  = OFF_Y     + BTC*512;
constexpr long long OFF_H2    = OFF_XRES  + BTC*512;
constexpr long long OFF_HM    = OFF_H2    + BTC*512;
constexpr long long OFF_WKQVT = OFF_HM    + BTC*512;
constexpr long long OFF_WPROJT= OFF_WKQVT + 1536LL*512;
constexpr long long OFF_WM1T  = OFF_WPROJT+ 512LL*512;
constexpr long long OFF_WM2T  = OFF_WM1T  + 512LL*512;
constexpr long long OFF_WRB   = OFF_WM2T  + 512LL*512;   // bf16 w_rand (half used)
constexpr long long OFF_XDP   = OFF_WRB   + 256LL*512;   // xd partials: 8 tiles x BTC
constexpr long long SCRATCH_TOTAL = OFF_XDP + 8LL*BTC;

__device__ __align__(128) float g_scratch[SCRATCH_TOTAL];

// ---------------------------- helpers --------------------------------------
__device__ __forceinline__ void mma_bf16(float c[4], const unsigned a[4], const unsigned b[2]) {
    asm volatile(
        "mma.sync.aligned.m16n8k16.row.col.f32.bf16.bf16.f32 "
        "{%0,%1,%2,%3}, {%4,%5,%6,%7}, {%8,%9}, {%0,%1,%2,%3};\n"
        : "+f"(c[0]), "+f"(c[1]), "+f"(c[2]), "+f"(c[3])
        : "r"(a[0]), "r"(a[1]), "r"(a[2]), "r"(a[3]), "r"(b[0]), "r"(b[1]));
}

__device__ __forceinline__ void cp_async16(uint32_t saddr, const void* gmem, bool pred) {
    int sz = pred ? 16 : 0;   // src-size 0 => zero-fill, no gmem access
    asm volatile("cp.async.cg.shared.global [%0], [%1], 16, %2;\n"
                 :: "r"(saddr), "l"(gmem), "r"(sz));
}
#define CP_COMMIT() asm volatile("cp.async.commit_group;\n" ::: "memory")
#define CP_WAIT0()  asm volatile("cp.async.wait_group 0;\n" ::: "memory")

__device__ __forceinline__ float gelu_exact(float x) {
    return 0.5f * x * (1.0f + erff(x * 0.7071067811865476f));
}

// ------------------------------ LayerNorm -----------------------------------
__global__ void ln_kernel(const float* __restrict__ in, const float* __restrict__ g,
                          const float* __restrict__ be, __nv_bfloat16* __restrict__ outv) {
    int r = blockIdx.x;
    int t = threadIdx.x;         // 128 threads, 4 floats each
    const float4* p = (const float4*)(in + (size_t)r * 512);
    float4 v = p[t];
    float s  = v.x + v.y + v.z + v.w;
    float sq = v.x*v.x + v.y*v.y + v.z*v.z + v.w*v.w;
    #pragma unroll
    for (int o = 16; o; o >>= 1) {
        s  += __shfl_xor_sync(0xffffffffu, s,  o);
        sq += __shfl_xor_sync(0xffffffffu, sq, o);
    }
    __shared__ float shs[4], shq[4];
    int wid = t >> 5, lane = t & 31;
    if (!lane) { shs[wid] = s; shq[wid] = sq; }
    __syncthreads();
    s  = shs[0] + shs[1] + shs[2] + shs[3];
    sq = shq[0] + shq[1] + shq[2] + shq[3];
    float mu  = s * (1.0f / 512.0f);
    float var = sq * (1.0f / 512.0f) - mu * mu;
    float inv = rsqrtf(var + 1e-5f);
    float4 gg = ((const float4*)g)[t];
    float4 bb = ((const float4*)be)[t];
    float4 o;
    o.x = (v.x - mu) * inv * gg.x + bb.x;
    o.y = (v.y - mu) * inv * gg.y + bb.y;
    o.z = (v.z - mu) * inv * gg.z + bb.z;
    o.w = (v.w - mu) * inv * gg.w + bb.w;
    __nv_bfloat16* ob = outv + (size_t)r * 512 + t * 4;
    *(__nv_bfloat162*)(ob)     = __floats2bfloat162_rn(o.x, o.y);
    *(__nv_bfloat162*)(ob + 2) = __floats2bfloat162_rn(o.z, o.w);
}

// ks partial sums over t-chunks (bf16 kp in, fp32 partials)
__global__ void kpsum_part(const __nv_bfloat16* __restrict__ kp, float* __restrict__ part) {
    int b = blockIdx.y, c = blockIdx.x, m = threadIdx.x;  // 256 threads
    const __nv_bfloat16* p = kp + ((size_t)b * TT + (size_t)c * 112) * 256 + m;
    float s = 0.f;
    #pragma unroll 4
    for (int t = 0; t < 112; t++) s += __bfloat162float(p[(size_t)t * 256]);
    part[((size_t)c * NB + b) * 256 + m] = s;
}

__global__ void kpsum_reduce(const float* __restrict__ part, float* __restrict__ ks) {
    int b = blockIdx.x, m = threadIdx.x;
    float s = 0.f;
    #pragma unroll
    for (int c = 0; c < 28; c++) s += part[((size_t)c * NB + b) * 256 + m];
    ks[b * 256 + m] = s;
}

// D[r] = qp[r,:] . ks[b,:]   (qp bf16)
__global__ void d_kernel(const __nv_bfloat16* __restrict__ qp, const float* __restrict__ ks,
                         float* __restrict__ D) {
    int r = blockIdx.x * 8 + (threadIdx.x >> 5);
    int lane = threadIdx.x & 31;
    int b = r / (int)TT;
    const __nv_bfloat16* q = qp + (size_t)r * 256;
    const float* s = ks + b * 256;
    float acc = 0.f;
    #pragma unroll
    for (int j = lane; j < 256; j += 32) acc += __bfloat162float(q[j]) * s[j];
    #pragma unroll
    for (int o = 16; o; o >>= 1) acc += __shfl_xor_sync(0xffffffffu, acc, o);
    if (!lane) D[r] = acc;
}

// reduce per-tile xd partials: xd = 0.5 * sum of 4 tile partials (fixed order)
__global__ void reduce_xd(const float* __restrict__ part,
                          float* __restrict__ xdk, float* __restrict__ xdq) {
    long long r = (long long)blockIdx.x * 256 + threadIdx.x;
    float sk = part[r] + part[BTC + r] + part[2*BTC + r] + part[3*BTC + r];
    float sq = part[4*BTC + r] + part[5*BTC + r] + part[6*BTC + r] + part[7*BTC + r];
    xdk[r] = 0.5f * sk;
    xdq[r] = 0.5f * sq;
}

// 32x32 tiled transpose, bf16 in -> bf16 out
__global__ void transpose_b2b(const __nv_bfloat16* __restrict__ in, int ldin, long long strIn,
                              __nv_bfloat16* __restrict__ out, int ldout, long long strOut,
                              int rows, int cols) {
    __shared__ __nv_bfloat16 tile[32][34];
    const __nv_bfloat16* inp = in + (size_t)blockIdx.z * strIn;
    __nv_bfloat16* outp = out + (size_t)blockIdx.z * strOut;
    int bx = blockIdx.x * 32, by = blockIdx.y * 32;
    int x = bx + threadIdx.x;
    #pragma unroll
    for (int j = threadIdx.y; j < 32; j += 8) {
        int y = by + j;
        tile[j][threadIdx.x] = (y < rows && x < cols) ? inp[(size_t)y * ldin + x]
                                                      : __float2bfloat16(0.f);
    }
    __syncthreads();
    int ox = by + threadIdx.x;
    #pragma unroll
    for (int j = threadIdx.y; j < 32; j += 8) {
        int oy = bx + j;
        if (oy < cols && ox < rows) outp[(size_t)oy * ldout + ox] = tile[threadIdx.x][j];
    }
}

// merged weight transpose: wkqv/wproj/wm1/wm2 -> bf16 NT form
__global__ void transpose_weights(const float* __restrict__ wkqv,
                                  const float* __restrict__ wproj,
                                  const float* __restrict__ wm1,
                                  const float* __restrict__ wm2,
                                  __nv_bfloat16* __restrict__ okqv,
                                  __nv_bfloat16* __restrict__ oproj,
                                  __nv_bfloat16* __restrict__ om1,
                                  __nv_bfloat16* __restrict__ om2) {
    __shared__ float tile[32][33];
    int bx = blockIdx.x;
    const float* in; int ldin, ct;
    __nv_bfloat16* outb;
    if (bx < 48)      { in = wkqv;  ldin = 1536; ct = bx;      outb = okqv; }
    else if (bx < 64) { in = wproj; ldin = 512;  ct = bx - 48; outb = oproj; }
    else if (bx < 80) { in = wm1;   ldin = 512;  ct = bx - 64; outb = om1; }
    else              { in = wm2;   ldin = 512;  ct = bx - 80; outb = om2; }
    int c0 = ct * 32, r0 = blockIdx.y * 32;
    int x = c0 + threadIdx.x;
    #pragma unroll
    for (int j = threadIdx.y; j < 32; j += 8)
        tile[j][threadIdx.x] = in[(size_t)(r0 + j) * ldin + x];
    __syncthreads();
    int ox = r0 + threadIdx.x;
    #pragma unroll
    for (int j = threadIdx.y; j < 32; j += 8)
        outb[(size_t)(c0 + j) * 512 + ox] = __float2bfloat16(tile[threadIdx.x][j]);
}

// fp32 -> bf16 copy of w_rand (already NT form: [256, 512])
__global__ void convert_wrand(const float* __restrict__ in, __nv_bfloat16* __restrict__ out) {
    int i = blockIdx.x * 256 + threadIdx.x;   // 131072 elems
    out[i] = __float2bfloat16(in[i]);
}

// reduce split-K kptv partials (7 chunks) -> bf16
__global__ void reduce_kptv(const float* __restrict__ part, __nv_bfloat16* __restrict__ out) {
    int idx = blockIdx.x * 256 + threadIdx.x;   // over 16*131072
    float s = 0.f;
    #pragma unroll
    for (int c = 0; c < 7; c++) s += part[(size_t)c * 2097152 + idx];
    out[idx] = __float2bfloat16(s);
}

// ------------- bf16 GEMM (NT), 128x128 tile, 2 CTAs/SM, GBK=64 --------------
// EPI: 0 none, 1 +bias (+xd per-tile partial sumsq), 2 gelu(+bias),
//      3 +bias+resid(fp32), 4 exp(v-rowv)/16, 5 /(rowv+eps).
// zdiv: blockIdx.z = kc*zdiv + bz; bz indexes batch strides, kc*K is k-offset.
// smem row stride 160B -> conflict-free k-permuted LDS.64 fragment loads.
// 8 warps: wm = wid&1 (2 x 64 rows), wn = wid>>1 (4 x 32 cols).
#define B16_STAGE 40960          // A 128*160 + B 128*160
#define B16_SMEM  81920          // 2 stages

template <int EPI, int OB>
__global__ __launch_bounds__(256, 2) void bgemm(
    const __nv_bfloat16* __restrict__ A, int lda, long long strA,
    const __nv_bfloat16* __restrict__ B, int ldb, long long strB,
    void* __restrict__ Cv, int ldc, long long strC,
    int Mdim, int K, int zdiv,
    const float* __restrict__ bias,
    const float* __restrict__ rowv, long long strRow,
    const float* __restrict__ resid, long long strRes,
    float* __restrict__ xdpart) {
    extern __shared__ __align__(16) char smem[];
    __shared__ float sxd[4][128];
    const uint32_t sbase = (uint32_t)__cvta_generic_to_shared(smem);
    const int tid = threadIdx.x;
    const int wid = tid >> 5, lane = tid & 31;
    const int wm = wid & 1, wn = wid >> 1;
    const int grp = lane >> 2, tig = lane & 3;

    const int bz = blockIdx.z % zdiv;
    const int kc = blockIdx.z / zdiv;
    A += (size_t)bz * strA + (size_t)kc * K;
    B += (size_t)bz * strB + (size_t)kc * K;
    if (rowv)  rowv  += (size_t)bz * strRow;
    if (resid) resid += (size_t)bz * strRes;
    const size_t cOff = (size_t)blockIdx.z * strC;

    const int m0 = blockIdx.y * 128;
    const int n0 = blockIdx.x * 128;

    // copy map: 8 x 16B per thread per stage (A 1024 chunks, B 1024 chunks)
    uint32_t soff[8];
    const char* gp[8];
    bool pred[8];
    #pragma unroll
    for (int i = 0; i < 8; i++) {
        int q = tid + (i & 3) * 256;               // 0..1023
        int r = q >> 3, kcq = q & 7;
        if (i < 4) {
            soff[i] = (uint32_t)(r * 160 + kcq * 16);
            gp[i] = (const char*)(A + (size_t)(m0 + r) * lda + kcq * 8);
            pred[i] = (m0 + r) < Mdim;
        } else {
            soff[i] = (uint32_t)(20480 + r * 160 + kcq * 16);
            gp[i] = (const char*)(B + (size_t)(n0 + r) * ldb + kcq * 8);
            pred[i] = true;
        }
    }

    float acc[4][4][4];
    #pragma unroll
    for (int mi = 0; mi < 4; mi++)
        #pragma unroll
        for (int ni = 0; ni < 4; ni++)
            #pragma unroll
            for (int j = 0; j < 4; j++) acc[mi][ni][j] = 0.f;

    const int nk = K / 64;
    #pragma unroll
    for (int i = 0; i < 8; i++) cp_async16(sbase + soff[i], gp[i], pred[i]);
    CP_COMMIT();

    for (int it = 0; it < nk; it++) {
        CP_WAIT0();
        __syncthreads();
        if (it + 1 < nk) {
            const uint32_t sb1 = sbase + ((it + 1) & 1) * B16_STAGE;
            const int adv = (it + 1) * 128;   // 64 bf16 = 128 bytes
            #pragma unroll
            for (int i = 0; i < 8; i++) cp_async16(sb1 + soff[i], gp[i] + adv, pred[i]);
            CP_COMMIT();
        }
        const char* sb = smem + (it & 1) * B16_STAGE;
        #pragma unroll
        for (int kk = 0; kk < 64; kk += 16) {
            unsigned af[4][4], bf[4][2];
            #pragma unroll
            for (int mi = 0; mi < 4; mi++) {
                int r = wm * 64 + mi * 16 + grp;
                uint2 a0 = *(const uint2*)(sb + r * 160 + (kk + 4 * tig) * 2);
                uint2 a1 = *(const uint2*)(sb + (r + 8) * 160 + (kk + 4 * tig) * 2);
                af[mi][0] = a0.x; af[mi][2] = a0.y;
                af[mi][1] = a1.x; af[mi][3] = a1.y;
            }
            #pragma unroll
            for (int ni = 0; ni < 4; ni++) {
                int c = wn * 32 + ni * 8 + grp;
                uint2 b0 = *(const uint2*)(sb + 20480 + c * 160 + (kk + 4 * tig) * 2);
                bf[ni][0] = b0.x; bf[ni][1] = b0.y;
            }
            #pragma unroll
            for (int mi = 0; mi < 4; mi++)
                #pragma unroll
                for (int ni = 0; ni < 4; ni++)
                    mma_bf16(acc[mi][ni], af[mi], bf[ni]);
        }
    }

    // epilogue (+ optional per-tile xd partial sumsq)
    #pragma unroll
    for (int mi = 0; mi < 4; mi++) {
        #pragma unroll
        for (int half = 0; half < 2; half++) {
            int r = m0 + wm * 64 + mi * 16 + grp + half * 8;
            float ss = 0.f;
            if (r < Mdim) {
                float invd = 0.f, rv = 0.f;
                if (EPI == 5) invd = 1.0f / (rowv[r] + 1e-8f);
                if (EPI == 4) rv = rowv[r];
                #pragma unroll
                for (int ni = 0; ni < 4; ni++) {
                    int c = n0 + wn * 32 + ni * 8 + tig * 2;
                    float v0 = acc[mi][ni][half * 2 + 0];
                    float v1 = acc[mi][ni][half * 2 + 1];
                    if (EPI == 1 || EPI == 2 || EPI == 3) { v0 += bias[c]; v1 += bias[c + 1]; }
                    if (EPI == 2) { v0 = gelu_exact(v0); v1 = gelu_exact(v1); }
                    if (EPI == 3) {
                        float2 rr = *(const float2*)(resid + (size_t)r * ldc + c);
                        v0 += rr.x; v1 += rr.y;
                    }
                    if (EPI == 4) {
                        v0 = expf(v0 - rv) * 0.0625f;
                        v1 = expf(v1 - rv) * 0.0625f;
                    }
                    if (EPI == 5) { v0 *= invd; v1 *= invd; }
                    if (EPI == 1) ss += v0 * v0 + v1 * v1;
                    if (OB) {
                        __nv_bfloat16* cp = (__nv_bfloat16*)Cv + cOff + (size_t)r * ldc + c;
                        *(__nv_bfloat162*)cp = __floats2bfloat162_rn(v0, v1);
                    } else {
                        float* cp = (float*)Cv + cOff + (size_t)r * ldc + c;
                        *(float2*)cp = make_float2(v0, v1);
                    }
                }
            }
            if (EPI == 1) {
                ss += __shfl_xor_sync(0xffffffffu, ss, 1);
                ss += __shfl_xor_sync(0xffffffffu, ss, 2);
                if (tig == 0) sxd[wn][wm * 64 + mi * 16 + grp + half * 8] = ss;
            }
        }
    }
    if (EPI == 1) {
        __syncthreads();
        int tile = n0 >> 7;              // 0..3 k, 4..7 q, 8..11 v
        if (tile < 8 && tid < 128 && (m0 + tid) < Mdim) {
            float s = sxd[0][tid] + sxd[1][tid] + sxd[2][tid] + sxd[3][tid];
            xdpart[(size_t)tile * BTC + m0 + tid] = s;   // written exactly once
        }
    }
}

// ------------------------------- driver -------------------------------------
extern "C" void kernel_launch(void* const* d_in, const int* in_sizes, int n_in,
                              void* d_out, int out_size) {
    const float* x      = (const float*)d_in[0];
    const float* w_kqv  = (const float*)d_in[1];
    const float* b_kqv  = (const float*)d_in[2];
    const float* w_proj = (const float*)d_in[3];
    const float* b_proj = (const float*)d_in[4];
    const float* g1     = (const float*)d_in[5];
    const float* be1    = (const float*)d_in[6];
    const float* g2     = (const float*)d_in[7];
    const float* be2    = (const float*)d_in[8];
    const float* w_mlp1 = (const float*)d_in[9];
    const float* b_mlp1 = (const float*)d_in[10];
    const float* w_mlp2 = (const float*)d_in[11];
    const float* b_mlp2 = (const float*)d_in[12];
    const float* w_rand = (const float*)d_in[13];
    float* out = (float*)d_out;

    float* S = nullptr;
    cudaGetSymbolAddress((void**)&S, g_scratch);

    __nv_bfloat16* h1b   = (__nv_bfloat16*)(S + OFF_H1);
    float* kpart  = S + OFF_H1;               // reused after kqv consumes h1
    __nv_bfloat16* kqvb  = (__nv_bfloat16*)(S + OFF_KQV);
    __nv_bfloat16* kpb   = (__nv_bfloat16*)(S + OFF_KP);
    float* xdk    = S + OFF_XDK;
    float* xdq    = S + OFF_XDQ;
    float* Dv     = S + OFF_DV;
    float* ks     = S + OFF_KS;
    float* ksp    = S + OFF_KSP;
    __nv_bfloat16* vTb   = (__nv_bfloat16*)(S + OFF_VT);
    __nv_bfloat16* kpTb  = (__nv_bfloat16*)(S + OFF_KPT);
    __nv_bfloat16* kptvb = (__nv_bfloat16*)(S + OFF_KPTV);
    __nv_bfloat16* yb    = (__nv_bfloat16*)(S + OFF_Y);
    float* xres   = S + OFF_XRES;
    __nv_bfloat16* h2b   = (__nv_bfloat16*)(S + OFF_H2);
    __nv_bfloat16* hmb   = (__nv_bfloat16*)(S + OFF_HM);
    __nv_bfloat16* wkqvTb  = (__nv_bfloat16*)(S + OFF_WKQVT);
    __nv_bfloat16* wprojTb = (__nv_bfloat16*)(S + OFF_WPROJT);
    __nv_bfloat16* wm1Tb   = (__nv_bfloat16*)(S + OFF_WM1T);
    __nv_bfloat16* wm2Tb   = (__nv_bfloat16*)(S + OFF_WM2T);
    __nv_bfloat16* wrandb  = (__nv_bfloat16*)(S + OFF_WRB);
    float* xdpart = S + OFF_XDP;

    // qp lives right after kp: stride BTC*512 bf16 elems (merged z launch)
    __nv_bfloat16* qpb = kpb + (size_t)BTC * 512;

    cudaFuncSetAttribute(bgemm<1,1>, cudaFuncAttributeMaxDynamicSharedMemorySize, B16_SMEM);
    cudaFuncSetAttribute(bgemm<4,1>, cudaFuncAttributeMaxDynamicSharedMemorySize, B16_SMEM);
    cudaFuncSetAttribute(bgemm<0,0>, cudaFuncAttributeMaxDynamicSharedMemorySize, B16_SMEM);
    cudaFuncSetAttribute(bgemm<5,1>, cudaFuncAttributeMaxDynamicSharedMemorySize, B16_SMEM);
    cudaFuncSetAttribute(bgemm<3,0>, cudaFuncAttributeMaxDynamicSharedMemorySize, B16_SMEM);
    cudaFuncSetAttribute(bgemm<2,1>, cudaFuncAttributeMaxDynamicSharedMemorySize, B16_SMEM);

    const int BT = (int)BTC;
    const float* nullf = nullptr;
    float* nullx = nullptr;
    dim3 tb(32, 8);

    // 1. h1 = LN(x)  (bf16)
    ln_kernel<<<BT, 128>>>(x, g1, be1, h1b);

    // 2. weight transposes (bf16) + w_rand bf16 copy
    transpose_weights<<<dim3(96, 16), tb>>>(w_kqv, w_proj, w_mlp1, w_mlp2,
                                            wkqvTb, wprojTb, wm1Tb, wm2Tb);
    convert_wrand<<<512, 256>>>(w_rand, wrandb);

    // 3. kqv = h1 @ w_kqv + b_kqv  (bf16 out) + per-tile xd partials
    bgemm<1,1><<<dim3(12, 392, 1), 256, B16_SMEM>>>(h1b, 512, 0, wkqvTb, 512, 0,
                                                    kqvb, 1536, 0, BT, 512, 1,
                                                    b_kqv, nullf, 0, nullf, 0,
                                                    xdpart);

    // 4. xd = 0.5 * sum of 4 tile partials each (deterministic fixed order)
    reduce_xd<<<196, 256>>>(xdpart, xdk, xdq);

    // 5. kp/qp = exp((k|q) @ w_rand^T - xd)/16  (merged; z%2: 0->k, 1->q)
    bgemm<4,1><<<dim3(2, 392, 2), 256, B16_SMEM>>>(kqvb, 1536, 512, wrandb, 512, 0,
                                                   kpb, 256, (long long)BTC * 512,
                                                   BT, 512, 2,
                                                   nullf, xdk, BTC, nullf, 0,
                                                   nullx);

    // 6. ks = sum_t kp
    kpsum_part<<<dim3(28, 16), 256>>>(kpb, ksp);
    kpsum_reduce<<<16, 256>>>(ksp, ks);

    // 7. D = qp . ks
    d_kernel<<<BT / 8, 256>>>(qpb, ks, Dv);

    // 8. transposes into K-major bf16
    transpose_b2b<<<dim3(16, 98, 16), tb>>>(kqvb + 1024, 1536, TT * 1536,
                                            vTb, (int)TT, 512 * TT, (int)TT, 512);
    transpose_b2b<<<dim3(8, 98, 16), tb>>>(kpb, 256, TT * 256,
                                           kpTb, (int)TT, 256 * TT, (int)TT, 256);

    // 9. kptv split-K x7: partials (fp32) then reduce -> bf16
    bgemm<0,0><<<dim3(2, 4, 112), 256, B16_SMEM>>>(vTb, (int)TT, 512 * TT,
                                                   kpTb, (int)TT, 256 * TT,
                                                   kpart, 256, 131072, 512, 448, 16,
                                                   nullf, nullf, 0, nullf, 0,
                                                   nullx);
    reduce_kptv<<<8192, 256>>>(kpart, kptvb);

    // 10. y[b] = (qp @ kptv^T) / (D + eps)  (bf16)
    bgemm<5,1><<<dim3(4, 25, 16), 256, B16_SMEM>>>(qpb, 256, TT * 256,
                                                   kptvb, 256, 512 * 256,
                                                   yb, 512, TT * 512, (int)TT, 256, 16,
                                                   nullf, Dv, TT, nullf, 0,
                                                   nullx);

    // 11. xres = x + y @ w_proj + b_proj  (fp32 out)
    bgemm<3,0><<<dim3(4, 392, 1), 256, B16_SMEM>>>(yb, 512, 0, wprojTb, 512, 0,
                                                   xres, 512, 0, BT, 512, 1,
                                                   b_proj, nullf, 0, x, 0,
                                                   nullx);

    // 12. h2 = LN(xres)  (bf16)
    ln_kernel<<<BT, 128>>>(xres, g2, be2, h2b);

    // 13. hm = gelu(h2 @ w_mlp1 + b_mlp1)  (bf16)
    bgemm<2,1><<<dim3(4, 392, 1), 256, B16_SMEM>>>(h2b, 512, 0, wm1Tb, 512, 0,
                                                   hmb, 512, 0, BT, 512, 1,
                                                   b_mlp1, nullf, 0, nullf, 0,
                                                   nullx);

    // 14. out = xres + hm @ w_mlp2 + b_mlp2  (fp32 out)
    bgemm<3,0><<<dim3(4, 392, 1), 256, B16_SMEM>>>(hmb, 512, 0, wm2Tb, 512, 0,
                                                   out, 512, 0, BT, 512, 1,
                                                   b_mlp2, nullf, 0, xres, 0,
                                                   nullx);
}